// round 4
// baseline (speedup 1.0000x reference)
#include <cuda_runtime.h>
#include <math.h>

#define DINLINE __device__ __forceinline__
typedef unsigned long long u64;

constexpr int NN = 100000;   // nodes
constexpr int TT = 24;       // time steps
constexpr int EE = 3200000;  // edges

// ----------------------------------------------------------------------------
// Scratch (static device globals; no allocations allowed)
// ----------------------------------------------------------------------------
__device__ __align__(16) float g_xw[NN * 32];      // linear output / spmm input
__device__ __align__(16) float g_acc[NN * 32];     // spmm accumulator
__device__ __align__(16) float g_gi[NN * 192];     // time-invariant input-gate projections (+bias)
__device__ __align__(16) float g_WhhT[64 * 192];   // W_hh transposed: [k][j]  (j order: r|z|n)
__device__ __align__(16) float g_Wih8T[8 * 192];   // W_ih[:,32:40] transposed: [k8][j]
__device__ __align__(16) float g_h1wT[64 * 64];    // h1_W transposed: [k][j]
__device__ __align__(16) float g_bhn[64];          // b_hh[128:192]

DINLINE float sigf(float x)  { return __fdividef(1.0f, 1.0f + __expf(-x)); }
DINLINE float tanhx(float x) { return __fdividef(2.0f, 1.0f + __expf(-2.0f * x)) - 1.0f; }

// f32x2 packed math (sm_103a FFMA2 — only reachable via PTX)
DINLINE u64 pack2(float lo, float hi) {
    u64 r; asm("mov.b64 %0, {%1, %2};" : "=l"(r) : "f"(lo), "f"(hi)); return r;
}
DINLINE void unpack2(u64 v, float& lo, float& hi) {
    asm("mov.b64 {%0, %1}, %2;" : "=f"(lo), "=f"(hi) : "l"(v));
}
DINLINE u64 fma2(u64 a, u64 b, u64 c) {
    u64 d; asm("fma.rn.f32x2 %0, %1, %2, %3;" : "=l"(d) : "l"(a), "l"(b), "l"(c)); return d;
}

// ----------------------------------------------------------------------------
// Dense 32->32 linear + g_acc zeroing. 32 nodes / 256-thread block; grid 3125.
// ----------------------------------------------------------------------------
__global__ void lin32_kernel(const float* __restrict__ Xext,
                             const float* __restrict__ W,
                             const float* __restrict__ bias,
                             int relu_acc_src) {
    __shared__ float Wt[1024];      // Wt[k*32+j] = W[j][k]
    __shared__ float Xs[32 * 33];   // 32 nodes, padded rows
    int tid = threadIdx.x;
    int n0  = blockIdx.x * 32;

    for (int e = tid; e < 1024; e += 256) {
        int j = e >> 5, k = e & 31;
        Wt[k * 32 + j] = W[j * 32 + k];
    }
    for (int e = tid; e < 1024; e += 256) {
        int n = e >> 5, k = e & 31;
        float v;
        if (relu_acc_src) v = fmaxf(g_acc[(n0 + n) * 32 + k], 0.0f);
        else              v = Xext[(n0 + n) * 32 + k];
        Xs[n * 33 + k] = v;
    }
    __syncthreads();

    // zero this block's g_acc slice for the following spmm
    for (int e = tid; e < 1024; e += 256)
        g_acc[n0 * 32 + e] = 0.0f;

    int j = tid & 31;
    float b = bias[j];
#pragma unroll
    for (int g = 0; g < 4; ++g) {
        int n = (tid >> 5) + g * 8;
        float acc = b;
#pragma unroll
        for (int k = 0; k < 32; ++k)
            acc = fmaf(Xs[n * 33 + k], Wt[k * 32 + j], acc);
        g_xw[(n0 + n) * 32 + j] = acc;
    }
}

// ----------------------------------------------------------------------------
// SpMM scatter with vector REDs: 8 threads / edge, one v4 red each.
// grid = E*8/256 = 100000 blocks exactly.
// ----------------------------------------------------------------------------
__global__ void spmm_kernel(const int*  __restrict__ er,
                            const int*  __restrict__ ec,
                            const float* __restrict__ ev) {
    int idx = blockIdx.x * 256 + threadIdx.x;
    int e = idx >> 3, q = idx & 7;
    int r = __ldg(er + e);
    int c = __ldg(ec + e);
    float v = __ldg(ev + e);
    float4 x = *(const float4*)(g_xw + c * 32 + q * 4);
    float* dst = g_acc + r * 32 + q * 4;
    asm volatile("red.global.add.v4.f32 [%0], {%1, %2, %3, %4};"
                 :: "l"(dst), "f"(v * x.x), "f"(v * x.y), "f"(v * x.z), "f"(v * x.w)
                 : "memory");
}

// ----------------------------------------------------------------------------
// gi_static + weight prep (fused). 32 nodes / 256-thread block; grid 3125.
// ----------------------------------------------------------------------------
__global__ void gi_prep_kernel(const float* __restrict__ Wih,
                               const float* __restrict__ bih,
                               const float* __restrict__ bhh,
                               const float* __restrict__ Whh,
                               const float* __restrict__ h1W) {
    __shared__ float Ws[32 * 192];   // Ws[k*192+j] = W_ih[j][k]
    __shared__ float Hs[32 * 33];    // relu'd h tile, padded rows
    int tid = threadIdx.x;
    int n0  = blockIdx.x * 32;

    // weight-prep side work on the first 36 blocks (2 ids each thread)
    if (blockIdx.x < 36) {
#pragma unroll
        for (int h = 0; h < 2; ++h) {
            int id = blockIdx.x * 512 + h * 256 + tid;
            if (id < 12288) {                       // W_hh: [192][64] -> [64][192]
                int k = id / 192, j = id - k * 192;
                g_WhhT[id] = Whh[j * 64 + k];
            } else if (id < 13824) {                // W_ih cols 32..39 -> [8][192]
                int q = id - 12288;
                int k = q / 192, j = q - k * 192;
                g_Wih8T[q] = Wih[j * 40 + 32 + k];
            } else if (id < 17920) {                // h1_W -> transposed [64][64]
                int q = id - 13824;
                int k = q >> 6, j = q & 63;
                g_h1wT[q] = h1W[j * 64 + k];
            } else if (id < 17984) {
                g_bhn[id - 17920] = bhh[128 + id - 17920];
            }
        }
    }

    for (int e = tid; e < 6144; e += 256) {
        int k = e / 192, j = e - k * 192;
        Ws[e] = Wih[j * 40 + k];
    }
    for (int e = tid; e < 1024; e += 256) {
        int n = e >> 5, k = e & 31;
        Hs[n * 33 + k] = fmaxf(g_acc[(n0 + n) * 32 + k], 0.0f);
    }
    __syncthreads();

#pragma unroll 1
    for (int it = 0; it < 24; ++it) {
        int p = it * 256 + tid;        // 32*192 = 6144 = 24*256
        int n = p / 192, j = p - n * 192;
        float acc = bih[j] + (j < 128 ? bhh[j] : 0.0f);
#pragma unroll
        for (int k = 0; k < 32; ++k)
            acc = fmaf(Hs[n * 33 + k], Ws[k * 192 + j], acc);
        g_gi[(n0 + n) * 192 + j] = acc;
    }
}

// ----------------------------------------------------------------------------
// Persistent GRU: one block = 128 nodes, all 24 steps. MLP head for h_{t} is
// fused into step t+1's gate GEMM (shares x loads and packs); 2 barriers/step.
// Thread (ng = tid&31, hg = tid>>5) owns 4 nodes x 4 hidden units.
// ----------------------------------------------------------------------------
// smem layout (floats):
//   s_zt   [72*128]  = 9216   @ 0       (rows 0-63: h, rows 64-71: x_t)
//   s_gi   [12288 u64]        @ 9216    (24576 floats)
//   s_whh  [64*192]  = 12288  @ 33792
//   s_wih8 [8*192]   = 1536   @ 46080
//   s_h1w  [64*64]   = 4096   @ 47616
//   s_red  [16*128]  = 2048   @ 51712
//   s_bhn  64                 @ 53760
//   s_h1b  64                 @ 53824
//   s_h2w  64                 @ 53888
//   s_h2b  4                  @ 53952
constexpr int GRU_SMEM_FLOATS = 53956;
constexpr int GRU_SMEM_BYTES  = GRU_SMEM_FLOATS * 4;   // 215,824 B

__global__ void __launch_bounds__(512, 1)
gru_persistent_kernel(const float* __restrict__ xdyn,   // X_dyn_mean base
                      const float* __restrict__ h1b,
                      const float* __restrict__ h2w,
                      const float* __restrict__ h2b,
                      float* __restrict__ yout) {        // d_out base
    extern __shared__ float sm[];
    float* s_zt   = sm;
    u64*   s_gi   = (u64*)(sm + 9216);
    float* s_whh  = sm + 33792;
    float* s_wih8 = sm + 46080;
    float* s_h1w  = sm + 47616;
    float* s_red  = sm + 51712;
    float* s_bhn  = sm + 53760;
    float* s_h1b  = sm + 53824;
    float* s_h2w  = sm + 53888;
    float* s_h2b  = sm + 53952;

    int tid = threadIdx.x;
    int n0  = blockIdx.x * 128;
    int ng = tid & 31, hg = tid >> 5;
    int nb = ng * 4;

    // ---- prologue: weights & biases ----
    {
        float4* d4; const float4* s4;
        d4 = (float4*)s_whh;  s4 = (const float4*)g_WhhT;
        for (int i = tid; i < 3072; i += 512) d4[i] = s4[i];
        d4 = (float4*)s_wih8; s4 = (const float4*)g_Wih8T;
        if (tid < 384) d4[tid] = s4[tid];
        d4 = (float4*)s_h1w;  s4 = (const float4*)g_h1wT;
        for (int i = tid; i < 1024; i += 512) d4[i] = s4[i];
        if (tid < 64) { s_bhn[tid] = g_bhn[tid]; s_h1b[tid] = h1b[tid]; s_h2w[tid] = h2w[tid]; }
        if (tid == 0) s_h2b[0] = h2b[0];
    }
    // ---- prologue: gi slice for this thread's 4 nodes (kept all 24 steps) ----
#pragma unroll
    for (int i = 0; i < 4; ++i) {
        int gn = min(n0 + nb + i, NN - 1);
        const ulonglong2* g2 = (const ulonglong2*)(g_gi + gn * 192);
        ulonglong2 rv = g2[hg];         // r chunk
        ulonglong2 zv = g2[16 + hg];    // z chunk
        ulonglong2 iv = g2[32 + hg];    // i_n chunk
        s_gi[(i * 6 + 0) * 512 + tid] = rv.x;
        s_gi[(i * 6 + 1) * 512 + tid] = rv.y;
        s_gi[(i * 6 + 2) * 512 + tid] = zv.x;
        s_gi[(i * 6 + 3) * 512 + tid] = zv.y;
        s_gi[(i * 6 + 4) * 512 + tid] = iv.x;
        s_gi[(i * 6 + 5) * 512 + tid] = iv.y;
    }
    // ---- prologue: h0 = 0, stage x_0 ----
    for (int i = tid; i < 8192; i += 512) s_zt[i] = 0.0f;
    if (tid < 128) {
        int gn2 = min(n0 + tid, NN - 1);
        const float4* x4 = (const float4*)(xdyn + (size_t)gn2 * 8);
        float4 a = x4[0], b = x4[1];
        float* dst = s_zt + 64 * 128 + tid;
        dst[0] = a.x; dst[128] = a.y; dst[256] = a.z; dst[384] = a.w;
        dst[512] = b.x; dst[640] = b.y; dst[768] = b.z; dst[896] = b.w;
    }
    __syncthreads();

    u64 bn0 = *(const u64*)(s_bhn + (hg << 2));
    u64 bn1 = *(const u64*)(s_bhn + (hg << 2) + 2);
    u64 hb0 = *(const u64*)(s_h1b + (hg << 2));
    u64 hb1 = *(const u64*)(s_h1b + (hg << 2) + 2);
    float w2a = s_h2w[(hg << 2) + 0], w2b = s_h2w[(hg << 2) + 1];
    float w2c = s_h2w[(hg << 2) + 2], w2d = s_h2w[(hg << 2) + 3];

#pragma unroll 1
    for (int t = 0; t < TT; ++t) {
        // s_zt rows 0-63 = h_old (h of step t-1), rows 64-71 = x_t.
        // This GEMM computes gates(t) AND the MLP head on h_old (= y_{t-1}).
        u64 ar2[4][2], az2[4][2], ain2[4][2], ahn2[4][2], ahd2[4][2];
#pragma unroll
        for (int i = 0; i < 4; ++i) {
            ar2[i][0]  = s_gi[(i * 6 + 0) * 512 + tid];
            ar2[i][1]  = s_gi[(i * 6 + 1) * 512 + tid];
            az2[i][0]  = s_gi[(i * 6 + 2) * 512 + tid];
            az2[i][1]  = s_gi[(i * 6 + 3) * 512 + tid];
            ain2[i][0] = s_gi[(i * 6 + 4) * 512 + tid];
            ain2[i][1] = s_gi[(i * 6 + 5) * 512 + tid];
            ahn2[i][0] = bn0;  ahn2[i][1] = bn1;
            ahd2[i][0] = hb0;  ahd2[i][1] = hb1;
        }

        // ---- K = 64 over h_old: gates r, z, h_n  +  head H1 ----
#pragma unroll 2
        for (int k = 0; k < 64; ++k) {
            float4 xv = *(const float4*)(s_zt + k * 128 + nb);
            const float* wp = s_whh + k * 192 + (hg << 2);
            ulonglong2 wr = *(const ulonglong2*)(wp);
            ulonglong2 wz = *(const ulonglong2*)(wp + 64);
            ulonglong2 wn = *(const ulonglong2*)(wp + 128);
            ulonglong2 wh = *(const ulonglong2*)(s_h1w + k * 64 + (hg << 2));
            u64 xd[4] = {pack2(xv.x, xv.x), pack2(xv.y, xv.y),
                         pack2(xv.z, xv.z), pack2(xv.w, xv.w)};
#pragma unroll
            for (int i = 0; i < 4; ++i) {
                ar2[i][0]  = fma2(xd[i], wr.x, ar2[i][0]);
                ar2[i][1]  = fma2(xd[i], wr.y, ar2[i][1]);
                az2[i][0]  = fma2(xd[i], wz.x, az2[i][0]);
                az2[i][1]  = fma2(xd[i], wz.y, az2[i][1]);
                ahn2[i][0] = fma2(xd[i], wn.x, ahn2[i][0]);
                ahn2[i][1] = fma2(xd[i], wn.y, ahn2[i][1]);
                ahd2[i][0] = fma2(xd[i], wh.x, ahd2[i][0]);
                ahd2[i][1] = fma2(xd[i], wh.y, ahd2[i][1]);
            }
        }
        // ---- K = 8 over x_dyn: r, z, i_n ----
#pragma unroll
        for (int k = 0; k < 8; ++k) {
            float4 xv = *(const float4*)(s_zt + (64 + k) * 128 + nb);
            const float* wp = s_wih8 + k * 192 + (hg << 2);
            ulonglong2 wr = *(const ulonglong2*)(wp);
            ulonglong2 wz = *(const ulonglong2*)(wp + 64);
            ulonglong2 wi = *(const ulonglong2*)(wp + 128);
            u64 xd[4] = {pack2(xv.x, xv.x), pack2(xv.y, xv.y),
                         pack2(xv.z, xv.z), pack2(xv.w, xv.w)};
#pragma unroll
            for (int i = 0; i < 4; ++i) {
                ar2[i][0]  = fma2(xd[i], wr.x, ar2[i][0]);
                ar2[i][1]  = fma2(xd[i], wr.y, ar2[i][1]);
                az2[i][0]  = fma2(xd[i], wz.x, az2[i][0]);
                az2[i][1]  = fma2(xd[i], wz.y, az2[i][1]);
                ain2[i][0] = fma2(xd[i], wi.x, ain2[i][0]);
                ain2[i][1] = fma2(xd[i], wi.y, ain2[i][1]);
            }
        }

        // ---- head partials (y_{t-1}) into s_red (own slots) ----
#pragma unroll
        for (int i = 0; i < 4; ++i) {
            float p0, p1, p2, p3;
            unpack2(ahd2[i][0], p0, p1);
            unpack2(ahd2[i][1], p2, p3);
            float part = w2a * fmaxf(p0, 0.0f) + w2b * fmaxf(p1, 0.0f)
                       + w2c * fmaxf(p2, 0.0f) + w2d * fmaxf(p3, 0.0f);
            s_red[hg * 128 + nb + i] = part;
        }
        __syncthreads();   // GEMM reads of s_zt done; s_red complete

        // ---- write y_{t-1} ----
        if (t > 0 && tid < 128) {
            float s = 0.0f;
#pragma unroll
            for (int g = 0; g < 16; ++g) s += s_red[g * 128 + tid];
            int gn = n0 + tid;
            if (gn < NN)
                yout[(size_t)(t - 1) * NN + gn] = sigf(s + s_h2b[0]);
        }

        // ---- gates + in-place h update (own slots only) ----
#pragma unroll
        for (int i = 0; i < 4; ++i) {
            int nl = nb + i;
#pragma unroll
            for (int jp = 0; jp < 2; ++jp) {
                float r0, r1, z0, z1, in0, in1, hn0, hn1;
                unpack2(ar2[i][jp],  r0,  r1);
                unpack2(az2[i][jp],  z0,  z1);
                unpack2(ain2[i][jp], in0, in1);
                unpack2(ahn2[i][jp], hn0, hn1);
                float hpa = s_zt[(hg * 4 + jp * 2 + 0) * 128 + nl];
                float hpb = s_zt[(hg * 4 + jp * 2 + 1) * 128 + nl];
                float ra = sigf(r0), rb = sigf(r1);
                float za = sigf(z0), zb = sigf(z1);
                float na  = tanhx(in0 + ra * hn0);
                float nbv = tanhx(in1 + rb * hn1);
                float ha = na  + za * (hpa - na);
                float hb = nbv + zb * (hpb - nbv);
                s_zt[(hg * 4 + jp * 2 + 0) * 128 + nl] = ha;
                s_zt[(hg * 4 + jp * 2 + 1) * 128 + nl] = hb;
            }
        }

        // ---- stage x_{t+1} into rows 64..71 (not read again this iter) ----
        if (t < TT - 1 && tid < 128) {
            int gn2 = min(n0 + tid, NN - 1);
            const float4* x4 = (const float4*)(xdyn + ((size_t)(t + 1) * NN + gn2) * 8);
            float4 a = x4[0], b = x4[1];
            float* dst = s_zt + 64 * 128 + tid;
            dst[0] = a.x; dst[128] = a.y; dst[256] = a.z; dst[384] = a.w;
            dst[512] = b.x; dst[640] = b.y; dst[768] = b.z; dst[896] = b.w;
        }
        __syncthreads();
    }

    // ---- tail: head for the final h (y_23) ----
    {
        u64 ahd2[4][2];
#pragma unroll
        for (int i = 0; i < 4; ++i) { ahd2[i][0] = hb0; ahd2[i][1] = hb1; }
#pragma unroll 4
        for (int k = 0; k < 64; ++k) {
            float4 xv = *(const float4*)(s_zt + k * 128 + nb);
            ulonglong2 wh = *(const ulonglong2*)(s_h1w + k * 64 + (hg << 2));
            u64 xd[4] = {pack2(xv.x, xv.x), pack2(xv.y, xv.y),
                         pack2(xv.z, xv.z), pack2(xv.w, xv.w)};
#pragma unroll
            for (int i = 0; i < 4; ++i) {
                ahd2[i][0] = fma2(xd[i], wh.x, ahd2[i][0]);
                ahd2[i][1] = fma2(xd[i], wh.y, ahd2[i][1]);
            }
        }
#pragma unroll
        for (int i = 0; i < 4; ++i) {
            float p0, p1, p2, p3;
            unpack2(ahd2[i][0], p0, p1);
            unpack2(ahd2[i][1], p2, p3);
            float part = w2a * fmaxf(p0, 0.0f) + w2b * fmaxf(p1, 0.0f)
                       + w2c * fmaxf(p2, 0.0f) + w2d * fmaxf(p3, 0.0f);
            s_red[hg * 128 + nb + i] = part;
        }
        __syncthreads();
        if (tid < 128) {
            float s = 0.0f;
#pragma unroll
            for (int g = 0; g < 16; ++g) s += s_red[g * 128 + tid];
            int gn = n0 + tid;
            if (gn < NN)
                yout[(size_t)(TT - 1) * NN + gn] = sigf(s + s_h2b[0]);
        }
    }
}

// ----------------------------------------------------------------------------
// Launch (6 kernels total)
// ----------------------------------------------------------------------------
extern "C" void kernel_launch(void* const* d_in, const int* in_sizes, int n_in,
                              void* d_out, int out_size) {
    const float* X_static = (const float*)d_in[0];
    const float* X_dyn    = (const float*)d_in[1];
    const int*   er       = (const int*)d_in[2];
    const int*   ec       = (const int*)d_in[3];
    const float* ev       = (const float*)d_in[4];
    const float* g1W      = (const float*)d_in[5];
    const float* g1b      = (const float*)d_in[6];
    const float* g2W      = (const float*)d_in[7];
    const float* g2b      = (const float*)d_in[8];
    const float* Wih      = (const float*)d_in[9];
    const float* Whh      = (const float*)d_in[10];
    const float* bih      = (const float*)d_in[11];
    const float* bhh      = (const float*)d_in[12];
    const float* h1W      = (const float*)d_in[13];
    const float* h1b      = (const float*)d_in[14];
    const float* h2W      = (const float*)d_in[15];
    const float* h2b      = (const float*)d_in[16];
    float* out = (float*)d_out;

    cudaFuncSetAttribute(gru_persistent_kernel,
                         cudaFuncAttributeMaxDynamicSharedMemorySize, GRU_SMEM_BYTES);

    // GraphConv layer 1 (lin32 also zeroes g_acc)
    lin32_kernel<<<3125, 256>>>(X_static, g1W, g1b, 0);
    spmm_kernel<<<100000, 256>>>(er, ec, ev);

    // GraphConv layer 2 (relu on read of g_acc, then re-zero)
    lin32_kernel<<<3125, 256>>>(X_static /*unused*/, g2W, g2b, 1);
    spmm_kernel<<<100000, 256>>>(er, ec, ev);

    // Time-invariant gate projections + weight prep (fused)
    gi_prep_kernel<<<3125, 256>>>(Wih, bih, bhh, Whh, h1W);

    // Persistent GRU: all 24 steps + fused MLP head in one launch
    gru_persistent_kernel<<<782, 512, GRU_SMEM_BYTES>>>(X_dyn, h1b, h2W, h2b, out);
}

// round 5
// speedup vs baseline: 1.0452x; 1.0452x over previous
#include <cuda_runtime.h>
#include <math.h>

#define DINLINE __device__ __forceinline__
typedef unsigned long long u64;

constexpr int NN = 100000;   // nodes
constexpr int TT = 24;       // time steps
constexpr int EE = 3200000;  // edges

// ----------------------------------------------------------------------------
// Scratch (static device globals; no allocations allowed)
// ----------------------------------------------------------------------------
__device__ __align__(16) float g_xw[NN * 32];      // linear output / spmm input
__device__ __align__(16) float g_acc[NN * 32];     // spmm accumulator
__device__ __align__(16) float g_gi[NN * 192];     // time-invariant input-gate projections (+bias)
__device__ __align__(16) float g_WhhT[64 * 192];   // W_hh transposed: [k][j]  (j order: r|z|n)
__device__ __align__(16) float g_Wih8T[8 * 192];   // W_ih[:,32:40] transposed: [k8][j]
__device__ __align__(16) float g_h1wT[64 * 64];    // h1_W transposed: [k][j]
__device__ __align__(16) float g_bhn[64];          // b_hh[128:192]

DINLINE float sigf(float x)  { return __fdividef(1.0f, 1.0f + __expf(-x)); }
DINLINE float tanhx(float x) { return __fdividef(2.0f, 1.0f + __expf(-2.0f * x)) - 1.0f; }
// fast sigmoid via MUFU.TANH (gates r/z only; abs err ~2.5e-4)
DINLINE float tanh_mufu(float x) {
    float y; asm("tanh.approx.f32 %0, %1;" : "=f"(y) : "f"(x)); return y;
}
DINLINE float sigf_fast(float x) { return fmaf(0.5f, tanh_mufu(0.5f * x), 0.5f); }

// f32x2 packed math (sm_103a FFMA2 — only reachable via PTX)
DINLINE u64 pack2(float lo, float hi) {
    u64 r; asm("mov.b64 %0, {%1, %2};" : "=l"(r) : "f"(lo), "f"(hi)); return r;
}
DINLINE void unpack2(u64 v, float& lo, float& hi) {
    asm("mov.b64 {%0, %1}, %2;" : "=f"(lo), "=f"(hi) : "l"(v));
}
DINLINE u64 fma2(u64 a, u64 b, u64 c) {
    u64 d; asm("fma.rn.f32x2 %0, %1, %2, %3;" : "=l"(d) : "l"(a), "l"(b), "l"(c)); return d;
}

// ----------------------------------------------------------------------------
// Dense 32->32 linear + g_acc zeroing. 32 nodes / 256-thread block; grid 3125.
// ----------------------------------------------------------------------------
__global__ void lin32_kernel(const float* __restrict__ Xext,
                             const float* __restrict__ W,
                             const float* __restrict__ bias,
                             int relu_acc_src) {
    __shared__ float Wt[1024];      // Wt[k*32+j] = W[j][k]
    __shared__ float Xs[32 * 33];   // 32 nodes, padded rows
    int tid = threadIdx.x;
    int n0  = blockIdx.x * 32;

    for (int e = tid; e < 1024; e += 256) {
        int j = e >> 5, k = e & 31;
        Wt[k * 32 + j] = W[j * 32 + k];
    }
    for (int e = tid; e < 1024; e += 256) {
        int n = e >> 5, k = e & 31;
        float v;
        if (relu_acc_src) v = fmaxf(g_acc[(n0 + n) * 32 + k], 0.0f);
        else              v = Xext[(n0 + n) * 32 + k];
        Xs[n * 33 + k] = v;
    }
    __syncthreads();

    // zero this block's g_acc slice for the following spmm
    for (int e = tid; e < 1024; e += 256)
        g_acc[n0 * 32 + e] = 0.0f;

    int j = tid & 31;
    float b = bias[j];
#pragma unroll
    for (int g = 0; g < 4; ++g) {
        int n = (tid >> 5) + g * 8;
        float acc = b;
#pragma unroll
        for (int k = 0; k < 32; ++k)
            acc = fmaf(Xs[n * 33 + k], Wt[k * 32 + j], acc);
        g_xw[(n0 + n) * 32 + j] = acc;
    }
}

// ----------------------------------------------------------------------------
// SpMM scatter with vector REDs: 8 threads / edge, one v4 red each.
// grid = E*8/256 = 100000 blocks exactly.
// ----------------------------------------------------------------------------
__global__ void spmm_kernel(const int*  __restrict__ er,
                            const int*  __restrict__ ec,
                            const float* __restrict__ ev) {
    int idx = blockIdx.x * 256 + threadIdx.x;
    int e = idx >> 3, q = idx & 7;
    int r = __ldg(er + e);
    int c = __ldg(ec + e);
    float v = __ldg(ev + e);
    float4 x = *(const float4*)(g_xw + c * 32 + q * 4);
    float* dst = g_acc + r * 32 + q * 4;
    asm volatile("red.global.add.v4.f32 [%0], {%1, %2, %3, %4};"
                 :: "l"(dst), "f"(v * x.x), "f"(v * x.y), "f"(v * x.z), "f"(v * x.w)
                 : "memory");
}

// ----------------------------------------------------------------------------
// gi_static + weight prep (fused). 32 nodes / 256-thread block; grid 3125.
// ----------------------------------------------------------------------------
__global__ void gi_prep_kernel(const float* __restrict__ Wih,
                               const float* __restrict__ bih,
                               const float* __restrict__ bhh,
                               const float* __restrict__ Whh,
                               const float* __restrict__ h1W) {
    __shared__ float Ws[32 * 192];   // Ws[k*192+j] = W_ih[j][k]
    __shared__ float Hs[32 * 33];    // relu'd h tile, padded rows
    int tid = threadIdx.x;
    int n0  = blockIdx.x * 32;

    // weight-prep side work on the first 36 blocks (2 ids each thread)
    if (blockIdx.x < 36) {
#pragma unroll
        for (int h = 0; h < 2; ++h) {
            int id = blockIdx.x * 512 + h * 256 + tid;
            if (id < 12288) {                       // W_hh: [192][64] -> [64][192]
                int k = id / 192, j = id - k * 192;
                g_WhhT[id] = Whh[j * 64 + k];
            } else if (id < 13824) {                // W_ih cols 32..39 -> [8][192]
                int q = id - 12288;
                int k = q / 192, j = q - k * 192;
                g_Wih8T[q] = Wih[j * 40 + 32 + k];
            } else if (id < 17920) {                // h1_W -> transposed [64][64]
                int q = id - 13824;
                int k = q >> 6, j = q & 63;
                g_h1wT[q] = h1W[j * 64 + k];
            } else if (id < 17984) {
                g_bhn[id - 17920] = bhh[128 + id - 17920];
            }
        }
    }

    for (int e = tid; e < 6144; e += 256) {
        int k = e / 192, j = e - k * 192;
        Ws[e] = Wih[j * 40 + k];
    }
    for (int e = tid; e < 1024; e += 256) {
        int n = e >> 5, k = e & 31;
        Hs[n * 33 + k] = fmaxf(g_acc[(n0 + n) * 32 + k], 0.0f);
    }
    __syncthreads();

#pragma unroll 1
    for (int it = 0; it < 24; ++it) {
        int p = it * 256 + tid;        // 32*192 = 6144 = 24*256
        int n = p / 192, j = p - n * 192;
        float acc = bih[j] + (j < 128 ? bhh[j] : 0.0f);
#pragma unroll
        for (int k = 0; k < 32; ++k)
            acc = fmaf(Hs[n * 33 + k], Ws[k * 192 + j], acc);
        g_gi[(n0 + n) * 192 + j] = acc;
    }
}

// ----------------------------------------------------------------------------
// Persistent GRU: one block = 128 nodes, all 24 steps. MLP head for h_{t-1} is
// fused into step t's gate GEMM (shares x loads and packs); 2 barriers/step.
// ain2 accumulators are initialized AFTER the k64 loop (liveness fix vs R4).
// Thread (ng = tid&31, hg = tid>>5) owns 4 nodes x 4 hidden units.
// ----------------------------------------------------------------------------
constexpr int GRU_SMEM_FLOATS = 53956;
constexpr int GRU_SMEM_BYTES  = GRU_SMEM_FLOATS * 4;   // 215,824 B

__global__ void __launch_bounds__(512, 1)
gru_persistent_kernel(const float* __restrict__ xdyn,   // X_dyn_mean base
                      const float* __restrict__ h1b,
                      const float* __restrict__ h2w,
                      const float* __restrict__ h2b,
                      float* __restrict__ yout) {        // d_out base
    extern __shared__ float sm[];
    float* s_zt   = sm;                       // [72][128]: rows 0-63 h, 64-71 x_t
    u64*   s_gi   = (u64*)(sm + 9216);        // [24 slots][512]
    float* s_whh  = sm + 33792;               // [64][192]
    float* s_wih8 = sm + 46080;               // [8][192]
    float* s_h1w  = sm + 47616;               // [64][64]
    float* s_red  = sm + 51712;               // [16][128]
    float* s_bhn  = sm + 53760;
    float* s_h1b  = sm + 53824;
    float* s_h2w  = sm + 53888;
    float* s_h2b  = sm + 53952;

    int tid = threadIdx.x;
    int n0  = blockIdx.x * 128;
    int ng = tid & 31, hg = tid >> 5;
    int nb = ng * 4;

    // ---- prologue: weights & biases ----
    {
        float4* d4; const float4* s4;
        d4 = (float4*)s_whh;  s4 = (const float4*)g_WhhT;
        for (int i = tid; i < 3072; i += 512) d4[i] = s4[i];
        d4 = (float4*)s_wih8; s4 = (const float4*)g_Wih8T;
        if (tid < 384) d4[tid] = s4[tid];
        d4 = (float4*)s_h1w;  s4 = (const float4*)g_h1wT;
        for (int i = tid; i < 1024; i += 512) d4[i] = s4[i];
        if (tid < 64) { s_bhn[tid] = g_bhn[tid]; s_h1b[tid] = h1b[tid]; s_h2w[tid] = h2w[tid]; }
        if (tid == 0) s_h2b[0] = h2b[0];
    }
    // ---- prologue: gi slice for this thread's 4 nodes (kept all 24 steps) ----
#pragma unroll
    for (int i = 0; i < 4; ++i) {
        int gn = min(n0 + nb + i, NN - 1);
        const ulonglong2* g2 = (const ulonglong2*)(g_gi + gn * 192);
        ulonglong2 rv = g2[hg];         // r chunk
        ulonglong2 zv = g2[16 + hg];    // z chunk
        ulonglong2 iv = g2[32 + hg];    // i_n chunk
        s_gi[(i * 6 + 0) * 512 + tid] = rv.x;
        s_gi[(i * 6 + 1) * 512 + tid] = rv.y;
        s_gi[(i * 6 + 2) * 512 + tid] = zv.x;
        s_gi[(i * 6 + 3) * 512 + tid] = zv.y;
        s_gi[(i * 6 + 4) * 512 + tid] = iv.x;
        s_gi[(i * 6 + 5) * 512 + tid] = iv.y;
    }
    // ---- prologue: h0 = 0, stage x_0 ----
    for (int i = tid; i < 8192; i += 512) s_zt[i] = 0.0f;
    if (tid < 128) {
        int gn2 = min(n0 + tid, NN - 1);
        const float4* x4 = (const float4*)(xdyn + (size_t)gn2 * 8);
        float4 a = x4[0], b = x4[1];
        float* dst = s_zt + 64 * 128 + tid;
        dst[0] = a.x; dst[128] = a.y; dst[256] = a.z; dst[384] = a.w;
        dst[512] = b.x; dst[640] = b.y; dst[768] = b.z; dst[896] = b.w;
    }
    __syncthreads();

    u64 bn0 = *(const u64*)(s_bhn + (hg << 2));
    u64 bn1 = *(const u64*)(s_bhn + (hg << 2) + 2);
    u64 hb0 = *(const u64*)(s_h1b + (hg << 2));
    u64 hb1 = *(const u64*)(s_h1b + (hg << 2) + 2);
    float w2a = s_h2w[(hg << 2) + 0], w2b = s_h2w[(hg << 2) + 1];
    float w2c = s_h2w[(hg << 2) + 2], w2d = s_h2w[(hg << 2) + 3];

#pragma unroll 1
    for (int t = 0; t < TT; ++t) {
        // s_zt rows 0-63 = h_old (h of step t-1), rows 64-71 = x_t.
        // This GEMM computes gates(t) AND the MLP head on h_old (= y_{t-1}).
        u64 ar2[4][2], az2[4][2], ahn2[4][2], ahd2[4][2];
#pragma unroll
        for (int i = 0; i < 4; ++i) {
            ar2[i][0]  = s_gi[(i * 6 + 0) * 512 + tid];
            ar2[i][1]  = s_gi[(i * 6 + 1) * 512 + tid];
            az2[i][0]  = s_gi[(i * 6 + 2) * 512 + tid];
            az2[i][1]  = s_gi[(i * 6 + 3) * 512 + tid];
            ahn2[i][0] = bn0;  ahn2[i][1] = bn1;
            ahd2[i][0] = hb0;  ahd2[i][1] = hb1;
        }

        // ---- K = 64 over h_old: gates r, z, h_n  +  head H1 (4 live acc sets) ----
#pragma unroll 2
        for (int k = 0; k < 64; ++k) {
            float4 xv = *(const float4*)(s_zt + k * 128 + nb);
            const float* wp = s_whh + k * 192 + (hg << 2);
            ulonglong2 wr = *(const ulonglong2*)(wp);
            ulonglong2 wz = *(const ulonglong2*)(wp + 64);
            ulonglong2 wn = *(const ulonglong2*)(wp + 128);
            ulonglong2 wh = *(const ulonglong2*)(s_h1w + k * 64 + (hg << 2));
            u64 xd[4] = {pack2(xv.x, xv.x), pack2(xv.y, xv.y),
                         pack2(xv.z, xv.z), pack2(xv.w, xv.w)};
#pragma unroll
            for (int i = 0; i < 4; ++i) {
                ar2[i][0]  = fma2(xd[i], wr.x, ar2[i][0]);
                ar2[i][1]  = fma2(xd[i], wr.y, ar2[i][1]);
                az2[i][0]  = fma2(xd[i], wz.x, az2[i][0]);
                az2[i][1]  = fma2(xd[i], wz.y, az2[i][1]);
                ahn2[i][0] = fma2(xd[i], wn.x, ahn2[i][0]);
                ahn2[i][1] = fma2(xd[i], wn.y, ahn2[i][1]);
                ahd2[i][0] = fma2(xd[i], wh.x, ahd2[i][0]);
                ahd2[i][1] = fma2(xd[i], wh.y, ahd2[i][1]);
            }
        }

        // ---- head partials (y_{t-1}) into s_red — retires ahd2 before k8 ----
#pragma unroll
        for (int i = 0; i < 4; ++i) {
            float p0, p1, p2, p3;
            unpack2(ahd2[i][0], p0, p1);
            unpack2(ahd2[i][1], p2, p3);
            float part = w2a * fmaxf(p0, 0.0f) + w2b * fmaxf(p1, 0.0f)
                       + w2c * fmaxf(p2, 0.0f) + w2d * fmaxf(p3, 0.0f);
            s_red[hg * 128 + nb + i] = part;
        }

        // ---- init i_n accumulators NOW (liveness starts here, not before k64) ----
        u64 ain2[4][2];
#pragma unroll
        for (int i = 0; i < 4; ++i) {
            ain2[i][0] = s_gi[(i * 6 + 4) * 512 + tid];
            ain2[i][1] = s_gi[(i * 6 + 5) * 512 + tid];
        }
        // ---- K = 8 over x_dyn: r, z, i_n ----
#pragma unroll
        for (int k = 0; k < 8; ++k) {
            float4 xv = *(const float4*)(s_zt + (64 + k) * 128 + nb);
            const float* wp = s_wih8 + k * 192 + (hg << 2);
            ulonglong2 wr = *(const ulonglong2*)(wp);
            ulonglong2 wz = *(const ulonglong2*)(wp + 64);
            ulonglong2 wi = *(const ulonglong2*)(wp + 128);
            u64 xd[4] = {pack2(xv.x, xv.x), pack2(xv.y, xv.y),
                         pack2(xv.z, xv.z), pack2(xv.w, xv.w)};
#pragma unroll
            for (int i = 0; i < 4; ++i) {
                ar2[i][0]  = fma2(xd[i], wr.x, ar2[i][0]);
                ar2[i][1]  = fma2(xd[i], wr.y, ar2[i][1]);
                az2[i][0]  = fma2(xd[i], wz.x, az2[i][0]);
                az2[i][1]  = fma2(xd[i], wz.y, az2[i][1]);
                ain2[i][0] = fma2(xd[i], wi.x, ain2[i][0]);
                ain2[i][1] = fma2(xd[i], wi.y, ain2[i][1]);
            }
        }
        __syncthreads();   // GEMM reads of s_zt done; s_red complete

        // ---- write y_{t-1} ----
        if (t > 0 && tid < 128) {
            float s = 0.0f;
#pragma unroll
            for (int g = 0; g < 16; ++g) s += s_red[g * 128 + tid];
            int gn = n0 + tid;
            if (gn < NN)
                yout[(size_t)(t - 1) * NN + gn] = sigf(s + s_h2b[0]);
        }

        // ---- gates + in-place h update (own slots only) ----
#pragma unroll
        for (int i = 0; i < 4; ++i) {
            int nl = nb + i;
#pragma unroll
            for (int jp = 0; jp < 2; ++jp) {
                float r0, r1, z0, z1, in0, in1, hn0, hn1;
                unpack2(ar2[i][jp],  r0,  r1);
                unpack2(az2[i][jp],  z0,  z1);
                unpack2(ain2[i][jp], in0, in1);
                unpack2(ahn2[i][jp], hn0, hn1);
                float hpa = s_zt[(hg * 4 + jp * 2 + 0) * 128 + nl];
                float hpb = s_zt[(hg * 4 + jp * 2 + 1) * 128 + nl];
                float ra = sigf_fast(r0), rb = sigf_fast(r1);
                float za = sigf_fast(z0), zb = sigf_fast(z1);
                float na  = tanhx(in0 + ra * hn0);
                float nbv = tanhx(in1 + rb * hn1);
                float ha = na  + za * (hpa - na);
                float hb = nbv + zb * (hpb - nbv);
                s_zt[(hg * 4 + jp * 2 + 0) * 128 + nl] = ha;
                s_zt[(hg * 4 + jp * 2 + 1) * 128 + nl] = hb;
            }
        }

        // ---- stage x_{t+1} into rows 64..71 (not read again this iter) ----
        if (t < TT - 1 && tid < 128) {
            int gn2 = min(n0 + tid, NN - 1);
            const float4* x4 = (const float4*)(xdyn + ((size_t)(t + 1) * NN + gn2) * 8);
            float4 a = x4[0], b = x4[1];
            float* dst = s_zt + 64 * 128 + tid;
            dst[0] = a.x; dst[128] = a.y; dst[256] = a.z; dst[384] = a.w;
            dst[512] = b.x; dst[640] = b.y; dst[768] = b.z; dst[896] = b.w;
        }
        __syncthreads();
    }

    // ---- tail: head for the final h (y_23) ----
    {
        u64 ahd2[4][2];
#pragma unroll
        for (int i = 0; i < 4; ++i) { ahd2[i][0] = hb0; ahd2[i][1] = hb1; }
#pragma unroll 4
        for (int k = 0; k < 64; ++k) {
            float4 xv = *(const float4*)(s_zt + k * 128 + nb);
            ulonglong2 wh = *(const ulonglong2*)(s_h1w + k * 64 + (hg << 2));
            u64 xd[4] = {pack2(xv.x, xv.x), pack2(xv.y, xv.y),
                         pack2(xv.z, xv.z), pack2(xv.w, xv.w)};
#pragma unroll
            for (int i = 0; i < 4; ++i) {
                ahd2[i][0] = fma2(xd[i], wh.x, ahd2[i][0]);
                ahd2[i][1] = fma2(xd[i], wh.y, ahd2[i][1]);
            }
        }
#pragma unroll
        for (int i = 0; i < 4; ++i) {
            float p0, p1, p2, p3;
            unpack2(ahd2[i][0], p0, p1);
            unpack2(ahd2[i][1], p2, p3);
            float part = w2a * fmaxf(p0, 0.0f) + w2b * fmaxf(p1, 0.0f)
                       + w2c * fmaxf(p2, 0.0f) + w2d * fmaxf(p3, 0.0f);
            s_red[hg * 128 + nb + i] = part;
        }
        __syncthreads();
        if (tid < 128) {
            float s = 0.0f;
#pragma unroll
            for (int g = 0; g < 16; ++g) s += s_red[g * 128 + tid];
            int gn = n0 + tid;
            if (gn < NN)
                yout[(size_t)(TT - 1) * NN + gn] = sigf(s + s_h2b[0]);
        }
    }
}

// ----------------------------------------------------------------------------
// Launch (6 kernels total)
// ----------------------------------------------------------------------------
extern "C" void kernel_launch(void* const* d_in, const int* in_sizes, int n_in,
                              void* d_out, int out_size) {
    const float* X_static = (const float*)d_in[0];
    const float* X_dyn    = (const float*)d_in[1];
    const int*   er       = (const int*)d_in[2];
    const int*   ec       = (const int*)d_in[3];
    const float* ev       = (const float*)d_in[4];
    const float* g1W      = (const float*)d_in[5];
    const float* g1b      = (const float*)d_in[6];
    const float* g2W      = (const float*)d_in[7];
    const float* g2b      = (const float*)d_in[8];
    const float* Wih      = (const float*)d_in[9];
    const float* Whh      = (const float*)d_in[10];
    const float* bih      = (const float*)d_in[11];
    const float* bhh      = (const float*)d_in[12];
    const float* h1W      = (const float*)d_in[13];
    const float* h1b      = (const float*)d_in[14];
    const float* h2W      = (const float*)d_in[15];
    const float* h2b      = (const float*)d_in[16];
    float* out = (float*)d_out;

    cudaFuncSetAttribute(gru_persistent_kernel,
                         cudaFuncAttributeMaxDynamicSharedMemorySize, GRU_SMEM_BYTES);

    // GraphConv layer 1 (lin32 also zeroes g_acc)
    lin32_kernel<<<3125, 256>>>(X_static, g1W, g1b, 0);
    spmm_kernel<<<100000, 256>>>(er, ec, ev);

    // GraphConv layer 2 (relu on read of g_acc, then re-zero)
    lin32_kernel<<<3125, 256>>>(X_static /*unused*/, g2W, g2b, 1);
    spmm_kernel<<<100000, 256>>>(er, ec, ev);

    // Time-invariant gate projections + weight prep (fused)
    gi_prep_kernel<<<3125, 256>>>(Wih, bih, bhh, Whh, h1W);

    // Persistent GRU: all 24 steps + fused MLP head in one launch
    gru_persistent_kernel<<<782, 512, GRU_SMEM_BYTES>>>(X_dyn, h1b, h2W, h2b, out);
}

// round 6
// speedup vs baseline: 1.1086x; 1.0607x over previous
#include <cuda_runtime.h>
#include <math.h>

#define DINLINE __device__ __forceinline__
typedef unsigned long long u64;

constexpr int NN = 100000;   // nodes
constexpr int TT = 24;       // time steps
constexpr int EE = 3200000;  // edges

// ----------------------------------------------------------------------------
// Scratch (static device globals; no allocations allowed)
// ----------------------------------------------------------------------------
__device__ __align__(16) float g_xw[NN * 32];      // linear output / spmm input
__device__ __align__(16) float g_acc[NN * 32];     // spmm accumulator
__device__ __align__(16) float g_gi[NN * 192];     // time-invariant input-gate projections (+bias)
__device__ __align__(16) float g_WhhT[64 * 192];   // W_hh transposed: [k][j]  (j order: r|z|n)
__device__ __align__(16) float g_Wih8T[8 * 192];   // W_ih[:,32:40] transposed: [k8][j]
__device__ __align__(16) float g_h1wT[64 * 64];    // h1_W transposed: [k][j]
__device__ __align__(16) float g_bhn[64];          // b_hh[128:192]

DINLINE float sigf(float x)  { return __fdividef(1.0f, 1.0f + __expf(-x)); }
// MUFU.TANH (abs err ~5e-4) — used for r/z/n gates
DINLINE float tanh_mufu(float x) {
    float y; asm("tanh.approx.f32 %0, %1;" : "=f"(y) : "f"(x)); return y;
}
DINLINE float sigf_fast(float x) { return fmaf(0.5f, tanh_mufu(0.5f * x), 0.5f); }

// f32x2 packed math (sm_103a FFMA2 — only reachable via PTX)
DINLINE u64 pack2(float lo, float hi) {
    u64 r; asm("mov.b64 %0, {%1, %2};" : "=l"(r) : "f"(lo), "f"(hi)); return r;
}
DINLINE void unpack2(u64 v, float& lo, float& hi) {
    asm("mov.b64 {%0, %1}, %2;" : "=f"(lo), "=f"(hi) : "l"(v));
}
DINLINE u64 fma2(u64 a, u64 b, u64 c) {
    u64 d; asm("fma.rn.f32x2 %0, %1, %2, %3;" : "=l"(d) : "l"(a), "l"(b), "l"(c)); return d;
}

// ----------------------------------------------------------------------------
// Dense 32->32 linear + g_acc zeroing. 32 nodes / 256-thread block; grid 3125.
// ----------------------------------------------------------------------------
__global__ void lin32_kernel(const float* __restrict__ Xext,
                             const float* __restrict__ W,
                             const float* __restrict__ bias,
                             int relu_acc_src) {
    __shared__ float Wt[1024];      // Wt[k*32+j] = W[j][k]
    __shared__ float Xs[32 * 33];   // 32 nodes, padded rows
    int tid = threadIdx.x;
    int n0  = blockIdx.x * 32;

    for (int e = tid; e < 1024; e += 256) {
        int j = e >> 5, k = e & 31;
        Wt[k * 32 + j] = W[j * 32 + k];
    }
    for (int e = tid; e < 1024; e += 256) {
        int n = e >> 5, k = e & 31;
        float v;
        if (relu_acc_src) v = fmaxf(g_acc[(n0 + n) * 32 + k], 0.0f);
        else              v = Xext[(n0 + n) * 32 + k];
        Xs[n * 33 + k] = v;
    }
    __syncthreads();

    // zero this block's g_acc slice for the following spmm
    for (int e = tid; e < 1024; e += 256)
        g_acc[n0 * 32 + e] = 0.0f;

    int j = tid & 31;
    float b = bias[j];
#pragma unroll
    for (int g = 0; g < 4; ++g) {
        int n = (tid >> 5) + g * 8;
        float acc = b;
#pragma unroll
        for (int k = 0; k < 32; ++k)
            acc = fmaf(Xs[n * 33 + k], Wt[k * 32 + j], acc);
        g_xw[(n0 + n) * 32 + j] = acc;
    }
}

// ----------------------------------------------------------------------------
// SpMM scatter with vector REDs: 8 threads / edge, one v4 red each.
// grid = E*8/256 = 100000 blocks exactly.
// ----------------------------------------------------------------------------
__global__ void spmm_kernel(const int*  __restrict__ er,
                            const int*  __restrict__ ec,
                            const float* __restrict__ ev) {
    int idx = blockIdx.x * 256 + threadIdx.x;
    int e = idx >> 3, q = idx & 7;
    int r = __ldg(er + e);
    int c = __ldg(ec + e);
    float v = __ldg(ev + e);
    float4 x = *(const float4*)(g_xw + c * 32 + q * 4);
    float* dst = g_acc + r * 32 + q * 4;
    asm volatile("red.global.add.v4.f32 [%0], {%1, %2, %3, %4};"
                 :: "l"(dst), "f"(v * x.x), "f"(v * x.y), "f"(v * x.z), "f"(v * x.w)
                 : "memory");
}

// ----------------------------------------------------------------------------
// gi_static + weight prep (fused). 32 nodes / 256-thread block; grid 3125.
// ----------------------------------------------------------------------------
__global__ void gi_prep_kernel(const float* __restrict__ Wih,
                               const float* __restrict__ bih,
                               const float* __restrict__ bhh,
                               const float* __restrict__ Whh,
                               const float* __restrict__ h1W) {
    __shared__ float Ws[32 * 192];   // Ws[k*192+j] = W_ih[j][k]
    __shared__ float Hs[32 * 33];    // relu'd h tile, padded rows
    int tid = threadIdx.x;
    int n0  = blockIdx.x * 32;

    // weight-prep side work on the first 36 blocks (2 ids each thread)
    if (blockIdx.x < 36) {
#pragma unroll
        for (int h = 0; h < 2; ++h) {
            int id = blockIdx.x * 512 + h * 256 + tid;
            if (id < 12288) {                       // W_hh: [192][64] -> [64][192]
                int k = id / 192, j = id - k * 192;
                g_WhhT[id] = Whh[j * 64 + k];
            } else if (id < 13824) {                // W_ih cols 32..39 -> [8][192]
                int q = id - 12288;
                int k = q / 192, j = q - k * 192;
                g_Wih8T[q] = Wih[j * 40 + 32 + k];
            } else if (id < 17920) {                // h1_W -> transposed [64][64]
                int q = id - 13824;
                int k = q >> 6, j = q & 63;
                g_h1wT[q] = h1W[j * 64 + k];
            } else if (id < 17984) {
                g_bhn[id - 17920] = bhh[128 + id - 17920];
            }
        }
    }

    for (int e = tid; e < 6144; e += 256) {
        int k = e / 192, j = e - k * 192;
        Ws[e] = Wih[j * 40 + k];
    }
    for (int e = tid; e < 1024; e += 256) {
        int n = e >> 5, k = e & 31;
        Hs[n * 33 + k] = fmaxf(g_acc[(n0 + n) * 32 + k], 0.0f);
    }
    __syncthreads();

#pragma unroll 1
    for (int it = 0; it < 24; ++it) {
        int p = it * 256 + tid;        // 32*192 = 6144 = 24*256
        int n = p / 192, j = p - n * 192;
        float acc = bih[j] + (j < 128 ? bhh[j] : 0.0f);
#pragma unroll
        for (int k = 0; k < 32; ++k)
            acc = fmaf(Hs[n * 33 + k], Ws[k * 192 + j], acc);
        g_gi[(n0 + n) * 192 + j] = acc;
    }
}

// ----------------------------------------------------------------------------
// Persistent GRU: one block = 64 nodes, 512 threads, all 24 steps.
// Thread (ng = tid&31, hg = tid>>5) owns 2 nodes x 4 hidden units.
// MLP head for h_{t-1} fused into step t's gate GEMM. 2 barriers/step.
// Grid 1563 -> 10.56 waves (vs 5.28->6 at 128-node tiles): 4% tail waste.
// ----------------------------------------------------------------------------
// smem float offsets:
//   s_zt   [72][64] = 4608   @ 0      (rows 0-63 h, 64-71 x_t)
//   s_gi   6144 u64          @ 4608   (12288 floats)
//   s_whh  [64][192]= 12288  @ 16896
//   s_wih8 [8][192] = 1536   @ 29184
//   s_h1w  [64][64] = 4096   @ 30720
//   s_red  [16][64] = 1024   @ 34816
//   s_bhn  64                @ 35840
//   s_h1b  64                @ 35904
//   s_h2w  64                @ 35968
//   s_h2b  4                 @ 36032
constexpr int GRU_SMEM_FLOATS = 36036;
constexpr int GRU_SMEM_BYTES  = GRU_SMEM_FLOATS * 4;   // 144,144 B

__global__ void __launch_bounds__(512, 1)
gru_persistent_kernel(const float* __restrict__ xdyn,   // X_dyn_mean base
                      const float* __restrict__ h1b,
                      const float* __restrict__ h2w,
                      const float* __restrict__ h2b,
                      float* __restrict__ yout) {        // d_out base
    extern __shared__ float sm[];
    float* s_zt   = sm;
    u64*   s_gi   = (u64*)(sm + 4608);
    float* s_whh  = sm + 16896;
    float* s_wih8 = sm + 29184;
    float* s_h1w  = sm + 30720;
    float* s_red  = sm + 34816;
    float* s_bhn  = sm + 35840;
    float* s_h1b  = sm + 35904;
    float* s_h2w  = sm + 35968;
    float* s_h2b  = sm + 36032;

    int tid = threadIdx.x;
    int n0  = blockIdx.x * 64;
    int ng = tid & 31, hg = tid >> 5;    // hg in 0..15
    int nb = ng * 2;                     // 2 nodes per thread

    // ---- prologue: weights & biases ----
    {
        float4* d4; const float4* s4;
        d4 = (float4*)s_whh;  s4 = (const float4*)g_WhhT;
        for (int i = tid; i < 3072; i += 512) d4[i] = s4[i];
        d4 = (float4*)s_wih8; s4 = (const float4*)g_Wih8T;
        if (tid < 384) d4[tid] = s4[tid];
        d4 = (float4*)s_h1w;  s4 = (const float4*)g_h1wT;
        for (int i = tid; i < 1024; i += 512) d4[i] = s4[i];
        if (tid < 64) { s_bhn[tid] = g_bhn[tid]; s_h1b[tid] = h1b[tid]; s_h2w[tid] = h2w[tid]; }
        if (tid == 0) s_h2b[0] = h2b[0];
    }
    // ---- prologue: gi slice for this thread's 2 nodes (resident all steps) ----
#pragma unroll
    for (int i = 0; i < 2; ++i) {
        int gn = min(n0 + nb + i, NN - 1);
        const ulonglong2* g2 = (const ulonglong2*)(g_gi + gn * 192);
        ulonglong2 rv = g2[hg];         // r chunk (j = hg*4..hg*4+3)
        ulonglong2 zv = g2[16 + hg];    // z chunk
        ulonglong2 iv = g2[32 + hg];    // i_n chunk
        s_gi[(i * 6 + 0) * 512 + tid] = rv.x;
        s_gi[(i * 6 + 1) * 512 + tid] = rv.y;
        s_gi[(i * 6 + 2) * 512 + tid] = zv.x;
        s_gi[(i * 6 + 3) * 512 + tid] = zv.y;
        s_gi[(i * 6 + 4) * 512 + tid] = iv.x;
        s_gi[(i * 6 + 5) * 512 + tid] = iv.y;
    }
    // ---- prologue: h0 = 0, stage x_0 ----
    for (int i = tid; i < 4608; i += 512) s_zt[i] = 0.0f;
    if (tid < 64) {
        int gn2 = min(n0 + tid, NN - 1);
        const float4* x4 = (const float4*)(xdyn + (size_t)gn2 * 8);
        float4 a = x4[0], b = x4[1];
        float* dst = s_zt + 64 * 64 + tid;
        dst[0] = a.x; dst[64] = a.y; dst[128] = a.z; dst[192] = a.w;
        dst[256] = b.x; dst[320] = b.y; dst[384] = b.z; dst[448] = b.w;
    }
    __syncthreads();

    u64 bn0 = *(const u64*)(s_bhn + (hg << 2));
    u64 bn1 = *(const u64*)(s_bhn + (hg << 2) + 2);
    u64 hb0 = *(const u64*)(s_h1b + (hg << 2));
    u64 hb1 = *(const u64*)(s_h1b + (hg << 2) + 2);
    float w2a = s_h2w[(hg << 2) + 0], w2b = s_h2w[(hg << 2) + 1];
    float w2c = s_h2w[(hg << 2) + 2], w2d = s_h2w[(hg << 2) + 3];

#pragma unroll 1
    for (int t = 0; t < TT; ++t) {
        // s_zt rows 0-63 = h_old, rows 64-71 = x_t.
        // Gate GEMM for step t + MLP head on h_old (= y_{t-1}).
        u64 ar2[2][2], az2[2][2], ahn2[2][2], ahd2[2][2];
#pragma unroll
        for (int i = 0; i < 2; ++i) {
            ar2[i][0]  = s_gi[(i * 6 + 0) * 512 + tid];
            ar2[i][1]  = s_gi[(i * 6 + 1) * 512 + tid];
            az2[i][0]  = s_gi[(i * 6 + 2) * 512 + tid];
            az2[i][1]  = s_gi[(i * 6 + 3) * 512 + tid];
            ahn2[i][0] = bn0;  ahn2[i][1] = bn1;
            ahd2[i][0] = hb0;  ahd2[i][1] = hb1;
        }

        // ---- K = 64 over h_old: gates r, z, h_n + head H1 ----
#pragma unroll 4
        for (int k = 0; k < 64; ++k) {
            float2 xv = *(const float2*)(s_zt + k * 64 + nb);
            const float* wp = s_whh + k * 192 + (hg << 2);
            ulonglong2 wr = *(const ulonglong2*)(wp);
            ulonglong2 wz = *(const ulonglong2*)(wp + 64);
            ulonglong2 wn = *(const ulonglong2*)(wp + 128);
            ulonglong2 wh = *(const ulonglong2*)(s_h1w + k * 64 + (hg << 2));
            u64 xd[2] = {pack2(xv.x, xv.x), pack2(xv.y, xv.y)};
#pragma unroll
            for (int i = 0; i < 2; ++i) {
                ar2[i][0]  = fma2(xd[i], wr.x, ar2[i][0]);
                ar2[i][1]  = fma2(xd[i], wr.y, ar2[i][1]);
                az2[i][0]  = fma2(xd[i], wz.x, az2[i][0]);
                az2[i][1]  = fma2(xd[i], wz.y, az2[i][1]);
                ahn2[i][0] = fma2(xd[i], wn.x, ahn2[i][0]);
                ahn2[i][1] = fma2(xd[i], wn.y, ahn2[i][1]);
                ahd2[i][0] = fma2(xd[i], wh.x, ahd2[i][0]);
                ahd2[i][1] = fma2(xd[i], wh.y, ahd2[i][1]);
            }
        }

        // ---- head partials (y_{t-1}) — retires ahd2 before k8 ----
#pragma unroll
        for (int i = 0; i < 2; ++i) {
            float p0, p1, p2, p3;
            unpack2(ahd2[i][0], p0, p1);
            unpack2(ahd2[i][1], p2, p3);
            float part = w2a * fmaxf(p0, 0.0f) + w2b * fmaxf(p1, 0.0f)
                       + w2c * fmaxf(p2, 0.0f) + w2d * fmaxf(p3, 0.0f);
            s_red[hg * 64 + nb + i] = part;
        }

        // ---- init i_n accumulators now (liveness) ----
        u64 ain2[2][2];
#pragma unroll
        for (int i = 0; i < 2; ++i) {
            ain2[i][0] = s_gi[(i * 6 + 4) * 512 + tid];
            ain2[i][1] = s_gi[(i * 6 + 5) * 512 + tid];
        }
        // ---- K = 8 over x_dyn: r, z, i_n ----
#pragma unroll
        for (int k = 0; k < 8; ++k) {
            float2 xv = *(const float2*)(s_zt + (64 + k) * 64 + nb);
            const float* wp = s_wih8 + k * 192 + (hg << 2);
            ulonglong2 wr = *(const ulonglong2*)(wp);
            ulonglong2 wz = *(const ulonglong2*)(wp + 64);
            ulonglong2 wi = *(const ulonglong2*)(wp + 128);
            u64 xd[2] = {pack2(xv.x, xv.x), pack2(xv.y, xv.y)};
#pragma unroll
            for (int i = 0; i < 2; ++i) {
                ar2[i][0]  = fma2(xd[i], wr.x, ar2[i][0]);
                ar2[i][1]  = fma2(xd[i], wr.y, ar2[i][1]);
                az2[i][0]  = fma2(xd[i], wz.x, az2[i][0]);
                az2[i][1]  = fma2(xd[i], wz.y, az2[i][1]);
                ain2[i][0] = fma2(xd[i], wi.x, ain2[i][0]);
                ain2[i][1] = fma2(xd[i], wi.y, ain2[i][1]);
            }
        }
        __syncthreads();   // GEMM reads of s_zt done; s_red complete

        // ---- write y_{t-1} ----
        if (t > 0 && tid < 64) {
            float s = 0.0f;
#pragma unroll
            for (int g = 0; g < 16; ++g) s += s_red[g * 64 + tid];
            int gn = n0 + tid;
            if (gn < NN)
                yout[(size_t)(t - 1) * NN + gn] = sigf(s + s_h2b[0]);
        }

        // ---- gates + in-place h update (own slots only) ----
#pragma unroll
        for (int i = 0; i < 2; ++i) {
            int nl = nb + i;
#pragma unroll
            for (int jp = 0; jp < 2; ++jp) {
                float r0, r1, z0, z1, in0, in1, hn0, hn1;
                unpack2(ar2[i][jp],  r0,  r1);
                unpack2(az2[i][jp],  z0,  z1);
                unpack2(ain2[i][jp], in0, in1);
                unpack2(ahn2[i][jp], hn0, hn1);
                float hpa = s_zt[(hg * 4 + jp * 2 + 0) * 64 + nl];
                float hpb = s_zt[(hg * 4 + jp * 2 + 1) * 64 + nl];
                float ra = sigf_fast(r0), rb = sigf_fast(r1);
                float za = sigf_fast(z0), zb = sigf_fast(z1);
                float na  = tanh_mufu(in0 + ra * hn0);
                float nbv = tanh_mufu(in1 + rb * hn1);
                float ha = na  + za * (hpa - na);
                float hb = nbv + zb * (hpb - nbv);
                s_zt[(hg * 4 + jp * 2 + 0) * 64 + nl] = ha;
                s_zt[(hg * 4 + jp * 2 + 1) * 64 + nl] = hb;
            }
        }

        // ---- stage x_{t+1} into rows 64..71 (not read again this iter) ----
        if (t < TT - 1 && tid < 64) {
            int gn2 = min(n0 + tid, NN - 1);
            const float4* x4 = (const float4*)(xdyn + ((size_t)(t + 1) * NN + gn2) * 8);
            float4 a = x4[0], b = x4[1];
            float* dst = s_zt + 64 * 64 + tid;
            dst[0] = a.x; dst[64] = a.y; dst[128] = a.z; dst[192] = a.w;
            dst[256] = b.x; dst[320] = b.y; dst[384] = b.z; dst[448] = b.w;
        }
        __syncthreads();
    }

    // ---- tail: head for the final h (y_23) ----
    {
        u64 ahd2[2][2];
#pragma unroll
        for (int i = 0; i < 2; ++i) { ahd2[i][0] = hb0; ahd2[i][1] = hb1; }
#pragma unroll 4
        for (int k = 0; k < 64; ++k) {
            float2 xv = *(const float2*)(s_zt + k * 64 + nb);
            ulonglong2 wh = *(const ulonglong2*)(s_h1w + k * 64 + (hg << 2));
            u64 xd[2] = {pack2(xv.x, xv.x), pack2(xv.y, xv.y)};
#pragma unroll
            for (int i = 0; i < 2; ++i) {
                ahd2[i][0] = fma2(xd[i], wh.x, ahd2[i][0]);
                ahd2[i][1] = fma2(xd[i], wh.y, ahd2[i][1]);
            }
        }
#pragma unroll
        for (int i = 0; i < 2; ++i) {
            float p0, p1, p2, p3;
            unpack2(ahd2[i][0], p0, p1);
            unpack2(ahd2[i][1], p2, p3);
            float part = w2a * fmaxf(p0, 0.0f) + w2b * fmaxf(p1, 0.0f)
                       + w2c * fmaxf(p2, 0.0f) + w2d * fmaxf(p3, 0.0f);
            s_red[hg * 64 + nb + i] = part;
        }
        __syncthreads();
        if (tid < 64) {
            float s = 0.0f;
#pragma unroll
            for (int g = 0; g < 16; ++g) s += s_red[g * 64 + tid];
            int gn = n0 + tid;
            if (gn < NN)
                yout[(size_t)(TT - 1) * NN + gn] = sigf(s + s_h2b[0]);
        }
    }
}

// ----------------------------------------------------------------------------
// Launch (6 kernels total)
// ----------------------------------------------------------------------------
extern "C" void kernel_launch(void* const* d_in, const int* in_sizes, int n_in,
                              void* d_out, int out_size) {
    const float* X_static = (const float*)d_in[0];
    const float* X_dyn    = (const float*)d_in[1];
    const int*   er       = (const int*)d_in[2];
    const int*   ec       = (const int*)d_in[3];
    const float* ev       = (const float*)d_in[4];
    const float* g1W      = (const float*)d_in[5];
    const float* g1b      = (const float*)d_in[6];
    const float* g2W      = (const float*)d_in[7];
    const float* g2b      = (const float*)d_in[8];
    const float* Wih      = (const float*)d_in[9];
    const float* Whh      = (const float*)d_in[10];
    const float* bih      = (const float*)d_in[11];
    const float* bhh      = (const float*)d_in[12];
    const float* h1W      = (const float*)d_in[13];
    const float* h1b      = (const float*)d_in[14];
    const float* h2W      = (const float*)d_in[15];
    const float* h2b      = (const float*)d_in[16];
    float* out = (float*)d_out;

    cudaFuncSetAttribute(gru_persistent_kernel,
                         cudaFuncAttributeMaxDynamicSharedMemorySize, GRU_SMEM_BYTES);

    // GraphConv layer 1 (lin32 also zeroes g_acc)
    lin32_kernel<<<3125, 256>>>(X_static, g1W, g1b, 0);
    spmm_kernel<<<100000, 256>>>(er, ec, ev);

    // GraphConv layer 2 (relu on read of g_acc, then re-zero)
    lin32_kernel<<<3125, 256>>>(X_static /*unused*/, g2W, g2b, 1);
    spmm_kernel<<<100000, 256>>>(er, ec, ev);

    // Time-invariant gate projections + weight prep (fused)
    gi_prep_kernel<<<3125, 256>>>(Wih, bih, bhh, Whh, h1W);

    // Persistent GRU: 64-node tiles, all 24 steps + fused MLP head
    gru_persistent_kernel<<<1563, 512, GRU_SMEM_BYTES>>>(X_dyn, h1b, h2W, h2b, out);
}

// round 7
// speedup vs baseline: 1.1193x; 1.0096x over previous
#include <cuda_runtime.h>
#include <math.h>

#define DINLINE __device__ __forceinline__
typedef unsigned long long u64;

constexpr int NN = 100000;   // nodes
constexpr int TT = 24;       // time steps
constexpr int EE = 3200000;  // edges

// ----------------------------------------------------------------------------
// Scratch (static device globals; no allocations allowed)
// ----------------------------------------------------------------------------
__device__ __align__(16) float g_xw[NN * 32];      // linear output / spmm input
__device__ __align__(16) float g_acc[NN * 32];     // spmm accumulator
__device__ __align__(16) float g_gi[NN * 192];     // time-invariant input-gate projections (+bias)
__device__ __align__(16) float g_WhhT[64 * 192];   // W_hh transposed: [k][j]  (j order: r|z|n)
__device__ __align__(16) float g_Wih8T[8 * 192];   // W_ih[:,32:40] transposed: [k8][j]
__device__ __align__(16) float g_h1wT[64 * 64];    // h1_W transposed: [k][j]
__device__ __align__(16) float g_bhn[64];          // b_hh[128:192]

DINLINE float sigf(float x)  { return __fdividef(1.0f, 1.0f + __expf(-x)); }
// MUFU.TANH (abs err ~5e-4) — used for r/z/n gates
DINLINE float tanh_mufu(float x) {
    float y; asm("tanh.approx.f32 %0, %1;" : "=f"(y) : "f"(x)); return y;
}
DINLINE float sigf_fast(float x) { return fmaf(0.5f, tanh_mufu(0.5f * x), 0.5f); }

// f32x2 packed math (sm_103a FFMA2 — only reachable via PTX)
DINLINE u64 pack2(float lo, float hi) {
    u64 r; asm("mov.b64 %0, {%1, %2};" : "=l"(r) : "f"(lo), "f"(hi)); return r;
}
DINLINE void unpack2(u64 v, float& lo, float& hi) {
    asm("mov.b64 {%0, %1}, %2;" : "=f"(lo), "=f"(hi) : "l"(v));
}
DINLINE u64 fma2(u64 a, u64 b, u64 c) {
    u64 d; asm("fma.rn.f32x2 %0, %1, %2, %3;" : "=l"(d) : "l"(a), "l"(b), "l"(c)); return d;
}

// ----------------------------------------------------------------------------
// Dense 32->32 linear + g_acc zeroing. 32 nodes / 256-thread block; grid 3125.
// ----------------------------------------------------------------------------
__global__ void lin32_kernel(const float* __restrict__ Xext,
                             const float* __restrict__ W,
                             const float* __restrict__ bias,
                             int relu_acc_src) {
    __shared__ float Wt[1024];      // Wt[k*32+j] = W[j][k]
    __shared__ float Xs[32 * 33];   // 32 nodes, padded rows
    int tid = threadIdx.x;
    int n0  = blockIdx.x * 32;

    for (int e = tid; e < 1024; e += 256) {
        int j = e >> 5, k = e & 31;
        Wt[k * 32 + j] = W[j * 32 + k];
    }
    for (int e = tid; e < 1024; e += 256) {
        int n = e >> 5, k = e & 31;
        float v;
        if (relu_acc_src) v = fmaxf(g_acc[(n0 + n) * 32 + k], 0.0f);
        else              v = Xext[(n0 + n) * 32 + k];
        Xs[n * 33 + k] = v;
    }
    __syncthreads();

    // zero this block's g_acc slice for the following spmm
    for (int e = tid; e < 1024; e += 256)
        g_acc[n0 * 32 + e] = 0.0f;

    int j = tid & 31;
    float b = bias[j];
#pragma unroll
    for (int g = 0; g < 4; ++g) {
        int n = (tid >> 5) + g * 8;
        float acc = b;
#pragma unroll
        for (int k = 0; k < 32; ++k)
            acc = fmaf(Xs[n * 33 + k], Wt[k * 32 + j], acc);
        g_xw[(n0 + n) * 32 + j] = acc;
    }
}

// ----------------------------------------------------------------------------
// SpMM scatter with vector REDs: 8 threads / edge, one v4 red each.
// grid = E*8/256 = 100000 blocks exactly.
// ----------------------------------------------------------------------------
__global__ void spmm_kernel(const int*  __restrict__ er,
                            const int*  __restrict__ ec,
                            const float* __restrict__ ev) {
    int idx = blockIdx.x * 256 + threadIdx.x;
    int e = idx >> 3, q = idx & 7;
    int r = __ldg(er + e);
    int c = __ldg(ec + e);
    float v = __ldg(ev + e);
    float4 x = *(const float4*)(g_xw + c * 32 + q * 4);
    float* dst = g_acc + r * 32 + q * 4;
    asm volatile("red.global.add.v4.f32 [%0], {%1, %2, %3, %4};"
                 :: "l"(dst), "f"(v * x.x), "f"(v * x.y), "f"(v * x.z), "f"(v * x.w)
                 : "memory");
}

// ----------------------------------------------------------------------------
// gi_static + weight prep (fused). 32 nodes / 256-thread block; grid 3125.
// ----------------------------------------------------------------------------
__global__ void gi_prep_kernel(const float* __restrict__ Wih,
                               const float* __restrict__ bih,
                               const float* __restrict__ bhh,
                               const float* __restrict__ Whh,
                               const float* __restrict__ h1W) {
    __shared__ float Ws[32 * 192];   // Ws[k*192+j] = W_ih[j][k]
    __shared__ float Hs[32 * 33];    // relu'd h tile, padded rows
    int tid = threadIdx.x;
    int n0  = blockIdx.x * 32;

    // weight-prep side work on the first 36 blocks (2 ids each thread)
    if (blockIdx.x < 36) {
#pragma unroll
        for (int h = 0; h < 2; ++h) {
            int id = blockIdx.x * 512 + h * 256 + tid;
            if (id < 12288) {                       // W_hh: [192][64] -> [64][192]
                int k = id / 192, j = id - k * 192;
                g_WhhT[id] = Whh[j * 64 + k];
            } else if (id < 13824) {                // W_ih cols 32..39 -> [8][192]
                int q = id - 12288;
                int k = q / 192, j = q - k * 192;
                g_Wih8T[q] = Wih[j * 40 + 32 + k];
            } else if (id < 17920) {                // h1_W -> transposed [64][64]
                int q = id - 13824;
                int k = q >> 6, j = q & 63;
                g_h1wT[q] = h1W[j * 64 + k];
            } else if (id < 17984) {
                g_bhn[id - 17920] = bhh[128 + id - 17920];
            }
        }
    }

    for (int e = tid; e < 6144; e += 256) {
        int k = e / 192, j = e - k * 192;
        Ws[e] = Wih[j * 40 + k];
    }
    for (int e = tid; e < 1024; e += 256) {
        int n = e >> 5, k = e & 31;
        Hs[n * 33 + k] = fmaxf(g_acc[(n0 + n) * 32 + k], 0.0f);
    }
    __syncthreads();

#pragma unroll 1
    for (int it = 0; it < 24; ++it) {
        int p = it * 256 + tid;        // 32*192 = 6144 = 24*256
        int n = p / 192, j = p - n * 192;
        float acc = bih[j] + (j < 128 ? bhh[j] : 0.0f);
#pragma unroll
        for (int k = 0; k < 32; ++k)
            acc = fmaf(Hs[n * 33 + k], Ws[k * 192 + j], acc);
        g_gi[(n0 + n) * 192 + j] = acc;
    }
}

// ----------------------------------------------------------------------------
// Persistent GRU: one block = 64 nodes, 512 threads, all 24 steps.
// Fully double-buffered (h, x, red) -> ONE barrier per step.
// Thread (ng = tid&31, hg = tid>>5) owns 2 nodes x 4 hidden units.
// MLP head for h_{t-1} fused into step t's gate GEMM; y_{t-2} written at the
// top of step t (hidden under the GEMM).
// ----------------------------------------------------------------------------
// smem float offsets:
//   s_h[2]  2*4096 @ 0        (h buffers, [64 k][64 n])
//   s_x[2]  2*512  @ 8192     (x buffers, [8 k][64 n])
//   s_gi    12288  @ 9216     (6144 u64)
//   s_whh   12288  @ 21504
//   s_wih8  1536   @ 33792
//   s_h1w   4096   @ 35328
//   s_red[2] 2*1024 @ 39424   ([16 hg][64 n])
//   s_bhn   64     @ 41472
//   s_h1b   64     @ 41536
//   s_h2w   64     @ 41600
//   s_h2b   4      @ 41664
constexpr int GRU_SMEM_FLOATS = 41668;
constexpr int GRU_SMEM_BYTES  = GRU_SMEM_FLOATS * 4;   // 166,672 B

__global__ void __launch_bounds__(512, 1)
gru_persistent_kernel(const float* __restrict__ xdyn,   // X_dyn_mean base
                      const float* __restrict__ h1b,
                      const float* __restrict__ h2w,
                      const float* __restrict__ h2b,
                      float* __restrict__ yout) {        // d_out base
    extern __shared__ float sm[];
    float* s_h    = sm;                       // two 4096 buffers
    float* s_x    = sm + 8192;                // two 512 buffers
    u64*   s_gi   = (u64*)(sm + 9216);
    float* s_whh  = sm + 21504;
    float* s_wih8 = sm + 33792;
    float* s_h1w  = sm + 35328;
    float* s_red  = sm + 39424;               // two 1024 buffers
    float* s_bhn  = sm + 41472;
    float* s_h1b  = sm + 41536;
    float* s_h2w  = sm + 41600;
    float* s_h2b  = sm + 41664;

    int tid = threadIdx.x;
    int n0  = blockIdx.x * 64;
    int ng = tid & 31, hg = tid >> 5;    // hg in 0..15
    int nb = ng * 2;                     // 2 nodes per thread

    // ---- prologue: weights & biases ----
    {
        float4* d4; const float4* s4;
        d4 = (float4*)s_whh;  s4 = (const float4*)g_WhhT;
        for (int i = tid; i < 3072; i += 512) d4[i] = s4[i];
        d4 = (float4*)s_wih8; s4 = (const float4*)g_Wih8T;
        if (tid < 384) d4[tid] = s4[tid];
        d4 = (float4*)s_h1w;  s4 = (const float4*)g_h1wT;
        for (int i = tid; i < 1024; i += 512) d4[i] = s4[i];
        if (tid < 64) { s_bhn[tid] = g_bhn[tid]; s_h1b[tid] = h1b[tid]; s_h2w[tid] = h2w[tid]; }
        if (tid == 0) s_h2b[0] = h2b[0];
    }
    // ---- prologue: gi slice for this thread's 2 nodes (resident all steps) ----
#pragma unroll
    for (int i = 0; i < 2; ++i) {
        int gn = min(n0 + nb + i, NN - 1);
        const ulonglong2* g2 = (const ulonglong2*)(g_gi + gn * 192);
        ulonglong2 rv = g2[hg];         // r chunk (j = hg*4..hg*4+3)
        ulonglong2 zv = g2[16 + hg];    // z chunk
        ulonglong2 iv = g2[32 + hg];    // i_n chunk
        s_gi[(i * 6 + 0) * 512 + tid] = rv.x;
        s_gi[(i * 6 + 1) * 512 + tid] = rv.y;
        s_gi[(i * 6 + 2) * 512 + tid] = zv.x;
        s_gi[(i * 6 + 3) * 512 + tid] = zv.y;
        s_gi[(i * 6 + 4) * 512 + tid] = iv.x;
        s_gi[(i * 6 + 5) * 512 + tid] = iv.y;
    }
    // ---- prologue: h[-1] = 0 in buffer 1 (read by t=0); stage x_0 into x[0] ----
    for (int i = tid; i < 4096; i += 512) s_h[4096 + i] = 0.0f;
    if (tid < 64) {
        int gn2 = min(n0 + tid, NN - 1);
        const float4* x4 = (const float4*)(xdyn + (size_t)gn2 * 8);
        float4 a = x4[0], b = x4[1];
        float* dst = s_x + tid;          // x buffer 0
        dst[0] = a.x; dst[64] = a.y; dst[128] = a.z; dst[192] = a.w;
        dst[256] = b.x; dst[320] = b.y; dst[384] = b.z; dst[448] = b.w;
    }
    __syncthreads();

    u64 bn0 = *(const u64*)(s_bhn + (hg << 2));
    u64 bn1 = *(const u64*)(s_bhn + (hg << 2) + 2);
    u64 hb0 = *(const u64*)(s_h1b + (hg << 2));
    u64 hb1 = *(const u64*)(s_h1b + (hg << 2) + 2);
    float w2a = s_h2w[(hg << 2) + 0], w2b = s_h2w[(hg << 2) + 1];
    float w2c = s_h2w[(hg << 2) + 2], w2d = s_h2w[(hg << 2) + 3];

#pragma unroll 1
    for (int t = 0; t < TT; ++t) {
        int pw = (t & 1);                 // this step writes h[pw], red[pw]
        const float* hOld = s_h + ((t + 1) & 1) * 4096;   // h_{t-1}
        float*       hNew = s_h + pw * 4096;              // h_t
        const float* xCur = s_x + pw * 512;               // x_t
        float*       xNxt = s_x + ((t + 1) & 1) * 512;    // x_{t+1} staging
        float*       redW = s_red + pw * 1024;
        const float* redR = s_red + ((t + 1) & 1) * 1024; // head(h_{t-2})

        // ---- prefetch x_{t+1} from GMEM (latency hidden under GEMM) ----
        float4 xpa, xpb;
        if (t < TT - 1 && tid < 64) {
            int gn2 = min(n0 + tid, NN - 1);
            const float4* x4 = (const float4*)(xdyn + ((size_t)(t + 1) * NN + gn2) * 8);
            xpa = x4[0]; xpb = x4[1];
        }
        // ---- write y_{t-2} from the red buffer completed last step ----
        if (t >= 2 && tid < 64) {
            float s = 0.0f;
#pragma unroll
            for (int g = 0; g < 16; ++g) s += redR[g * 64 + tid];
            int gn = n0 + tid;
            if (gn < NN)
                yout[(size_t)(t - 2) * NN + gn] = sigf(s + s_h2b[0]);
        }

        // ---- accumulators from resident gi ----
        u64 ar2[2][2], az2[2][2], ahn2[2][2], ahd2[2][2];
#pragma unroll
        for (int i = 0; i < 2; ++i) {
            ar2[i][0]  = s_gi[(i * 6 + 0) * 512 + tid];
            ar2[i][1]  = s_gi[(i * 6 + 1) * 512 + tid];
            az2[i][0]  = s_gi[(i * 6 + 2) * 512 + tid];
            az2[i][1]  = s_gi[(i * 6 + 3) * 512 + tid];
            ahn2[i][0] = bn0;  ahn2[i][1] = bn1;
            ahd2[i][0] = hb0;  ahd2[i][1] = hb1;
        }

        // ---- K = 64 over h_old: gates r, z, h_n + head H1 ----
#pragma unroll 4
        for (int k = 0; k < 64; ++k) {
            float2 xv = *(const float2*)(hOld + k * 64 + nb);
            const float* wp = s_whh + k * 192 + (hg << 2);
            ulonglong2 wr = *(const ulonglong2*)(wp);
            ulonglong2 wz = *(const ulonglong2*)(wp + 64);
            ulonglong2 wn = *(const ulonglong2*)(wp + 128);
            ulonglong2 wh = *(const ulonglong2*)(s_h1w + k * 64 + (hg << 2));
            u64 xd[2] = {pack2(xv.x, xv.x), pack2(xv.y, xv.y)};
#pragma unroll
            for (int i = 0; i < 2; ++i) {
                ar2[i][0]  = fma2(xd[i], wr.x, ar2[i][0]);
                ar2[i][1]  = fma2(xd[i], wr.y, ar2[i][1]);
                az2[i][0]  = fma2(xd[i], wz.x, az2[i][0]);
                az2[i][1]  = fma2(xd[i], wz.y, az2[i][1]);
                ahn2[i][0] = fma2(xd[i], wn.x, ahn2[i][0]);
                ahn2[i][1] = fma2(xd[i], wn.y, ahn2[i][1]);
                ahd2[i][0] = fma2(xd[i], wh.x, ahd2[i][0]);
                ahd2[i][1] = fma2(xd[i], wh.y, ahd2[i][1]);
            }
        }

        // ---- head partials (h_{t-1}) into red[pw] — retires ahd2 ----
#pragma unroll
        for (int i = 0; i < 2; ++i) {
            float p0, p1, p2, p3;
            unpack2(ahd2[i][0], p0, p1);
            unpack2(ahd2[i][1], p2, p3);
            float part = w2a * fmaxf(p0, 0.0f) + w2b * fmaxf(p1, 0.0f)
                       + w2c * fmaxf(p2, 0.0f) + w2d * fmaxf(p3, 0.0f);
            redW[hg * 64 + nb + i] = part;
        }

        // ---- init i_n accumulators now (liveness) ----
        u64 ain2[2][2];
#pragma unroll
        for (int i = 0; i < 2; ++i) {
            ain2[i][0] = s_gi[(i * 6 + 4) * 512 + tid];
            ain2[i][1] = s_gi[(i * 6 + 5) * 512 + tid];
        }
        // ---- K = 8 over x_dyn: r, z, i_n ----
#pragma unroll
        for (int k = 0; k < 8; ++k) {
            float2 xv = *(const float2*)(xCur + k * 64 + nb);
            const float* wp = s_wih8 + k * 192 + (hg << 2);
            ulonglong2 wr = *(const ulonglong2*)(wp);
            ulonglong2 wz = *(const ulonglong2*)(wp + 64);
            ulonglong2 wi = *(const ulonglong2*)(wp + 128);
            u64 xd[2] = {pack2(xv.x, xv.x), pack2(xv.y, xv.y)};
#pragma unroll
            for (int i = 0; i < 2; ++i) {
                ar2[i][0]  = fma2(xd[i], wr.x, ar2[i][0]);
                ar2[i][1]  = fma2(xd[i], wr.y, ar2[i][1]);
                az2[i][0]  = fma2(xd[i], wz.x, az2[i][0]);
                az2[i][1]  = fma2(xd[i], wz.y, az2[i][1]);
                ain2[i][0] = fma2(xd[i], wi.x, ain2[i][0]);
                ain2[i][1] = fma2(xd[i], wi.y, ain2[i][1]);
            }
        }

        // ---- gates + h update into the OTHER h buffer (no barrier needed) ----
#pragma unroll
        for (int i = 0; i < 2; ++i) {
            int nl = nb + i;
#pragma unroll
            for (int jp = 0; jp < 2; ++jp) {
                float r0, r1, z0, z1, in0, in1, hn0, hn1;
                unpack2(ar2[i][jp],  r0,  r1);
                unpack2(az2[i][jp],  z0,  z1);
                unpack2(ain2[i][jp], in0, in1);
                unpack2(ahn2[i][jp], hn0, hn1);
                float hpa = hOld[(hg * 4 + jp * 2 + 0) * 64 + nl];
                float hpb = hOld[(hg * 4 + jp * 2 + 1) * 64 + nl];
                float ra = sigf_fast(r0), rb = sigf_fast(r1);
                float za = sigf_fast(z0), zb = sigf_fast(z1);
                float na  = tanh_mufu(in0 + ra * hn0);
                float nbv = tanh_mufu(in1 + rb * hn1);
                float ha = na  + za * (hpa - na);
                float hb = nbv + zb * (hpb - nbv);
                hNew[(hg * 4 + jp * 2 + 0) * 64 + nl] = ha;
                hNew[(hg * 4 + jp * 2 + 1) * 64 + nl] = hb;
            }
        }

        // ---- store prefetched x_{t+1} into the other x buffer ----
        if (t < TT - 1 && tid < 64) {
            float* dst = xNxt + tid;
            dst[0] = xpa.x; dst[64] = xpa.y; dst[128] = xpa.z; dst[192] = xpa.w;
            dst[256] = xpb.x; dst[320] = xpb.y; dst[384] = xpb.z; dst[448] = xpb.w;
        }
        __syncthreads();   // single barrier: publishes hNew, xNxt, redW
    }

    // ---- tail 1: y_{TT-2} from red[(TT-1)&1] ----
    if (tid < 64) {
        const float* redR = s_red + ((TT - 1) & 1) * 1024;
        float s = 0.0f;
#pragma unroll
        for (int g = 0; g < 16; ++g) s += redR[g * 64 + tid];
        int gn = n0 + tid;
        if (gn < NN)
            yout[(size_t)(TT - 2) * NN + gn] = sigf(s + s_h2b[0]);
    }

    // ---- tail 2: head for the final h (y_{TT-1}) ----
    {
        const float* hF = s_h + ((TT - 1) & 1) * 4096;   // h_{TT-1}
        float* redW = s_red;                              // reuse buffer 0
        u64 ahd2[2][2];
#pragma unroll
        for (int i = 0; i < 2; ++i) { ahd2[i][0] = hb0; ahd2[i][1] = hb1; }
#pragma unroll 4
        for (int k = 0; k < 64; ++k) {
            float2 xv = *(const float2*)(hF + k * 64 + nb);
            ulonglong2 wh = *(const ulonglong2*)(s_h1w + k * 64 + (hg << 2));
            u64 xd[2] = {pack2(xv.x, xv.x), pack2(xv.y, xv.y)};
#pragma unroll
            for (int i = 0; i < 2; ++i) {
                ahd2[i][0] = fma2(xd[i], wh.x, ahd2[i][0]);
                ahd2[i][1] = fma2(xd[i], wh.y, ahd2[i][1]);
            }
        }
#pragma unroll
        for (int i = 0; i < 2; ++i) {
            float p0, p1, p2, p3;
            unpack2(ahd2[i][0], p0, p1);
            unpack2(ahd2[i][1], p2, p3);
            float part = w2a * fmaxf(p0, 0.0f) + w2b * fmaxf(p1, 0.0f)
                       + w2c * fmaxf(p2, 0.0f) + w2d * fmaxf(p3, 0.0f);
            redW[hg * 64 + nb + i] = part;
        }
        __syncthreads();
        if (tid < 64) {
            float s = 0.0f;
#pragma unroll
            for (int g = 0; g < 16; ++g) s += redW[g * 64 + tid];
            int gn = n0 + tid;
            if (gn < NN)
                yout[(size_t)(TT - 1) * NN + gn] = sigf(s + s_h2b[0]);
        }
    }
}

// ----------------------------------------------------------------------------
// Launch (6 kernels total)
// ----------------------------------------------------------------------------
extern "C" void kernel_launch(void* const* d_in, const int* in_sizes, int n_in,
                              void* d_out, int out_size) {
    const float* X_static = (const float*)d_in[0];
    const float* X_dyn    = (const float*)d_in[1];
    const int*   er       = (const int*)d_in[2];
    const int*   ec       = (const int*)d_in[3];
    const float* ev       = (const float*)d_in[4];
    const float* g1W      = (const float*)d_in[5];
    const float* g1b      = (const float*)d_in[6];
    const float* g2W      = (const float*)d_in[7];
    const float* g2b      = (const float*)d_in[8];
    const float* Wih      = (const float*)d_in[9];
    const float* Whh      = (const float*)d_in[10];
    const float* bih      = (const float*)d_in[11];
    const float* bhh      = (const float*)d_in[12];
    const float* h1W      = (const float*)d_in[13];
    const float* h1b      = (const float*)d_in[14];
    const float* h2W      = (const float*)d_in[15];
    const float* h2b      = (const float*)d_in[16];
    float* out = (float*)d_out;

    cudaFuncSetAttribute(gru_persistent_kernel,
                         cudaFuncAttributeMaxDynamicSharedMemorySize, GRU_SMEM_BYTES);

    // GraphConv layer 1 (lin32 also zeroes g_acc)
    lin32_kernel<<<3125, 256>>>(X_static, g1W, g1b, 0);
    spmm_kernel<<<100000, 256>>>(er, ec, ev);

    // GraphConv layer 2 (relu on read of g_acc, then re-zero)
    lin32_kernel<<<3125, 256>>>(X_static /*unused*/, g2W, g2b, 1);
    spmm_kernel<<<100000, 256>>>(er, ec, ev);

    // Time-invariant gate projections + weight prep (fused)
    gi_prep_kernel<<<3125, 256>>>(Wih, bih, bhh, Whh, h1W);

    // Persistent GRU: 64-node tiles, all 24 steps, 1 barrier/step
    gru_persistent_kernel<<<1563, 512, GRU_SMEM_BYTES>>>(X_dyn, h1b, h2W, h2b, out);
}

// round 8
// speedup vs baseline: 1.1193x; 1.0000x over previous
#include <cuda_runtime.h>
#include <math.h>

#define DINLINE __device__ __forceinline__
typedef unsigned long long u64;

constexpr int NN = 100000;   // nodes
constexpr int TT = 24;       // time steps
constexpr int EE = 3200000;  // edges

// ----------------------------------------------------------------------------
// Scratch (static device globals; no allocations allowed)
// ----------------------------------------------------------------------------
__device__ __align__(16) float g_xw[NN * 32];      // linear output / spmm input
__device__ __align__(16) float g_acc[NN * 32];     // spmm accumulator
__device__ __align__(16) float g_gi[NN * 192];     // time-invariant input-gate projections (+bias)
__device__ __align__(16) float g_WhhT[64 * 192];   // W_hh transposed: [k][j]  (j order: r|z|n)
__device__ __align__(16) float g_Wih8T[8 * 192];   // W_ih[:,32:40] transposed: [k8][j]
__device__ __align__(16) float g_h1wT[64 * 64];    // h1_W transposed: [k][j]
__device__ __align__(16) float g_bhn[64];          // b_hh[128:192]

DINLINE float sigf(float x)  { return __fdividef(1.0f, 1.0f + __expf(-x)); }
// MUFU.TANH (abs err ~5e-4) — used for r/z/n gates
DINLINE float tanh_mufu(float x) {
    float y; asm("tanh.approx.f32 %0, %1;" : "=f"(y) : "f"(x)); return y;
}
DINLINE float sigf_fast(float x) { return fmaf(0.5f, tanh_mufu(0.5f * x), 0.5f); }

// f32x2 packed math (sm_103a FFMA2 — only reachable via PTX)
DINLINE u64 pack2(float lo, float hi) {
    u64 r; asm("mov.b64 %0, {%1, %2};" : "=l"(r) : "f"(lo), "f"(hi)); return r;
}
DINLINE void unpack2(u64 v, float& lo, float& hi) {
    asm("mov.b64 {%0, %1}, %2;" : "=f"(lo), "=f"(hi) : "l"(v));
}
DINLINE u64 fma2(u64 a, u64 b, u64 c) {
    u64 d; asm("fma.rn.f32x2 %0, %1, %2, %3;" : "=l"(d) : "l"(a), "l"(b), "l"(c)); return d;
}

// ----------------------------------------------------------------------------
// Dense 32->32 linear + g_acc zeroing. 32 nodes / 256-thread block; grid 3125.
// ----------------------------------------------------------------------------
__global__ void lin32_kernel(const float* __restrict__ Xext,
                             const float* __restrict__ W,
                             const float* __restrict__ bias,
                             int relu_acc_src) {
    __shared__ float Wt[1024];      // Wt[k*32+j] = W[j][k]
    __shared__ float Xs[32 * 33];   // 32 nodes, padded rows
    int tid = threadIdx.x;
    int n0  = blockIdx.x * 32;

    for (int e = tid; e < 1024; e += 256) {
        int j = e >> 5, k = e & 31;
        Wt[k * 32 + j] = W[j * 32 + k];
    }
    for (int e = tid; e < 1024; e += 256) {
        int n = e >> 5, k = e & 31;
        float v;
        if (relu_acc_src) v = fmaxf(g_acc[(n0 + n) * 32 + k], 0.0f);
        else              v = Xext[(n0 + n) * 32 + k];
        Xs[n * 33 + k] = v;
    }
    __syncthreads();

    // zero this block's g_acc slice for the following spmm
    for (int e = tid; e < 1024; e += 256)
        g_acc[n0 * 32 + e] = 0.0f;

    int j = tid & 31;
    float b = bias[j];
#pragma unroll
    for (int g = 0; g < 4; ++g) {
        int n = (tid >> 5) + g * 8;
        float acc = b;
#pragma unroll
        for (int k = 0; k < 32; ++k)
            acc = fmaf(Xs[n * 33 + k], Wt[k * 32 + j], acc);
        g_xw[(n0 + n) * 32 + j] = acc;
    }
}

// ----------------------------------------------------------------------------
// SpMM scatter with vector REDs: 8 threads / edge, one v4 red each.
// grid = E*8/256 = 100000 blocks exactly.
// ----------------------------------------------------------------------------
__global__ void spmm_kernel(const int*  __restrict__ er,
                            const int*  __restrict__ ec,
                            const float* __restrict__ ev) {
    int idx = blockIdx.x * 256 + threadIdx.x;
    int e = idx >> 3, q = idx & 7;
    int r = __ldg(er + e);
    int c = __ldg(ec + e);
    float v = __ldg(ev + e);
    float4 x = *(const float4*)(g_xw + c * 32 + q * 4);
    float* dst = g_acc + r * 32 + q * 4;
    asm volatile("red.global.add.v4.f32 [%0], {%1, %2, %3, %4};"
                 :: "l"(dst), "f"(v * x.x), "f"(v * x.y), "f"(v * x.z), "f"(v * x.w)
                 : "memory");
}

// ----------------------------------------------------------------------------
// gi_static + weight prep (fused). 32 nodes / 256-thread block; grid 3125.
// ----------------------------------------------------------------------------
__global__ void gi_prep_kernel(const float* __restrict__ Wih,
                               const float* __restrict__ bih,
                               const float* __restrict__ bhh,
                               const float* __restrict__ Whh,
                               const float* __restrict__ h1W) {
    __shared__ float Ws[32 * 192];   // Ws[k*192+j] = W_ih[j][k]
    __shared__ float Hs[32 * 33];    // relu'd h tile, padded rows
    int tid = threadIdx.x;
    int n0  = blockIdx.x * 32;

    // weight-prep side work on the first 36 blocks (2 ids each thread)
    if (blockIdx.x < 36) {
#pragma unroll
        for (int h = 0; h < 2; ++h) {
            int id = blockIdx.x * 512 + h * 256 + tid;
            if (id < 12288) {                       // W_hh: [192][64] -> [64][192]
                int k = id / 192, j = id - k * 192;
                g_WhhT[id] = Whh[j * 64 + k];
            } else if (id < 13824) {                // W_ih cols 32..39 -> [8][192]
                int q = id - 12288;
                int k = q / 192, j = q - k * 192;
                g_Wih8T[q] = Wih[j * 40 + 32 + k];
            } else if (id < 17920) {                // h1_W -> transposed [64][64]
                int q = id - 13824;
                int k = q >> 6, j = q & 63;
                g_h1wT[q] = h1W[j * 64 + k];
            } else if (id < 17984) {
                g_bhn[id - 17920] = bhh[128 + id - 17920];
            }
        }
    }

    for (int e = tid; e < 6144; e += 256) {
        int k = e / 192, j = e - k * 192;
        Ws[e] = Wih[j * 40 + k];
    }
    for (int e = tid; e < 1024; e += 256) {
        int n = e >> 5, k = e & 31;
        Hs[n * 33 + k] = fmaxf(g_acc[(n0 + n) * 32 + k], 0.0f);
    }
    __syncthreads();

#pragma unroll 1
    for (int it = 0; it < 24; ++it) {
        int p = it * 256 + tid;        // 32*192 = 6144 = 24*256
        int n = p / 192, j = p - n * 192;
        float acc = bih[j] + (j < 128 ? bhh[j] : 0.0f);
#pragma unroll
        for (int k = 0; k < 32; ++k)
            acc = fmaf(Hs[n * 33 + k], Ws[k * 192 + j], acc);
        g_gi[(n0 + n) * 192 + j] = acc;
    }
}

// ----------------------------------------------------------------------------
// Persistent GRU: one block = 64 nodes, 512 threads, all 24 steps.
// Fully double-buffered (h, x, red) -> ONE barrier per step.
// Thread (ng = tid&31, hg = tid>>5) owns 2 nodes x 4 hidden units.
// MLP head for h_{t-1} fused into step t's gate GEMM; y_{t-2} written at the
// top of step t (hidden under the GEMM).
// ----------------------------------------------------------------------------
// smem float offsets:
//   s_h[2]  2*4096 @ 0        (h buffers, [64 k][64 n])
//   s_x[2]  2*512  @ 8192     (x buffers, [8 k][64 n])
//   s_gi    12288  @ 9216     (6144 u64)
//   s_whh   12288  @ 21504
//   s_wih8  1536   @ 33792
//   s_h1w   4096   @ 35328
//   s_red[2] 2*1024 @ 39424   ([16 hg][64 n])
//   s_bhn   64     @ 41472
//   s_h1b   64     @ 41536
//   s_h2w   64     @ 41600
//   s_h2b   4      @ 41664
constexpr int GRU_SMEM_FLOATS = 41668;
constexpr int GRU_SMEM_BYTES  = GRU_SMEM_FLOATS * 4;   // 166,672 B

__global__ void __launch_bounds__(512, 1)
gru_persistent_kernel(const float* __restrict__ xdyn,   // X_dyn_mean base
                      const float* __restrict__ h1b,
                      const float* __restrict__ h2w,
                      const float* __restrict__ h2b,
                      float* __restrict__ yout) {        // d_out base
    extern __shared__ float sm[];
    float* s_h    = sm;                       // two 4096 buffers
    float* s_x    = sm + 8192;                // two 512 buffers
    u64*   s_gi   = (u64*)(sm + 9216);
    float* s_whh  = sm + 21504;
    float* s_wih8 = sm + 33792;
    float* s_h1w  = sm + 35328;
    float* s_red  = sm + 39424;               // two 1024 buffers
    float* s_bhn  = sm + 41472;
    float* s_h1b  = sm + 41536;
    float* s_h2w  = sm + 41600;
    float* s_h2b  = sm + 41664;

    int tid = threadIdx.x;
    int n0  = blockIdx.x * 64;
    int ng = tid & 31, hg = tid >> 5;    // hg in 0..15
    int nb = ng * 2;                     // 2 nodes per thread

    // ---- prologue: weights & biases ----
    {
        float4* d4; const float4* s4;
        d4 = (float4*)s_whh;  s4 = (const float4*)g_WhhT;
        for (int i = tid; i < 3072; i += 512) d4[i] = s4[i];
        d4 = (float4*)s_wih8; s4 = (const float4*)g_Wih8T;
        if (tid < 384) d4[tid] = s4[tid];
        d4 = (float4*)s_h1w;  s4 = (const float4*)g_h1wT;
        for (int i = tid; i < 1024; i += 512) d4[i] = s4[i];
        if (tid < 64) { s_bhn[tid] = g_bhn[tid]; s_h1b[tid] = h1b[tid]; s_h2w[tid] = h2w[tid]; }
        if (tid == 0) s_h2b[0] = h2b[0];
    }
    // ---- prologue: gi slice for this thread's 2 nodes (resident all steps) ----
#pragma unroll
    for (int i = 0; i < 2; ++i) {
        int gn = min(n0 + nb + i, NN - 1);
        const ulonglong2* g2 = (const ulonglong2*)(g_gi + gn * 192);
        ulonglong2 rv = g2[hg];         // r chunk (j = hg*4..hg*4+3)
        ulonglong2 zv = g2[16 + hg];    // z chunk
        ulonglong2 iv = g2[32 + hg];    // i_n chunk
        s_gi[(i * 6 + 0) * 512 + tid] = rv.x;
        s_gi[(i * 6 + 1) * 512 + tid] = rv.y;
        s_gi[(i * 6 + 2) * 512 + tid] = zv.x;
        s_gi[(i * 6 + 3) * 512 + tid] = zv.y;
        s_gi[(i * 6 + 4) * 512 + tid] = iv.x;
        s_gi[(i * 6 + 5) * 512 + tid] = iv.y;
    }
    // ---- prologue: h[-1] = 0 in buffer 1 (read by t=0); stage x_0 into x[0] ----
    for (int i = tid; i < 4096; i += 512) s_h[4096 + i] = 0.0f;
    if (tid < 64) {
        int gn2 = min(n0 + tid, NN - 1);
        const float4* x4 = (const float4*)(xdyn + (size_t)gn2 * 8);
        float4 a = x4[0], b = x4[1];
        float* dst = s_x + tid;          // x buffer 0
        dst[0] = a.x; dst[64] = a.y; dst[128] = a.z; dst[192] = a.w;
        dst[256] = b.x; dst[320] = b.y; dst[384] = b.z; dst[448] = b.w;
    }
    __syncthreads();

    u64 bn0 = *(const u64*)(s_bhn + (hg << 2));
    u64 bn1 = *(const u64*)(s_bhn + (hg << 2) + 2);
    u64 hb0 = *(const u64*)(s_h1b + (hg << 2));
    u64 hb1 = *(const u64*)(s_h1b + (hg << 2) + 2);
    float w2a = s_h2w[(hg << 2) + 0], w2b = s_h2w[(hg << 2) + 1];
    float w2c = s_h2w[(hg << 2) + 2], w2d = s_h2w[(hg << 2) + 3];

#pragma unroll 1
    for (int t = 0; t < TT; ++t) {
        int pw = (t & 1);                 // this step writes h[pw], red[pw]
        const float* hOld = s_h + ((t + 1) & 1) * 4096;   // h_{t-1}
        float*       hNew = s_h + pw * 4096;              // h_t
        const float* xCur = s_x + pw * 512;               // x_t
        float*       xNxt = s_x + ((t + 1) & 1) * 512;    // x_{t+1} staging
        float*       redW = s_red + pw * 1024;
        const float* redR = s_red + ((t + 1) & 1) * 1024; // head(h_{t-2})

        // ---- prefetch x_{t+1} from GMEM (latency hidden under GEMM) ----
        float4 xpa, xpb;
        if (t < TT - 1 && tid < 64) {
            int gn2 = min(n0 + tid, NN - 1);
            const float4* x4 = (const float4*)(xdyn + ((size_t)(t + 1) * NN + gn2) * 8);
            xpa = x4[0]; xpb = x4[1];
        }
        // ---- write y_{t-2} from the red buffer completed last step ----
        if (t >= 2 && tid < 64) {
            float s = 0.0f;
#pragma unroll
            for (int g = 0; g < 16; ++g) s += redR[g * 64 + tid];
            int gn = n0 + tid;
            if (gn < NN)
                yout[(size_t)(t - 2) * NN + gn] = sigf(s + s_h2b[0]);
        }

        // ---- accumulators from resident gi ----
        u64 ar2[2][2], az2[2][2], ahn2[2][2], ahd2[2][2];
#pragma unroll
        for (int i = 0; i < 2; ++i) {
            ar2[i][0]  = s_gi[(i * 6 + 0) * 512 + tid];
            ar2[i][1]  = s_gi[(i * 6 + 1) * 512 + tid];
            az2[i][0]  = s_gi[(i * 6 + 2) * 512 + tid];
            az2[i][1]  = s_gi[(i * 6 + 3) * 512 + tid];
            ahn2[i][0] = bn0;  ahn2[i][1] = bn1;
            ahd2[i][0] = hb0;  ahd2[i][1] = hb1;
        }

        // ---- K = 64 over h_old: gates r, z, h_n + head H1 ----
#pragma unroll 4
        for (int k = 0; k < 64; ++k) {
            float2 xv = *(const float2*)(hOld + k * 64 + nb);
            const float* wp = s_whh + k * 192 + (hg << 2);
            ulonglong2 wr = *(const ulonglong2*)(wp);
            ulonglong2 wz = *(const ulonglong2*)(wp + 64);
            ulonglong2 wn = *(const ulonglong2*)(wp + 128);
            ulonglong2 wh = *(const ulonglong2*)(s_h1w + k * 64 + (hg << 2));
            u64 xd[2] = {pack2(xv.x, xv.x), pack2(xv.y, xv.y)};
#pragma unroll
            for (int i = 0; i < 2; ++i) {
                ar2[i][0]  = fma2(xd[i], wr.x, ar2[i][0]);
                ar2[i][1]  = fma2(xd[i], wr.y, ar2[i][1]);
                az2[i][0]  = fma2(xd[i], wz.x, az2[i][0]);
                az2[i][1]  = fma2(xd[i], wz.y, az2[i][1]);
                ahn2[i][0] = fma2(xd[i], wn.x, ahn2[i][0]);
                ahn2[i][1] = fma2(xd[i], wn.y, ahn2[i][1]);
                ahd2[i][0] = fma2(xd[i], wh.x, ahd2[i][0]);
                ahd2[i][1] = fma2(xd[i], wh.y, ahd2[i][1]);
            }
        }

        // ---- head partials (h_{t-1}) into red[pw] — retires ahd2 ----
#pragma unroll
        for (int i = 0; i < 2; ++i) {
            float p0, p1, p2, p3;
            unpack2(ahd2[i][0], p0, p1);
            unpack2(ahd2[i][1], p2, p3);
            float part = w2a * fmaxf(p0, 0.0f) + w2b * fmaxf(p1, 0.0f)
                       + w2c * fmaxf(p2, 0.0f) + w2d * fmaxf(p3, 0.0f);
            redW[hg * 64 + nb + i] = part;
        }

        // ---- init i_n accumulators now (liveness) ----
        u64 ain2[2][2];
#pragma unroll
        for (int i = 0; i < 2; ++i) {
            ain2[i][0] = s_gi[(i * 6 + 4) * 512 + tid];
            ain2[i][1] = s_gi[(i * 6 + 5) * 512 + tid];
        }
        // ---- K = 8 over x_dyn: r, z, i_n ----
#pragma unroll
        for (int k = 0; k < 8; ++k) {
            float2 xv = *(const float2*)(xCur + k * 64 + nb);
            const float* wp = s_wih8 + k * 192 + (hg << 2);
            ulonglong2 wr = *(const ulonglong2*)(wp);
            ulonglong2 wz = *(const ulonglong2*)(wp + 64);
            ulonglong2 wi = *(const ulonglong2*)(wp + 128);
            u64 xd[2] = {pack2(xv.x, xv.x), pack2(xv.y, xv.y)};
#pragma unroll
            for (int i = 0; i < 2; ++i) {
                ar2[i][0]  = fma2(xd[i], wr.x, ar2[i][0]);
                ar2[i][1]  = fma2(xd[i], wr.y, ar2[i][1]);
                az2[i][0]  = fma2(xd[i], wz.x, az2[i][0]);
                az2[i][1]  = fma2(xd[i], wz.y, az2[i][1]);
                ain2[i][0] = fma2(xd[i], wi.x, ain2[i][0]);
                ain2[i][1] = fma2(xd[i], wi.y, ain2[i][1]);
            }
        }

        // ---- gates + h update into the OTHER h buffer (no barrier needed) ----
#pragma unroll
        for (int i = 0; i < 2; ++i) {
            int nl = nb + i;
#pragma unroll
            for (int jp = 0; jp < 2; ++jp) {
                float r0, r1, z0, z1, in0, in1, hn0, hn1;
                unpack2(ar2[i][jp],  r0,  r1);
                unpack2(az2[i][jp],  z0,  z1);
                unpack2(ain2[i][jp], in0, in1);
                unpack2(ahn2[i][jp], hn0, hn1);
                float hpa = hOld[(hg * 4 + jp * 2 + 0) * 64 + nl];
                float hpb = hOld[(hg * 4 + jp * 2 + 1) * 64 + nl];
                float ra = sigf_fast(r0), rb = sigf_fast(r1);
                float za = sigf_fast(z0), zb = sigf_fast(z1);
                float na  = tanh_mufu(in0 + ra * hn0);
                float nbv = tanh_mufu(in1 + rb * hn1);
                float ha = na  + za * (hpa - na);
                float hb = nbv + zb * (hpb - nbv);
                hNew[(hg * 4 + jp * 2 + 0) * 64 + nl] = ha;
                hNew[(hg * 4 + jp * 2 + 1) * 64 + nl] = hb;
            }
        }

        // ---- store prefetched x_{t+1} into the other x buffer ----
        if (t < TT - 1 && tid < 64) {
            float* dst = xNxt + tid;
            dst[0] = xpa.x; dst[64] = xpa.y; dst[128] = xpa.z; dst[192] = xpa.w;
            dst[256] = xpb.x; dst[320] = xpb.y; dst[384] = xpb.z; dst[448] = xpb.w;
        }
        __syncthreads();   // single barrier: publishes hNew, xNxt, redW
    }

    // ---- tail 1: y_{TT-2} from red[(TT-1)&1] ----
    if (tid < 64) {
        const float* redR = s_red + ((TT - 1) & 1) * 1024;
        float s = 0.0f;
#pragma unroll
        for (int g = 0; g < 16; ++g) s += redR[g * 64 + tid];
        int gn = n0 + tid;
        if (gn < NN)
            yout[(size_t)(TT - 2) * NN + gn] = sigf(s + s_h2b[0]);
    }

    // ---- tail 2: head for the final h (y_{TT-1}) ----
    {
        const float* hF = s_h + ((TT - 1) & 1) * 4096;   // h_{TT-1}
        float* redW = s_red;                              // reuse buffer 0
        u64 ahd2[2][2];
#pragma unroll
        for (int i = 0; i < 2; ++i) { ahd2[i][0] = hb0; ahd2[i][1] = hb1; }
#pragma unroll 4
        for (int k = 0; k < 64; ++k) {
            float2 xv = *(const float2*)(hF + k * 64 + nb);
            ulonglong2 wh = *(const ulonglong2*)(s_h1w + k * 64 + (hg << 2));
            u64 xd[2] = {pack2(xv.x, xv.x), pack2(xv.y, xv.y)};
#pragma unroll
            for (int i = 0; i < 2; ++i) {
                ahd2[i][0] = fma2(xd[i], wh.x, ahd2[i][0]);
                ahd2[i][1] = fma2(xd[i], wh.y, ahd2[i][1]);
            }
        }
#pragma unroll
        for (int i = 0; i < 2; ++i) {
            float p0, p1, p2, p3;
            unpack2(ahd2[i][0], p0, p1);
            unpack2(ahd2[i][1], p2, p3);
            float part = w2a * fmaxf(p0, 0.0f) + w2b * fmaxf(p1, 0.0f)
                       + w2c * fmaxf(p2, 0.0f) + w2d * fmaxf(p3, 0.0f);
            redW[hg * 64 + nb + i] = part;
        }
        __syncthreads();
        if (tid < 64) {
            float s = 0.0f;
#pragma unroll
            for (int g = 0; g < 16; ++g) s += redW[g * 64 + tid];
            int gn = n0 + tid;
            if (gn < NN)
                yout[(size_t)(TT - 1) * NN + gn] = sigf(s + s_h2b[0]);
        }
    }
}

// ----------------------------------------------------------------------------
// Launch (6 kernels total)
// ----------------------------------------------------------------------------
extern "C" void kernel_launch(void* const* d_in, const int* in_sizes, int n_in,
                              void* d_out, int out_size) {
    const float* X_static = (const float*)d_in[0];
    const float* X_dyn    = (const float*)d_in[1];
    const int*   er       = (const int*)d_in[2];
    const int*   ec       = (const int*)d_in[3];
    const float* ev       = (const float*)d_in[4];
    const float* g1W      = (const float*)d_in[5];
    const float* g1b      = (const float*)d_in[6];
    const float* g2W      = (const float*)d_in[7];
    const float* g2b      = (const float*)d_in[8];
    const float* Wih      = (const float*)d_in[9];
    const float* Whh      = (const float*)d_in[10];
    const float* bih      = (const float*)d_in[11];
    const float* bhh      = (const float*)d_in[12];
    const float* h1W      = (const float*)d_in[13];
    const float* h1b      = (const float*)d_in[14];
    const float* h2W      = (const float*)d_in[15];
    const float* h2b      = (const float*)d_in[16];
    float* out = (float*)d_out;

    cudaFuncSetAttribute(gru_persistent_kernel,
                         cudaFuncAttributeMaxDynamicSharedMemorySize, GRU_SMEM_BYTES);

    // GraphConv layer 1 (lin32 also zeroes g_acc)
    lin32_kernel<<<3125, 256>>>(X_static, g1W, g1b, 0);
    spmm_kernel<<<100000, 256>>>(er, ec, ev);

    // GraphConv layer 2 (relu on read of g_acc, then re-zero)
    lin32_kernel<<<3125, 256>>>(X_static /*unused*/, g2W, g2b, 1);
    spmm_kernel<<<100000, 256>>>(er, ec, ev);

    // Time-invariant gate projections + weight prep (fused)
    gi_prep_kernel<<<3125, 256>>>(Wih, bih, bhh, Whh, h1W);

    // Persistent GRU: 64-node tiles, all 24 steps, 1 barrier/step
    gru_persistent_kernel<<<1563, 512, GRU_SMEM_BYTES>>>(X_dyn, h1b, h2W, h2b, out);
}

// round 9
// speedup vs baseline: 1.1850x; 1.0587x over previous
#include <cuda_runtime.h>
#include <cuda_bf16.h>
#include <math.h>

#define DINLINE __device__ __forceinline__

constexpr int NN = 100000;
constexpr int TT = 24;

// ---------------- scratch globals ----------------
__device__ __align__(16) float g_xw[NN * 32];
__device__ __align__(16) float g_acc[NN * 32];
__device__ __align__(16) float g_gi[NN * 192];          // [n][r(64)|z(64)|in(64)] (+biases)
__device__ __align__(16) __nv_bfloat16 g_B[256 * 152];  // MMA B [n=4j+c][k], k: Whi(64)|Wlo(64)|x(8)|pad
__device__ __align__(16) float g_Wn[64 * 8];            // W_ih n-rows, x cols (fp32, SIMT i_n)
__device__ __align__(16) float g_bhn[64];

DINLINE float sigf(float x)  { return __fdividef(1.0f, 1.0f + __expf(-x)); }
DINLINE float tanh_mufu(float x) { float y; asm("tanh.approx.f32 %0, %1;" : "=f"(y) : "f"(x)); return y; }
DINLINE float sigf_fast(float x) { return fmaf(0.5f, tanh_mufu(0.5f * x), 0.5f); }
DINLINE unsigned s2u(const void* p) {
    unsigned a; asm("{ .reg .u64 t; cvta.to.shared.u64 t, %1; cvt.u32.u64 %0, t; }" : "=r"(a) : "l"(p)); return a;
}
#define LDSM4(r0,r1,r2,r3,addr) \
    asm volatile("ldmatrix.sync.aligned.m8n8.x4.shared.b16 {%0,%1,%2,%3}, [%4];" \
        : "=r"(r0),"=r"(r1),"=r"(r2),"=r"(r3) : "r"(addr))
#define MMA16816(d,a0,a1,a2,a3,b0,b1) \
    asm volatile("mma.sync.aligned.m16n8k16.row.col.f32.bf16.bf16.f32 " \
        "{%0,%1,%2,%3},{%4,%5,%6,%7},{%8,%9},{%0,%1,%2,%3};" \
        : "+f"(d[0]),"+f"(d[1]),"+f"(d[2]),"+f"(d[3]) \
        : "r"(a0),"r"(a1),"r"(a2),"r"(a3),"r"(b0),"r"(b1))

// ---------------- graph conv (unchanged pipeline) ----------------
__global__ void lin32_kernel(const float* __restrict__ Xext, const float* __restrict__ W,
                             const float* __restrict__ bias, int relu_acc_src) {
    __shared__ float Wt[1024];
    __shared__ float Xs[32 * 33];
    int tid = threadIdx.x, n0 = blockIdx.x * 32;
    for (int e = tid; e < 1024; e += 256) { int j = e >> 5, k = e & 31; Wt[k * 32 + j] = W[j * 32 + k]; }
    for (int e = tid; e < 1024; e += 256) {
        int n = e >> 5, k = e & 31;
        float v = relu_acc_src ? fmaxf(g_acc[(n0 + n) * 32 + k], 0.0f) : Xext[(n0 + n) * 32 + k];
        Xs[n * 33 + k] = v;
    }
    __syncthreads();
    for (int e = tid; e < 1024; e += 256) g_acc[n0 * 32 + e] = 0.0f;
    int j = tid & 31; float b = bias[j];
#pragma unroll
    for (int g = 0; g < 4; ++g) {
        int n = (tid >> 5) + g * 8; float acc = b;
#pragma unroll
        for (int k = 0; k < 32; ++k) acc = fmaf(Xs[n * 33 + k], Wt[k * 32 + j], acc);
        g_xw[(n0 + n) * 32 + j] = acc;
    }
}

__global__ void spmm_kernel(const int* __restrict__ er, const int* __restrict__ ec,
                            const float* __restrict__ ev) {
    int idx = blockIdx.x * 256 + threadIdx.x;
    int e = idx >> 3, q = idx & 7;
    int r = __ldg(er + e), c = __ldg(ec + e);
    float v = __ldg(ev + e);
    float4 x = *(const float4*)(g_xw + c * 32 + q * 4);
    float* dst = g_acc + r * 32 + q * 4;
    asm volatile("red.global.add.v4.f32 [%0], {%1, %2, %3, %4};"
                 :: "l"(dst), "f"(v * x.x), "f"(v * x.y), "f"(v * x.z), "f"(v * x.w) : "memory");
}

__global__ void gi_prep_kernel(const float* __restrict__ Wih, const float* __restrict__ bih,
                               const float* __restrict__ bhh) {
    __shared__ float Ws[32 * 192];
    __shared__ float Hs[32 * 33];
    int tid = threadIdx.x, n0 = blockIdx.x * 32;
    for (int e = tid; e < 6144; e += 256) { int k = e / 192, j = e - k * 192; Ws[e] = Wih[j * 40 + k]; }
    for (int e = tid; e < 1024; e += 256) {
        int n = e >> 5, k = e & 31;
        Hs[n * 33 + k] = fmaxf(g_acc[(n0 + n) * 32 + k], 0.0f);
    }
    __syncthreads();
#pragma unroll 1
    for (int it = 0; it < 24; ++it) {
        int p = it * 256 + tid;
        int n = p / 192, j = p - n * 192;
        float acc = bih[j] + (j < 128 ? bhh[j] : 0.0f);
#pragma unroll
        for (int k = 0; k < 32; ++k) acc = fmaf(Hs[n * 33 + k], Ws[k * 192 + j], acc);
        g_gi[(n0 + n) * 192 + j] = acc;
    }
}

// Pack MMA B matrix (bf16, split hi/lo) + Wn + bhn. grid 155 x 256.
__global__ void prep_kernel(const float* __restrict__ Whh, const float* __restrict__ Wih,
                            const float* __restrict__ h1W, const float* __restrict__ bhh) {
    int id = blockIdx.x * 256 + threadIdx.x;
    if (id < 256 * 152) {
        int n = id / 152, k = id - n * 152;
        int j = n >> 2, c = n & 3;
        float w = 0.0f;
        if (k < 128) {
            int kk = k & 63; bool lo = k >= 64;
            float full;
            if (c == 0)      full = Whh[j * 64 + kk];
            else if (c == 1) full = Whh[(64 + j) * 64 + kk];
            else if (c == 2) full = Whh[(128 + j) * 64 + kk];
            else             full = h1W[j * 64 + kk];
            float hi = __bfloat162float(__float2bfloat16(full));
            w = lo ? (full - hi) : full;
        } else if (k < 136 && c < 2) {
            int kk = k - 128;
            w = Wih[(c == 0 ? j : 64 + j) * 40 + 32 + kk];
        }
        g_B[id] = __float2bfloat16(w);
    } else if (id < 256 * 152 + 512) {
        int q = id - 256 * 152;
        g_Wn[q] = Wih[(128 + (q >> 3)) * 40 + 32 + (q & 7)];
    } else if (id < 256 * 152 + 512 + 64) {
        g_bhn[id - (256 * 152 + 512)] = bhh[128 + id - (256 * 152 + 512)];
    }
}

// ---------------- persistent tensor-core GRU ----------------
// smem float offsets
constexpr int OF_A    = 0;        // 128 x 152 bf16 (h_hi|h_lo|x|pad) = 9728 floats
constexpr int OF_B    = 9728;     // 256 x 152 bf16 = 19456 floats
constexpr int OF_GIRZ = 29184;    // [m][j] float2 = 16384 floats
constexpr int OF_GIN  = 45568;    // [m][j] = 8192
constexpr int OF_XF   = 53760;    // [m][8] fp32 = 1024
constexpr int OF_WN   = 54784;    // [j][8] fp32 = 512
constexpr int OF_RED  = 55296;    // [2][128] = 256
constexpr int OF_BHN  = 55552;
constexpr int OF_H1B  = 55616;
constexpr int OF_H2W  = 55680;
constexpr int OF_H2B  = 55744;
constexpr int GRU_SMEM_FLOATS = 55748;
constexpr int GRU_SMEM_BYTES  = GRU_SMEM_FLOATS * 4;   // 222,992 B
constexpr int SAB = 304;   // row stride bytes (152 bf16)

__global__ void __launch_bounds__(512, 1)
gru_mma_kernel(const float* __restrict__ xdyn, const float* __restrict__ h1b,
               const float* __restrict__ h2w, const float* __restrict__ h2b,
               float* __restrict__ yout) {
    extern __shared__ float sm[];
    float2* s_girz = (float2*)(sm + OF_GIRZ);
    float*  s_gin  = sm + OF_GIN;
    float*  s_xf   = sm + OF_XF;
    float*  s_wn   = sm + OF_WN;
    float*  s_red  = sm + OF_RED;
    float*  s_bhn  = sm + OF_BHN;
    float*  s_h1b  = sm + OF_H1B;
    float*  s_h2w  = sm + OF_H2W;
    __nv_bfloat16* abf = (__nv_bfloat16*)(sm + OF_A);

    int tid = threadIdx.x;
    int n0  = blockIdx.x * 128;
    int L = tid & 31, wid = tid >> 5;
    int mg = wid >> 1, nh = wid & 1;
    int q = L & 3, rgrp = L >> 2;
    int m0 = mg * 16 + rgrp;

    // ---- prologue phase 1: zero A, copy B/gi/wn/biases ----
    for (int i = tid; i < 9728; i += 512) sm[OF_A + i] = 0.0f;
    {
        float4* d4 = (float4*)(sm + OF_B);
        const float4* s4 = (const float4*)g_B;
        for (int i = tid; i < 4864; i += 512) d4[i] = s4[i];
    }
    for (int idx = tid; idx < 8192; idx += 512) {
        int m = idx >> 6, j = idx & 63;
        int gm = min(n0 + m, NN - 1);
        const float* gp = g_gi + (size_t)gm * 192;
        s_girz[idx] = make_float2(gp[j], gp[64 + j]);
        s_gin[idx]  = gp[128 + j];
    }
    if (tid < 512) { if (tid < 512) s_wn[tid & 511] = g_Wn[tid & 511]; }
    if (tid < 64) { s_bhn[tid] = g_bhn[tid]; s_h1b[tid] = h1b[tid]; s_h2w[tid] = h2w[tid]; }
    if (tid == 0) sm[OF_H2B] = h2b[0];
    __syncthreads();
    // ---- prologue phase 2: x_0 ----
    if (tid < 128) {
        int gn = min(n0 + tid, NN - 1);
        const float4* x4 = (const float4*)(xdyn + (size_t)gn * 8);
        float4 a = x4[0], b = x4[1];
        float xv[8] = {a.x, a.y, a.z, a.w, b.x, b.y, b.z, b.w};
        __nv_bfloat16* ax = abf + tid * 152 + 128;
#pragma unroll
        for (int kk = 0; kk < 8; ++kk) { ax[kk] = __float2bfloat16(xv[kk]); s_xf[tid * 8 + kk] = xv[kk]; }
    }
    __syncthreads();

    unsigned smA = s2u(sm);
    unsigned smB = smA + 38912;
    unsigned aLane = smA + (unsigned)((mg * 16 + (L & 15)) * SAB) + ((L & 16) ? 16u : 0u);
    unsigned bLane = smB + (unsigned)((nh * 128 + (L & 7) + ((L & 16) >> 1)) * SAB) + ((L & 8) ? 16u : 0u);

    float h2b0 = sm[OF_H2B];

#pragma unroll 1
    for (int t = 0; t <= TT; ++t) {
        // prefetch x_{t+1}
        float4 xpa, xpb;
        if (t < TT - 1 && tid < 128) {
            int gn = min(n0 + tid, NN - 1);
            const float4* x4 = (const float4*)(xdyn + ((size_t)(t + 1) * NN + gn) * 8);
            xpa = x4[0]; xpb = x4[1];
        }

        // ---- GEMM: 13 k16 chunks ----
        float acc[16][4];
#pragma unroll
        for (int i = 0; i < 16; ++i) { acc[i][0] = acc[i][1] = acc[i][2] = acc[i][3] = 0.0f; }
        const int ACK[13] = {0,1,2,3,4,5,6,7,0,1,2,3,8};
        const int BCK[13] = {0,1,2,3,0,1,2,3,4,5,6,7,8};
#pragma unroll
        for (int c = 0; c < 13; ++c) {
            unsigned a0, a1, a2, a3;
            LDSM4(a0, a1, a2, a3, aLane + ACK[c] * 32);
            unsigned bb = bLane + BCK[c] * 32;
#pragma unroll
            for (int tp = 0; tp < 8; ++tp) {
                unsigned b0, b1, b2, b3;
                LDSM4(b0, b1, b2, b3, bb + tp * (16 * SAB));
                MMA16816(acc[tp * 2],     a0, a1, a2, a3, b0, b1);
                MMA16816(acc[tp * 2 + 1], a0, a1, a2, a3, b2, b3);
            }
        }

        // ---- epilogue ----
        float xf0[8], xf1[8];
#pragma unroll
        for (int k4 = 0; k4 < 2; ++k4) {
            float4 v0 = *(const float4*)(s_xf + m0 * 8 + k4 * 4);
            float4 v1 = *(const float4*)(s_xf + (m0 + 8) * 8 + k4 * 4);
            xf0[k4*4+0]=v0.x; xf0[k4*4+1]=v0.y; xf0[k4*4+2]=v0.z; xf0[k4*4+3]=v0.w;
            xf1[k4*4+0]=v1.x; xf1[k4*4+1]=v1.y; xf1[k4*4+2]=v1.z; xf1[k4*4+3]=v1.w;
        }
        float hp0 = 0.0f, hp1 = 0.0f;
#pragma unroll
        for (int tle = 0; tle < 16; ++tle) {
            int j = nh * 32 + tle * 2 + (q >> 1);
            float hnA = __shfl_xor_sync(0xffffffffu, acc[tle][0], 1);
            float hnB = __shfl_xor_sync(0xffffffffu, acc[tle][2], 1);
            if ((q & 1) == 0) {
                if (t < TT) {
                    float2 g0 = s_girz[m0 * 64 + j];
                    float2 g1 = s_girz[(m0 + 8) * 64 + j];
                    float ain0 = s_gin[m0 * 64 + j];
                    float ain1 = s_gin[(m0 + 8) * 64 + j];
                    float4 wa = *(const float4*)(s_wn + j * 8);
                    float4 wb = *(const float4*)(s_wn + j * 8 + 4);
                    ain0 += xf0[0]*wa.x + xf0[1]*wa.y + xf0[2]*wa.z + xf0[3]*wa.w
                          + xf0[4]*wb.x + xf0[5]*wb.y + xf0[6]*wb.z + xf0[7]*wb.w;
                    ain1 += xf1[0]*wa.x + xf1[1]*wa.y + xf1[2]*wa.z + xf1[3]*wa.w
                          + xf1[4]*wb.x + xf1[5]*wb.y + xf1[6]*wb.z + xf1[7]*wb.w;
                    float bh = s_bhn[j];
                    float r0 = sigf_fast(acc[tle][0] + g0.x);
                    float z0 = sigf_fast(acc[tle][1] + g0.y);
                    float nn0 = tanh_mufu(ain0 + r0 * (hnA + bh));
                    float r1 = sigf_fast(acc[tle][2] + g1.x);
                    float z1 = sigf_fast(acc[tle][3] + g1.y);
                    float nn1 = tanh_mufu(ain1 + r1 * (hnB + bh));
                    float ho0 = __bfloat162float(abf[m0 * 152 + j]) + __bfloat162float(abf[m0 * 152 + 64 + j]);
                    float ho1 = __bfloat162float(abf[(m0 + 8) * 152 + j]) + __bfloat162float(abf[(m0 + 8) * 152 + 64 + j]);
                    acc[tle][0] = nn0 + z0 * (ho0 - nn0);   // stash h_new rows
                    acc[tle][2] = nn1 + z1 * (ho1 - nn1);
                }
            } else {
                float w2j = s_h2w[j], b1j = s_h1b[j];
                hp0 = fmaf(w2j, fmaxf(acc[tle][1] + b1j, 0.0f), hp0);
                hp1 = fmaf(w2j, fmaxf(acc[tle][3] + b1j, 0.0f), hp1);
            }
        }
        hp0 += __shfl_xor_sync(0xffffffffu, hp0, 2);
        hp1 += __shfl_xor_sync(0xffffffffu, hp1, 2);
        if (q == 1) { s_red[nh * 128 + m0] = hp0; s_red[nh * 128 + m0 + 8] = hp1; }
        __syncthreads();   // bar1: MMA reads done, s_red ready

        if (t >= 1 && tid < 128) {
            int gn = n0 + tid;
            if (gn < NN)
                yout[(size_t)(t - 1) * NN + gn] = sigf(s_red[tid] + s_red[128 + tid] + h2b0);
        }
        if (t < TT) {
            if ((q & 1) == 0) {
#pragma unroll
                for (int tle = 0; tle < 16; ++tle) {
                    int j = nh * 32 + tle * 2 + (q >> 1);
                    float h0v = acc[tle][0], h1v = acc[tle][2];
                    __nv_bfloat16 hi0 = __float2bfloat16(h0v);
                    abf[m0 * 152 + j] = hi0;
                    abf[m0 * 152 + 64 + j] = __float2bfloat16(h0v - __bfloat162float(hi0));
                    __nv_bfloat16 hi1 = __float2bfloat16(h1v);
                    abf[(m0 + 8) * 152 + j] = hi1;
                    abf[(m0 + 8) * 152 + 64 + j] = __float2bfloat16(h1v - __bfloat162float(hi1));
                }
            }
            if (t < TT - 1 && tid < 128) {
                float xv[8] = {xpa.x, xpa.y, xpa.z, xpa.w, xpb.x, xpb.y, xpb.z, xpb.w};
                __nv_bfloat16* ax = abf + tid * 152 + 128;
#pragma unroll
                for (int kk = 0; kk < 8; ++kk) { ax[kk] = __float2bfloat16(xv[kk]); s_xf[tid * 8 + kk] = xv[kk]; }
            }
        }
        __syncthreads();   // bar2: A ready for next step
    }
}

// ---------------- launch ----------------
extern "C" void kernel_launch(void* const* d_in, const int* in_sizes, int n_in,
                              void* d_out, int out_size) {
    const float* X_static = (const float*)d_in[0];
    const float* X_dyn    = (const float*)d_in[1];
    const int*   er       = (const int*)d_in[2];
    const int*   ec       = (const int*)d_in[3];
    const float* ev       = (const float*)d_in[4];
    const float* g1W      = (const float*)d_in[5];
    const float* g1b      = (const float*)d_in[6];
    const float* g2W      = (const float*)d_in[7];
    const float* g2b      = (const float*)d_in[8];
    const float* Wih      = (const float*)d_in[9];
    const float* Whh      = (const float*)d_in[10];
    const float* bih      = (const float*)d_in[11];
    const float* bhh      = (const float*)d_in[12];
    const float* h1W      = (const float*)d_in[13];
    const float* h1b      = (const float*)d_in[14];
    const float* h2W      = (const float*)d_in[15];
    const float* h2b      = (const float*)d_in[16];
    float* out = (float*)d_out;

    cudaFuncSetAttribute(gru_mma_kernel,
                         cudaFuncAttributeMaxDynamicSharedMemorySize, GRU_SMEM_BYTES);

    lin32_kernel<<<3125, 256>>>(X_static, g1W, g1b, 0);
    spmm_kernel<<<100000, 256>>>(er, ec, ev);
    lin32_kernel<<<3125, 256>>>(X_static, g2W, g2b, 1);
    spmm_kernel<<<100000, 256>>>(er, ec, ev);

    prep_kernel<<<155, 256>>>(Whh, Wih, h1W, bhh);
    gi_prep_kernel<<<3125, 256>>>(Wih, bih, bhh);

    gru_mma_kernel<<<782, 512, GRU_SMEM_BYTES>>>(X_dyn, h1b, h2W, h2b, out);
}

// round 11
// speedup vs baseline: 1.4325x; 1.2089x over previous
#include <cuda_runtime.h>
#include <cuda_bf16.h>
#include <math.h>

#define DINLINE __device__ __forceinline__

constexpr int NN = 100000;
constexpr int TT = 24;

// ---------------- scratch globals ----------------
__device__ __align__(16) float g_xw[NN * 32];
__device__ __align__(16) float g_acc[NN * 32];
__device__ __align__(16) float g_gi[NN * 192];          // [n][r(64)|z(64)|in(64)] (+biases)
__device__ __align__(16) __nv_bfloat16 g_B[256 * 152];  // MMA B [n=4j+c][k], k: Whi(64)|Wlo(64)|x(8)|pad
__device__ __align__(16) float g_Wn[64 * 8];            // W_ih n-rows, x cols (fp32, SIMT i_n)
__device__ __align__(16) float g_bhn[64];

DINLINE float sigf(float x)  { return __fdividef(1.0f, 1.0f + __expf(-x)); }
DINLINE float tanh_mufu(float x) { float y; asm("tanh.approx.f32 %0, %1;" : "=f"(y) : "f"(x)); return y; }
DINLINE float sigf_fast(float x) { return fmaf(0.5f, tanh_mufu(0.5f * x), 0.5f); }
DINLINE unsigned s2u(const void* p) {
    unsigned a; asm("{ .reg .u64 t; cvta.to.shared.u64 t, %1; cvt.u32.u64 %0, t; }" : "=r"(a) : "l"(p)); return a;
}
#define LDSM4(r0,r1,r2,r3,addr) \
    asm volatile("ldmatrix.sync.aligned.m8n8.x4.shared.b16 {%0,%1,%2,%3}, [%4];" \
        : "=r"(r0),"=r"(r1),"=r"(r2),"=r"(r3) : "r"(addr))
#define MMA16816(d,a0,a1,a2,a3,b0,b1) \
    asm volatile("mma.sync.aligned.m16n8k16.row.col.f32.bf16.bf16.f32 " \
        "{%0,%1,%2,%3},{%4,%5,%6,%7},{%8,%9},{%0,%1,%2,%3};" \
        : "+f"(d[0]),"+f"(d[1]),"+f"(d[2]),"+f"(d[3]) \
        : "r"(a0),"r"(a1),"r"(a2),"r"(a3),"r"(b0),"r"(b1))

// ---------------- graph conv (unchanged pipeline) ----------------
__global__ void lin32_kernel(const float* __restrict__ Xext, const float* __restrict__ W,
                             const float* __restrict__ bias, int relu_acc_src) {
    __shared__ float Wt[1024];
    __shared__ float Xs[32 * 33];
    int tid = threadIdx.x, n0 = blockIdx.x * 32;
    for (int e = tid; e < 1024; e += 256) { int j = e >> 5, k = e & 31; Wt[k * 32 + j] = W[j * 32 + k]; }
    for (int e = tid; e < 1024; e += 256) {
        int n = e >> 5, k = e & 31;
        float v = relu_acc_src ? fmaxf(g_acc[(n0 + n) * 32 + k], 0.0f) : Xext[(n0 + n) * 32 + k];
        Xs[n * 33 + k] = v;
    }
    __syncthreads();
    for (int e = tid; e < 1024; e += 256) g_acc[n0 * 32 + e] = 0.0f;
    int j = tid & 31; float b = bias[j];
#pragma unroll
    for (int g = 0; g < 4; ++g) {
        int n = (tid >> 5) + g * 8; float acc = b;
#pragma unroll
        for (int k = 0; k < 32; ++k) acc = fmaf(Xs[n * 33 + k], Wt[k * 32 + j], acc);
        g_xw[(n0 + n) * 32 + j] = acc;
    }
}

__global__ void spmm_kernel(const int* __restrict__ er, const int* __restrict__ ec,
                            const float* __restrict__ ev) {
    int idx = blockIdx.x * 256 + threadIdx.x;
    int e = idx >> 3, q = idx & 7;
    int r = __ldg(er + e), c = __ldg(ec + e);
    float v = __ldg(ev + e);
    float4 x = *(const float4*)(g_xw + c * 32 + q * 4);
    float* dst = g_acc + r * 32 + q * 4;
    asm volatile("red.global.add.v4.f32 [%0], {%1, %2, %3, %4};"
                 :: "l"(dst), "f"(v * x.x), "f"(v * x.y), "f"(v * x.z), "f"(v * x.w) : "memory");
}

__global__ void gi_prep_kernel(const float* __restrict__ Wih, const float* __restrict__ bih,
                               const float* __restrict__ bhh) {
    __shared__ float Ws[32 * 192];
    __shared__ float Hs[32 * 33];
    int tid = threadIdx.x, n0 = blockIdx.x * 32;
    for (int e = tid; e < 6144; e += 256) { int k = e / 192, j = e - k * 192; Ws[e] = Wih[j * 40 + k]; }
    for (int e = tid; e < 1024; e += 256) {
        int n = e >> 5, k = e & 31;
        Hs[n * 33 + k] = fmaxf(g_acc[(n0 + n) * 32 + k], 0.0f);
    }
    __syncthreads();
#pragma unroll 1
    for (int it = 0; it < 24; ++it) {
        int p = it * 256 + tid;
        int n = p / 192, j = p - n * 192;
        float acc = bih[j] + (j < 128 ? bhh[j] : 0.0f);
#pragma unroll
        for (int k = 0; k < 32; ++k) acc = fmaf(Hs[n * 33 + k], Ws[k * 192 + j], acc);
        g_gi[(n0 + n) * 192 + j] = acc;
    }
}

// Pack MMA B matrix (bf16, split hi/lo) + Wn + bhn. grid 155 x 256.
__global__ void prep_kernel(const float* __restrict__ Whh, const float* __restrict__ Wih,
                            const float* __restrict__ h1W, const float* __restrict__ bhh) {
    int id = blockIdx.x * 256 + threadIdx.x;
    if (id < 256 * 152) {
        int n = id / 152, k = id - n * 152;
        int j = n >> 2, c = n & 3;
        float w = 0.0f;
        if (k < 128) {
            int kk = k & 63; bool lo = k >= 64;
            float full;
            if (c == 0)      full = Whh[j * 64 + kk];
            else if (c == 1) full = Whh[(64 + j) * 64 + kk];
            else if (c == 2) full = Whh[(128 + j) * 64 + kk];
            else             full = h1W[j * 64 + kk];
            float hi = __bfloat162float(__float2bfloat16(full));
            w = lo ? (full - hi) : full;
        } else if (k < 136 && c < 2) {
            int kk = k - 128;
            w = Wih[(c == 0 ? j : 64 + j) * 40 + 32 + kk];
        }
        g_B[id] = __float2bfloat16(w);
    } else if (id < 256 * 152 + 512) {
        int q = id - 256 * 152;
        g_Wn[q] = Wih[(128 + (q >> 3)) * 40 + 32 + (q & 7)];
    } else if (id < 256 * 152 + 512 + 64) {
        g_bhn[id - (256 * 152 + 512)] = bhh[128 + id - (256 * 152 + 512)];
    }
}

// ---------------- persistent tensor-core GRU (2-term split, shared-B MMA) ----------------
constexpr int OF_A    = 0;        // 128 x 152 bf16 (h_hi|h_lo|x|pad) = 9728 floats
constexpr int OF_B    = 9728;     // 256 x 152 bf16 = 19456 floats
constexpr int OF_GIRZ = 29184;    // [m][j] float2 = 16384 floats
constexpr int OF_GIN  = 45568;    // [m][j] = 8192
constexpr int OF_XF   = 53760;    // [m][8] fp32 = 1024
constexpr int OF_WN   = 54784;    // [j][8] fp32 = 512
constexpr int OF_RED  = 55296;    // [2][128] = 256
constexpr int OF_BHN  = 55552;
constexpr int OF_H1B  = 55616;
constexpr int OF_H2W  = 55680;
constexpr int OF_H2B  = 55744;
constexpr int GRU_SMEM_FLOATS = 55748;
constexpr int GRU_SMEM_BYTES  = GRU_SMEM_FLOATS * 4;   // 222,992 B
constexpr int SAB = 304;   // row stride bytes (152 bf16)

__global__ void __launch_bounds__(512, 1)
gru_mma_kernel(const float* __restrict__ xdyn, const float* __restrict__ h1b,
               const float* __restrict__ h2w, const float* __restrict__ h2b,
               float* __restrict__ yout) {
    extern __shared__ float sm[];
    float2* s_girz = (float2*)(sm + OF_GIRZ);
    float*  s_gin  = sm + OF_GIN;
    float*  s_xf   = sm + OF_XF;
    float*  s_wn   = sm + OF_WN;
    float*  s_red  = sm + OF_RED;
    float*  s_bhn  = sm + OF_BHN;
    float*  s_h1b  = sm + OF_H1B;
    float*  s_h2w  = sm + OF_H2W;
    __nv_bfloat16* abf = (__nv_bfloat16*)(sm + OF_A);

    int tid = threadIdx.x;
    int n0  = blockIdx.x * 128;
    int L = tid & 31, wid = tid >> 5;
    int mg = wid >> 1, nh = wid & 1;
    int q = L & 3, rgrp = L >> 2;
    int m0 = mg * 16 + rgrp;

    // ---- prologue phase 1: zero A, copy B/gi/wn/biases ----
    for (int i = tid; i < 9728; i += 512) sm[OF_A + i] = 0.0f;
    {
        float4* d4 = (float4*)(sm + OF_B);
        const float4* s4 = (const float4*)g_B;
        for (int i = tid; i < 4864; i += 512) d4[i] = s4[i];
    }
    for (int idx = tid; idx < 8192; idx += 512) {
        int m = idx >> 6, j = idx & 63;
        int gm = min(n0 + m, NN - 1);
        const float* gp = g_gi + (size_t)gm * 192;
        s_girz[idx] = make_float2(gp[j], gp[64 + j]);
        s_gin[idx]  = gp[128 + j];
    }
    if (tid < 512) s_wn[tid] = g_Wn[tid];
    if (tid < 64) { s_bhn[tid] = g_bhn[tid]; s_h1b[tid] = h1b[tid]; s_h2w[tid] = h2w[tid]; }
    if (tid == 0) sm[OF_H2B] = h2b[0];
    __syncthreads();
    // ---- prologue phase 2: x_0 ----
    if (tid < 128) {
        int gn = min(n0 + tid, NN - 1);
        const float4* x4 = (const float4*)(xdyn + (size_t)gn * 8);
        float4 a = x4[0], b = x4[1];
        float xv[8] = {a.x, a.y, a.z, a.w, b.x, b.y, b.z, b.w};
        __nv_bfloat16* ax = abf + tid * 152 + 128;
#pragma unroll
        for (int kk = 0; kk < 8; ++kk) { ax[kk] = __float2bfloat16(xv[kk]); s_xf[tid * 8 + kk] = xv[kk]; }
    }
    __syncthreads();

    unsigned smA = s2u(sm);
    unsigned smB = smA + 38912;
    unsigned aLane = smA + (unsigned)((mg * 16 + (L & 15)) * SAB) + ((L & 16) ? 16u : 0u);
    unsigned bLane = smB + (unsigned)((nh * 128 + (L & 7) + ((L & 16) >> 1)) * SAB) + ((L & 8) ? 16u : 0u);

    float h2b0 = sm[OF_H2B];

#pragma unroll 1
    for (int t = 0; t <= TT; ++t) {
        // prefetch x_{t+1}
        float4 xpa, xpb;
        if (t < TT - 1 && tid < 128) {
            int gn = min(n0 + tid, NN - 1);
            const float4* x4 = (const float4*)(xdyn + ((size_t)(t + 1) * NN + gn) * 8);
            xpa = x4[0]; xpb = x4[1];
        }

        // ---- GEMM: 4 shared-B k16 chunks (h_hi + h_lo vs same W_hi) + 1 x chunk ----
        float acc[16][4];
#pragma unroll
        for (int i = 0; i < 16; ++i) { acc[i][0] = acc[i][1] = acc[i][2] = acc[i][3] = 0.0f; }
#pragma unroll
        for (int c = 0; c < 4; ++c) {
            unsigned a0, a1, a2, a3;      // h_hi chunk c  (k 16c..16c+15)
            unsigned e0, e1, e2, e3;      // h_lo chunk c  (k 64+16c..)
            LDSM4(a0, a1, a2, a3, aLane + c * 32);
            LDSM4(e0, e1, e2, e3, aLane + (4 + c) * 32);
            unsigned bb = bLane + c * 32;
#pragma unroll
            for (int tp = 0; tp < 8; ++tp) {
                unsigned b0, b1, b2, b3;
                LDSM4(b0, b1, b2, b3, bb + tp * (16 * SAB));
                MMA16816(acc[tp * 2],     a0, a1, a2, a3, b0, b1);
                MMA16816(acc[tp * 2 + 1], a0, a1, a2, a3, b2, b3);
                MMA16816(acc[tp * 2],     e0, e1, e2, e3, b0, b1);
                MMA16816(acc[tp * 2 + 1], e0, e1, e2, e3, b2, b3);
            }
        }
        {   // x chunk: A k 128..143 vs B k 128..143
            unsigned a0, a1, a2, a3;
            LDSM4(a0, a1, a2, a3, aLane + 8 * 32);
            unsigned bb = bLane + 8 * 32;
#pragma unroll
            for (int tp = 0; tp < 8; ++tp) {
                unsigned b0, b1, b2, b3;
                LDSM4(b0, b1, b2, b3, bb + tp * (16 * SAB));
                MMA16816(acc[tp * 2],     a0, a1, a2, a3, b0, b1);
                MMA16816(acc[tp * 2 + 1], a0, a1, a2, a3, b2, b3);
            }
        }

        // ---- epilogue ----
        float xf0[8], xf1[8];
#pragma unroll
        for (int k4 = 0; k4 < 2; ++k4) {
            float4 v0 = *(const float4*)(s_xf + m0 * 8 + k4 * 4);
            float4 v1 = *(const float4*)(s_xf + (m0 + 8) * 8 + k4 * 4);
            xf0[k4*4+0]=v0.x; xf0[k4*4+1]=v0.y; xf0[k4*4+2]=v0.z; xf0[k4*4+3]=v0.w;
            xf1[k4*4+0]=v1.x; xf1[k4*4+1]=v1.y; xf1[k4*4+2]=v1.z; xf1[k4*4+3]=v1.w;
        }
        float hp0 = 0.0f, hp1 = 0.0f;
#pragma unroll
        for (int tle = 0; tle < 16; ++tle) {
            int j = nh * 32 + tle * 2 + (q >> 1);
            float hnA = __shfl_xor_sync(0xffffffffu, acc[tle][0], 1);
            float hnB = __shfl_xor_sync(0xffffffffu, acc[tle][2], 1);
            if ((q & 1) == 0) {
                if (t < TT) {
                    float2 g0 = s_girz[m0 * 64 + j];
                    float2 g1 = s_girz[(m0 + 8) * 64 + j];
                    float ain0 = s_gin[m0 * 64 + j];
                    float ain1 = s_gin[(m0 + 8) * 64 + j];
                    float4 wa = *(const float4*)(s_wn + j * 8);
                    float4 wb = *(const float4*)(s_wn + j * 8 + 4);
                    ain0 += xf0[0]*wa.x + xf0[1]*wa.y + xf0[2]*wa.z + xf0[3]*wa.w
                          + xf0[4]*wb.x + xf0[5]*wb.y + xf0[6]*wb.z + xf0[7]*wb.w;
                    ain1 += xf1[0]*wa.x + xf1[1]*wa.y + xf1[2]*wa.z + xf1[3]*wa.w
                          + xf1[4]*wb.x + xf1[5]*wb.y + xf1[6]*wb.z + xf1[7]*wb.w;
                    float bh = s_bhn[j];
                    float r0 = sigf_fast(acc[tle][0] + g0.x);
                    float z0 = sigf_fast(acc[tle][1] + g0.y);
                    float nn0 = tanh_mufu(ain0 + r0 * (hnA + bh));
                    float r1 = sigf_fast(acc[tle][2] + g1.x);
                    float z1 = sigf_fast(acc[tle][3] + g1.y);
                    float nn1 = tanh_mufu(ain1 + r1 * (hnB + bh));
                    float ho0 = __bfloat162float(abf[m0 * 152 + j]) + __bfloat162float(abf[m0 * 152 + 64 + j]);
                    float ho1 = __bfloat162float(abf[(m0 + 8) * 152 + j]) + __bfloat162float(abf[(m0 + 8) * 152 + 64 + j]);
                    acc[tle][0] = nn0 + z0 * (ho0 - nn0);   // stash h_new rows
                    acc[tle][2] = nn1 + z1 * (ho1 - nn1);
                }
            } else {
                float w2j = s_h2w[j], b1j = s_h1b[j];
                hp0 = fmaf(w2j, fmaxf(acc[tle][1] + b1j, 0.0f), hp0);
                hp1 = fmaf(w2j, fmaxf(acc[tle][3] + b1j, 0.0f), hp1);
            }
        }
        hp0 += __shfl_xor_sync(0xffffffffu, hp0, 2);
        hp1 += __shfl_xor_sync(0xffffffffu, hp1, 2);
        if (q == 1) { s_red[nh * 128 + m0] = hp0; s_red[nh * 128 + m0 + 8] = hp1; }
        __syncthreads();   // bar1: MMA reads done, s_red ready

        if (t >= 1 && tid < 128) {
            int gn = n0 + tid;
            if (gn < NN)
                yout[(size_t)(t - 1) * NN + gn] = sigf(s_red[tid] + s_red[128 + tid] + h2b0);
        }
        if (t < TT) {
            if ((q & 1) == 0) {
#pragma unroll
                for (int tle = 0; tle < 16; ++tle) {
                    int j = nh * 32 + tle * 2 + (q >> 1);
                    float h0v = acc[tle][0], h1v = acc[tle][2];
                    __nv_bfloat16 hi0 = __float2bfloat16(h0v);
                    abf[m0 * 152 + j] = hi0;
                    abf[m0 * 152 + 64 + j] = __float2bfloat16(h0v - __bfloat162float(hi0));
                    __nv_bfloat16 hi1 = __float2bfloat16(h1v);
                    abf[(m0 + 8) * 152 + j] = hi1;
                    abf[(m0 + 8) * 152 + 64 + j] = __float2bfloat16(h1v - __bfloat162float(hi1));
                }
            }
            if (t < TT - 1 && tid < 128) {
                float xv[8] = {xpa.x, xpa.y, xpa.z, xpa.w, xpb.x, xpb.y, xpb.z, xpb.w};
                __nv_bfloat16* ax = abf + tid * 152 + 128;
#pragma unroll
                for (int kk = 0; kk < 8; ++kk) { ax[kk] = __float2bfloat16(xv[kk]); s_xf[tid * 8 + kk] = xv[kk]; }
            }
        }
        __syncthreads();   // bar2: A ready for next step
    }
}

// ---------------- launch ----------------
extern "C" void kernel_launch(void* const* d_in, const int* in_sizes, int n_in,
                              void* d_out, int out_size) {
    const float* X_static = (const float*)d_in[0];
    const float* X_dyn    = (const float*)d_in[1];
    const int*   er       = (const int*)d_in[2];
    const int*   ec       = (const int*)d_in[3];
    const float* ev       = (const float*)d_in[4];
    const float* g1W      = (const float*)d_in[5];
    const float* g1b      = (const float*)d_in[6];
    const float* g2W      = (const float*)d_in[7];
    const float* g2b      = (const float*)d_in[8];
    const float* Wih      = (const float*)d_in[9];
    const float* Whh      = (const float*)d_in[10];
    const float* bih      = (const float*)d_in[11];
    const float* bhh      = (const float*)d_in[12];
    const float* h1W      = (const float*)d_in[13];
    const float* h1b      = (const float*)d_in[14];
    const float* h2W      = (const float*)d_in[15];
    const float* h2b      = (const float*)d_in[16];
    float* out = (float*)d_out;

    cudaFuncSetAttribute(gru_mma_kernel,
                         cudaFuncAttributeMaxDynamicSharedMemorySize, GRU_SMEM_BYTES);

    lin32_kernel<<<3125, 256>>>(X_static, g1W, g1b, 0);
    spmm_kernel<<<100000, 256>>>(er, ec, ev);
    lin32_kernel<<<3125, 256>>>(X_static, g2W, g2b, 1);
    spmm_kernel<<<100000, 256>>>(er, ec, ev);

    prep_kernel<<<155, 256>>>(Whh, Wih, h1W, bhh);
    gi_prep_kernel<<<3125, 256>>>(Wih, bih, bhh);

    gru_mma_kernel<<<782, 512, GRU_SMEM_BYTES>>>(X_dyn, h1b, h2W, h2b, out);
}

// round 12
// speedup vs baseline: 1.4853x; 1.0368x over previous
#include <cuda_runtime.h>
#include <cuda_bf16.h>
#include <math.h>

#define DINLINE __device__ __forceinline__

constexpr int NN = 100000;
constexpr int TT = 24;

// ---------------- scratch globals ----------------
__device__ __align__(16) float g_xw[NN * 32];
__device__ __align__(16) float g_acc[NN * 32];
__device__ __align__(16) float g_gi[NN * 192];          // [n][r(64)|z(64)|in(64)] (+biases)
__device__ __align__(16) __nv_bfloat16 g_B[256 * 152];  // MMA B [n=4j+c][k], k: Whi(64)|Wlo(64)|x(8)|pad
__device__ __align__(16) float g_Wn[64 * 8];            // W_ih n-rows, x cols (fp32, SIMT i_n)
__device__ __align__(16) float g_bhn[64];

DINLINE float sigf(float x)  { return __fdividef(1.0f, 1.0f + __expf(-x)); }
DINLINE float tanh_mufu(float x) { float y; asm("tanh.approx.f32 %0, %1;" : "=f"(y) : "f"(x)); return y; }
DINLINE float sigf_fast(float x) { return fmaf(0.5f, tanh_mufu(0.5f * x), 0.5f); }
DINLINE unsigned s2u(const void* p) {
    unsigned a; asm("{ .reg .u64 t; cvta.to.shared.u64 t, %1; cvt.u32.u64 %0, t; }" : "=r"(a) : "l"(p)); return a;
}
#define LDSM4(r0,r1,r2,r3,addr) \
    asm volatile("ldmatrix.sync.aligned.m8n8.x4.shared.b16 {%0,%1,%2,%3}, [%4];" \
        : "=r"(r0),"=r"(r1),"=r"(r2),"=r"(r3) : "r"(addr))
#define MMA16816(d,a0,a1,a2,a3,b0,b1) \
    asm volatile("mma.sync.aligned.m16n8k16.row.col.f32.bf16.bf16.f32 " \
        "{%0,%1,%2,%3},{%4,%5,%6,%7},{%8,%9},{%0,%1,%2,%3};" \
        : "+f"(d[0]),"+f"(d[1]),"+f"(d[2]),"+f"(d[3]) \
        : "r"(a0),"r"(a1),"r"(a2),"r"(a3),"r"(b0),"r"(b1))

// ---------------- graph conv (unchanged pipeline) ----------------
__global__ void lin32_kernel(const float* __restrict__ Xext, const float* __restrict__ W,
                             const float* __restrict__ bias, int relu_acc_src) {
    __shared__ float Wt[1024];
    __shared__ float Xs[32 * 33];
    int tid = threadIdx.x, n0 = blockIdx.x * 32;
    for (int e = tid; e < 1024; e += 256) { int j = e >> 5, k = e & 31; Wt[k * 32 + j] = W[j * 32 + k]; }
    for (int e = tid; e < 1024; e += 256) {
        int n = e >> 5, k = e & 31;
        float v = relu_acc_src ? fmaxf(g_acc[(n0 + n) * 32 + k], 0.0f) : Xext[(n0 + n) * 32 + k];
        Xs[n * 33 + k] = v;
    }
    __syncthreads();
    for (int e = tid; e < 1024; e += 256) g_acc[n0 * 32 + e] = 0.0f;
    int j = tid & 31; float b = bias[j];
#pragma unroll
    for (int g = 0; g < 4; ++g) {
        int n = (tid >> 5) + g * 8; float acc = b;
#pragma unroll
        for (int k = 0; k < 32; ++k) acc = fmaf(Xs[n * 33 + k], Wt[k * 32 + j], acc);
        g_xw[(n0 + n) * 32 + j] = acc;
    }
}

__global__ void spmm_kernel(const int* __restrict__ er, const int* __restrict__ ec,
                            const float* __restrict__ ev) {
    int idx = blockIdx.x * 256 + threadIdx.x;
    int e = idx >> 3, q = idx & 7;
    int r = __ldg(er + e), c = __ldg(ec + e);
    float v = __ldg(ev + e);
    float4 x = *(const float4*)(g_xw + c * 32 + q * 4);
    float* dst = g_acc + r * 32 + q * 4;
    asm volatile("red.global.add.v4.f32 [%0], {%1, %2, %3, %4};"
                 :: "l"(dst), "f"(v * x.x), "f"(v * x.y), "f"(v * x.z), "f"(v * x.w) : "memory");
}

__global__ void gi_prep_kernel(const float* __restrict__ Wih, const float* __restrict__ bih,
                               const float* __restrict__ bhh) {
    __shared__ float Ws[32 * 192];
    __shared__ float Hs[32 * 33];
    int tid = threadIdx.x, n0 = blockIdx.x * 32;
    for (int e = tid; e < 6144; e += 256) { int k = e / 192, j = e - k * 192; Ws[e] = Wih[j * 40 + k]; }
    for (int e = tid; e < 1024; e += 256) {
        int n = e >> 5, k = e & 31;
        Hs[n * 33 + k] = fmaxf(g_acc[(n0 + n) * 32 + k], 0.0f);
    }
    __syncthreads();
#pragma unroll 1
    for (int it = 0; it < 24; ++it) {
        int p = it * 256 + tid;
        int n = p / 192, j = p - n * 192;
        float acc = bih[j] + (j < 128 ? bhh[j] : 0.0f);
#pragma unroll
        for (int k = 0; k < 32; ++k) acc = fmaf(Hs[n * 33 + k], Ws[k * 192 + j], acc);
        g_gi[(n0 + n) * 192 + j] = acc;
    }
}

// Pack MMA B matrix (bf16, split hi/lo) + Wn + bhn. grid 155 x 256.
__global__ void prep_kernel(const float* __restrict__ Whh, const float* __restrict__ Wih,
                            const float* __restrict__ h1W, const float* __restrict__ bhh) {
    int id = blockIdx.x * 256 + threadIdx.x;
    if (id < 256 * 152) {
        int n = id / 152, k = id - n * 152;
        int j = n >> 2, c = n & 3;
        float w = 0.0f;
        if (k < 128) {
            int kk = k & 63; bool lo = k >= 64;
            float full;
            if (c == 0)      full = Whh[j * 64 + kk];
            else if (c == 1) full = Whh[(64 + j) * 64 + kk];
            else if (c == 2) full = Whh[(128 + j) * 64 + kk];
            else             full = h1W[j * 64 + kk];
            float hi = __bfloat162float(__float2bfloat16(full));
            w = lo ? (full - hi) : full;
        } else if (k < 136 && c < 2) {
            int kk = k - 128;
            w = Wih[(c == 0 ? j : 64 + j) * 40 + 32 + kk];
        }
        g_B[id] = __float2bfloat16(w);
    } else if (id < 256 * 152 + 512) {
        int q = id - 256 * 152;
        g_Wn[q] = Wih[(128 + (q >> 3)) * 40 + 32 + (q & 7)];
    } else if (id < 256 * 152 + 512 + 64) {
        g_bhn[id - (256 * 152 + 512)] = bhh[128 + id - (256 * 152 + 512)];
    }
}

// ---------------- persistent tensor-core GRU: 64-node tiles ----------------
// 16 warps: mg = wid>>2 (M 16-row group), nh = wid&3 (N 64-col group).
constexpr int OF_A    = 0;        // 64 x 152 bf16 = 4864 floats
constexpr int OF_B    = 4864;     // 256 x 152 bf16 = 19456 floats
constexpr int OF_GIRZ = 24320;    // [m][j] float2 = 8192 floats
constexpr int OF_GIN  = 32512;    // [m][j] = 4096
constexpr int OF_XF   = 36608;    // [m][8] fp32 = 512
constexpr int OF_WN   = 37120;    // [j][8] fp32 = 512
constexpr int OF_RED  = 37632;    // [4][64] = 256
constexpr int OF_BHN  = 37888;
constexpr int OF_H1B  = 37952;
constexpr int OF_H2W  = 38016;
constexpr int OF_H2B  = 38080;
constexpr int GRU_SMEM_FLOATS = 38084;
constexpr int GRU_SMEM_BYTES  = GRU_SMEM_FLOATS * 4;   // 152,336 B
constexpr int SAB = 304;   // row stride bytes (152 bf16)

__global__ void __launch_bounds__(512, 1)
gru_mma_kernel(const float* __restrict__ xdyn, const float* __restrict__ h1b,
               const float* __restrict__ h2w, const float* __restrict__ h2b,
               float* __restrict__ yout) {
    extern __shared__ float sm[];
    float2* s_girz = (float2*)(sm + OF_GIRZ);
    float*  s_gin  = sm + OF_GIN;
    float*  s_xf   = sm + OF_XF;
    float*  s_wn   = sm + OF_WN;
    float*  s_red  = sm + OF_RED;
    float*  s_bhn  = sm + OF_BHN;
    float*  s_h1b  = sm + OF_H1B;
    float*  s_h2w  = sm + OF_H2W;
    __nv_bfloat16* abf = (__nv_bfloat16*)(sm + OF_A);

    int tid = threadIdx.x;
    int n0  = blockIdx.x * 64;
    int L = tid & 31, wid = tid >> 5;
    int mg = wid >> 2, nh = wid & 3;
    int q = L & 3, rgrp = L >> 2;
    int m0 = mg * 16 + rgrp;

    // ---- prologue phase 1: zero A, copy B/gi/wn/biases ----
    for (int i = tid; i < 4864; i += 512) sm[OF_A + i] = 0.0f;
    {
        float4* d4 = (float4*)(sm + OF_B);
        const float4* s4 = (const float4*)g_B;
        for (int i = tid; i < 4864; i += 512) d4[i] = s4[i];
    }
    for (int idx = tid; idx < 4096; idx += 512) {
        int m = idx >> 6, j = idx & 63;
        int gm = min(n0 + m, NN - 1);
        const float* gp = g_gi + (size_t)gm * 192;
        s_girz[idx] = make_float2(gp[j], gp[64 + j]);
        s_gin[idx]  = gp[128 + j];
    }
    if (tid < 512) s_wn[tid] = g_Wn[tid];
    if (tid < 64) { s_bhn[tid] = g_bhn[tid]; s_h1b[tid] = h1b[tid]; s_h2w[tid] = h2w[tid]; }
    if (tid == 0) sm[OF_H2B] = h2b[0];
    __syncthreads();
    // ---- prologue phase 2: x_0 ----
    if (tid < 64) {
        int gn = min(n0 + tid, NN - 1);
        const float4* x4 = (const float4*)(xdyn + (size_t)gn * 8);
        float4 a = x4[0], b = x4[1];
        float xv[8] = {a.x, a.y, a.z, a.w, b.x, b.y, b.z, b.w};
        __nv_bfloat16* ax = abf + tid * 152 + 128;
#pragma unroll
        for (int kk = 0; kk < 8; ++kk) { ax[kk] = __float2bfloat16(xv[kk]); s_xf[tid * 8 + kk] = xv[kk]; }
    }
    __syncthreads();

    unsigned smA = s2u(sm);
    unsigned smB = smA + OF_B * 4;
    unsigned aLane = smA + (unsigned)((mg * 16 + (L & 15)) * SAB) + ((L & 16) ? 16u : 0u);
    unsigned bLane = smB + (unsigned)((nh * 64 + (L & 7) + ((L & 16) ? 8 : 0)) * SAB) + ((L & 8) ? 16u : 0u);

    float h2b0 = sm[OF_H2B];

#pragma unroll 1
    for (int t = 0; t <= TT; ++t) {
        // prefetch x_{t+1}
        float4 xpa, xpb;
        if (t < TT - 1 && tid < 64) {
            int gn = min(n0 + tid, NN - 1);
            const float4* x4 = (const float4*)(xdyn + ((size_t)(t + 1) * NN + gn) * 8);
            xpa = x4[0]; xpb = x4[1];
        }

        // ---- GEMM: 4 shared-B k16 chunks (h_hi + h_lo vs same W_hi) + 1 x chunk ----
        float acc[8][4];
#pragma unroll
        for (int i = 0; i < 8; ++i) { acc[i][0] = acc[i][1] = acc[i][2] = acc[i][3] = 0.0f; }
#pragma unroll
        for (int c = 0; c < 4; ++c) {
            unsigned a0, a1, a2, a3;      // h_hi chunk c
            unsigned e0, e1, e2, e3;      // h_lo chunk c
            LDSM4(a0, a1, a2, a3, aLane + c * 32);
            LDSM4(e0, e1, e2, e3, aLane + (4 + c) * 32);
            unsigned bb = bLane + c * 32;
#pragma unroll
            for (int tp = 0; tp < 4; ++tp) {
                unsigned b0, b1, b2, b3;
                LDSM4(b0, b1, b2, b3, bb + tp * (16 * SAB));
                MMA16816(acc[tp * 2],     a0, a1, a2, a3, b0, b1);
                MMA16816(acc[tp * 2 + 1], a0, a1, a2, a3, b2, b3);
                MMA16816(acc[tp * 2],     e0, e1, e2, e3, b0, b1);
                MMA16816(acc[tp * 2 + 1], e0, e1, e2, e3, b2, b3);
            }
        }
        {   // x chunk
            unsigned a0, a1, a2, a3;
            LDSM4(a0, a1, a2, a3, aLane + 8 * 32);
            unsigned bb = bLane + 8 * 32;
#pragma unroll
            for (int tp = 0; tp < 4; ++tp) {
                unsigned b0, b1, b2, b3;
                LDSM4(b0, b1, b2, b3, bb + tp * (16 * SAB));
                MMA16816(acc[tp * 2],     a0, a1, a2, a3, b0, b1);
                MMA16816(acc[tp * 2 + 1], a0, a1, a2, a3, b2, b3);
            }
        }

        // ---- epilogue ----
        float xf0[8], xf1[8];
#pragma unroll
        for (int k4 = 0; k4 < 2; ++k4) {
            float4 v0 = *(const float4*)(s_xf + m0 * 8 + k4 * 4);
            float4 v1 = *(const float4*)(s_xf + (m0 + 8) * 8 + k4 * 4);
            xf0[k4*4+0]=v0.x; xf0[k4*4+1]=v0.y; xf0[k4*4+2]=v0.z; xf0[k4*4+3]=v0.w;
            xf1[k4*4+0]=v1.x; xf1[k4*4+1]=v1.y; xf1[k4*4+2]=v1.z; xf1[k4*4+3]=v1.w;
        }
        float hp0 = 0.0f, hp1 = 0.0f;
#pragma unroll
        for (int tle = 0; tle < 8; ++tle) {
            int j = nh * 16 + tle * 2 + (q >> 1);
            float hnA = __shfl_xor_sync(0xffffffffu, acc[tle][0], 1);
            float hnB = __shfl_xor_sync(0xffffffffu, acc[tle][2], 1);
            if ((q & 1) == 0) {
                if (t < TT) {
                    float2 g0 = s_girz[m0 * 64 + j];
                    float2 g1 = s_girz[(m0 + 8) * 64 + j];
                    float ain0 = s_gin[m0 * 64 + j];
                    float ain1 = s_gin[(m0 + 8) * 64 + j];
                    float4 wa = *(const float4*)(s_wn + j * 8);
                    float4 wb = *(const float4*)(s_wn + j * 8 + 4);
                    ain0 += xf0[0]*wa.x + xf0[1]*wa.y + xf0[2]*wa.z + xf0[3]*wa.w
                          + xf0[4]*wb.x + xf0[5]*wb.y + xf0[6]*wb.z + xf0[7]*wb.w;
                    ain1 += xf1[0]*wa.x + xf1[1]*wa.y + xf1[2]*wa.z + xf1[3]*wa.w
                          + xf1[4]*wb.x + xf1[5]*wb.y + xf1[6]*wb.z + xf1[7]*wb.w;
                    float bh = s_bhn[j];
                    float r0 = sigf_fast(acc[tle][0] + g0.x);
                    float z0 = sigf_fast(acc[tle][1] + g0.y);
                    float nn0 = tanh_mufu(ain0 + r0 * (hnA + bh));
                    float r1 = sigf_fast(acc[tle][2] + g1.x);
                    float z1 = sigf_fast(acc[tle][3] + g1.y);
                    float nn1 = tanh_mufu(ain1 + r1 * (hnB + bh));
                    float ho0 = __bfloat162float(abf[m0 * 152 + j]) + __bfloat162float(abf[m0 * 152 + 64 + j]);
                    float ho1 = __bfloat162float(abf[(m0 + 8) * 152 + j]) + __bfloat162float(abf[(m0 + 8) * 152 + 64 + j]);
                    acc[tle][0] = nn0 + z0 * (ho0 - nn0);   // stash h_new rows
                    acc[tle][2] = nn1 + z1 * (ho1 - nn1);
                }
            } else {
                float w2j = s_h2w[j], b1j = s_h1b[j];
                hp0 = fmaf(w2j, fmaxf(acc[tle][1] + b1j, 0.0f), hp0);
                hp1 = fmaf(w2j, fmaxf(acc[tle][3] + b1j, 0.0f), hp1);
            }
        }
        hp0 += __shfl_xor_sync(0xffffffffu, hp0, 2);
        hp1 += __shfl_xor_sync(0xffffffffu, hp1, 2);
        if (q == 1) { s_red[nh * 64 + m0] = hp0; s_red[nh * 64 + m0 + 8] = hp1; }
        __syncthreads();   // bar1: MMA reads done, s_red ready

        if (t >= 1 && tid < 64) {
            int gn = n0 + tid;
            if (gn < NN)
                yout[(size_t)(t - 1) * NN + gn] =
                    sigf(s_red[tid] + s_red[64 + tid] + s_red[128 + tid] + s_red[192 + tid] + h2b0);
        }
        if (t < TT) {
            if ((q & 1) == 0) {
#pragma unroll
                for (int tle = 0; tle < 8; ++tle) {
                    int j = nh * 16 + tle * 2 + (q >> 1);
                    float h0v = acc[tle][0], h1v = acc[tle][2];
                    __nv_bfloat16 hi0 = __float2bfloat16(h0v);
                    abf[m0 * 152 + j] = hi0;
                    abf[m0 * 152 + 64 + j] = __float2bfloat16(h0v - __bfloat162float(hi0));
                    __nv_bfloat16 hi1 = __float2bfloat16(h1v);
                    abf[(m0 + 8) * 152 + j] = hi1;
                    abf[(m0 + 8) * 152 + 64 + j] = __float2bfloat16(h1v - __bfloat162float(hi1));
                }
            }
            if (t < TT - 1 && tid < 64) {
                float xv[8] = {xpa.x, xpa.y, xpa.z, xpa.w, xpb.x, xpb.y, xpb.z, xpb.w};
                __nv_bfloat16* ax = abf + tid * 152 + 128;
#pragma unroll
                for (int kk = 0; kk < 8; ++kk) { ax[kk] = __float2bfloat16(xv[kk]); s_xf[tid * 8 + kk] = xv[kk]; }
            }
        }
        __syncthreads();   // bar2: A ready for next step
    }
}

// ---------------- launch ----------------
extern "C" void kernel_launch(void* const* d_in, const int* in_sizes, int n_in,
                              void* d_out, int out_size) {
    const float* X_static = (const float*)d_in[0];
    const float* X_dyn    = (const float*)d_in[1];
    const int*   er       = (const int*)d_in[2];
    const int*   ec       = (const int*)d_in[3];
    const float* ev       = (const float*)d_in[4];
    const float* g1W      = (const float*)d_in[5];
    const float* g1b      = (const float*)d_in[6];
    const float* g2W      = (const float*)d_in[7];
    const float* g2b      = (const float*)d_in[8];
    const float* Wih      = (const float*)d_in[9];
    const float* Whh      = (const float*)d_in[10];
    const float* bih      = (const float*)d_in[11];
    const float* bhh      = (const float*)d_in[12];
    const float* h1W      = (const float*)d_in[13];
    const float* h1b      = (const float*)d_in[14];
    const float* h2W      = (const float*)d_in[15];
    const float* h2b      = (const float*)d_in[16];
    float* out = (float*)d_out;

    cudaFuncSetAttribute(gru_mma_kernel,
                         cudaFuncAttributeMaxDynamicSharedMemorySize, GRU_SMEM_BYTES);

    lin32_kernel<<<3125, 256>>>(X_static, g1W, g1b, 0);
    spmm_kernel<<<100000, 256>>>(er, ec, ev);
    lin32_kernel<<<3125, 256>>>(X_static, g2W, g2b, 1);
    spmm_kernel<<<100000, 256>>>(er, ec, ev);

    prep_kernel<<<155, 256>>>(Whh, Wih, h1W, bhh);
    gi_prep_kernel<<<3125, 256>>>(Wih, bih, bhh);

    gru_mma_kernel<<<1563, 512, GRU_SMEM_BYTES>>>(X_dyn, h1b, h2W, h2b, out);
}

// round 13
// speedup vs baseline: 1.9276x; 1.2978x over previous
#include <cuda_runtime.h>
#include <cuda_bf16.h>
#include <math.h>

#define DINLINE __device__ __forceinline__

constexpr int NN = 100000;
constexpr int TT = 24;

// ---------------- scratch globals ----------------
__device__ __align__(16) float g_xw[NN * 32];
__device__ __align__(16) float g_acc[NN * 32];
__device__ __align__(16) float g_gi[NN * 192];          // [n][r(64)|z(64)|in(64)] (+biases)
__device__ __align__(16) __nv_bfloat16 g_B[256 * 152];  // MMA B: n<128: (r,z) pairs; n>=128: (hn,head) pairs
__device__ __align__(16) float g_Wn[64 * 8];            // W_ih n-rows, x cols (fp32, SIMT i_n)
__device__ __align__(16) float g_bhn[64];

DINLINE float sigf(float x)  { return __fdividef(1.0f, 1.0f + __expf(-x)); }
DINLINE float tanh_mufu(float x) { float y; asm("tanh.approx.f32 %0, %1;" : "=f"(y) : "f"(x)); return y; }
DINLINE float sigf_fast(float x) { return fmaf(0.5f, tanh_mufu(0.5f * x), 0.5f); }
DINLINE unsigned s2u(const void* p) {
    unsigned a; asm("{ .reg .u64 t; cvta.to.shared.u64 t, %1; cvt.u32.u64 %0, t; }" : "=r"(a) : "l"(p)); return a;
}
#define LDSM4(r0,r1,r2,r3,addr) \
    asm volatile("ldmatrix.sync.aligned.m8n8.x4.shared.b16 {%0,%1,%2,%3}, [%4];" \
        : "=r"(r0),"=r"(r1),"=r"(r2),"=r"(r3) : "r"(addr))
#define MMA16816(d,a0,a1,a2,a3,b0,b1) \
    asm volatile("mma.sync.aligned.m16n8k16.row.col.f32.bf16.bf16.f32 " \
        "{%0,%1,%2,%3},{%4,%5,%6,%7},{%8,%9},{%0,%1,%2,%3};" \
        : "+f"(d[0]),"+f"(d[1]),"+f"(d[2]),"+f"(d[3]) \
        : "r"(a0),"r"(a1),"r"(a2),"r"(a3),"r"(b0),"r"(b1))

// ---------------- graph conv (unchanged pipeline) ----------------
__global__ void lin32_kernel(const float* __restrict__ Xext, const float* __restrict__ W,
                             const float* __restrict__ bias, int relu_acc_src) {
    __shared__ float Wt[1024];
    __shared__ float Xs[32 * 33];
    int tid = threadIdx.x, n0 = blockIdx.x * 32;
    for (int e = tid; e < 1024; e += 256) { int j = e >> 5, k = e & 31; Wt[k * 32 + j] = W[j * 32 + k]; }
    for (int e = tid; e < 1024; e += 256) {
        int n = e >> 5, k = e & 31;
        float v = relu_acc_src ? fmaxf(g_acc[(n0 + n) * 32 + k], 0.0f) : Xext[(n0 + n) * 32 + k];
        Xs[n * 33 + k] = v;
    }
    __syncthreads();
    for (int e = tid; e < 1024; e += 256) g_acc[n0 * 32 + e] = 0.0f;
    int j = tid & 31; float b = bias[j];
#pragma unroll
    for (int g = 0; g < 4; ++g) {
        int n = (tid >> 5) + g * 8; float acc = b;
#pragma unroll
        for (int k = 0; k < 32; ++k) acc = fmaf(Xs[n * 33 + k], Wt[k * 32 + j], acc);
        g_xw[(n0 + n) * 32 + j] = acc;
    }
}

__global__ void spmm_kernel(const int* __restrict__ er, const int* __restrict__ ec,
                            const float* __restrict__ ev) {
    int idx = blockIdx.x * 256 + threadIdx.x;
    int e = idx >> 3, q = idx & 7;
    int r = __ldg(er + e), c = __ldg(ec + e);
    float v = __ldg(ev + e);
    float4 x = *(const float4*)(g_xw + c * 32 + q * 4);
    float* dst = g_acc + r * 32 + q * 4;
    asm volatile("red.global.add.v4.f32 [%0], {%1, %2, %3, %4};"
                 :: "l"(dst), "f"(v * x.x), "f"(v * x.y), "f"(v * x.z), "f"(v * x.w) : "memory");
}

__global__ void gi_prep_kernel(const float* __restrict__ Wih, const float* __restrict__ bih,
                               const float* __restrict__ bhh) {
    __shared__ float Ws[32 * 192];
    __shared__ float Hs[32 * 33];
    int tid = threadIdx.x, n0 = blockIdx.x * 32;
    for (int e = tid; e < 6144; e += 256) { int k = e / 192, j = e - k * 192; Ws[e] = Wih[j * 40 + k]; }
    for (int e = tid; e < 1024; e += 256) {
        int n = e >> 5, k = e & 31;
        Hs[n * 33 + k] = fmaxf(g_acc[(n0 + n) * 32 + k], 0.0f);
    }
    __syncthreads();
#pragma unroll 1
    for (int it = 0; it < 24; ++it) {
        int p = it * 256 + tid;
        int n = p / 192, j = p - n * 192;
        float acc = bih[j] + (j < 128 ? bhh[j] : 0.0f);
#pragma unroll
        for (int k = 0; k < 32; ++k) acc = fmaf(Hs[n * 33 + k], Ws[k * 192 + j], acc);
        g_gi[(n0 + n) * 192 + j] = acc;
    }
}

// Pack MMA B matrix (bf16, split hi/lo) + Wn + bhn. grid 155 x 256.
// n<128:  n = 2j + c (c: 0=r, 1=z);     k: Whi(64)|Wlo(64)|x(8)|pad
// n>=128: n-128 = 2j + c (c: 0=hn, 1=head); x cols zero
__global__ void prep_kernel(const float* __restrict__ Whh, const float* __restrict__ Wih,
                            const float* __restrict__ h1W, const float* __restrict__ bhh) {
    int id = blockIdx.x * 256 + threadIdx.x;
    if (id < 256 * 152) {
        int n = id / 152, k = id - n * 152;
        float w = 0.0f;
        if (n < 128) {
            int j = n >> 1, c = n & 1;            // 0=r, 1=z
            if (k < 128) {
                int kk = k & 63;
                float full = Whh[(c ? 64 + j : j) * 64 + kk];
                float hi = __bfloat162float(__float2bfloat16(full));
                w = (k >= 64) ? (full - hi) : full;
            } else if (k < 136) {
                w = Wih[(c ? 64 + j : j) * 40 + 32 + (k - 128)];
            }
        } else {
            int n2 = n - 128, j = n2 >> 1, c = n2 & 1;   // 0=hn, 1=head
            if (k < 128) {
                int kk = k & 63;
                float full = c ? h1W[j * 64 + kk] : Whh[(128 + j) * 64 + kk];
                float hi = __bfloat162float(__float2bfloat16(full));
                w = (k >= 64) ? (full - hi) : full;
            }
        }
        g_B[id] = __float2bfloat16(w);
    } else if (id < 256 * 152 + 512) {
        int q = id - 256 * 152;
        g_Wn[q] = Wih[(128 + (q >> 3)) * 40 + 32 + (q & 7)];
    } else if (id < 256 * 152 + 512 + 64) {
        g_bhn[id - (256 * 152 + 512)] = bhh[128 + id - (256 * 152 + 512)];
    }
}

// ---------------- persistent tensor-core GRU: 64-node tiles, shfl-free gates ----------------
constexpr int OF_A    = 0;        // 64 x 152 bf16 = 4864 floats
constexpr int OF_B    = 4864;     // 256 x 152 bf16 = 19456 floats
constexpr int OF_GIRZ = 24320;    // [m][j] float2 = 8192 floats
constexpr int OF_GIN  = 32512;    // [m][j] = 4096
constexpr int OF_XF   = 36608;    // [m][8] fp32 = 512
constexpr int OF_WN   = 37120;    // [j][8] fp32 = 512
constexpr int OF_RED  = 37632;    // [4][64] = 256
constexpr int OF_BHN  = 37888;
constexpr int OF_H1B  = 37952;
constexpr int OF_H2W  = 38016;
constexpr int OF_H2B  = 38080;
constexpr int GRU_SMEM_FLOATS = 38084;
constexpr int GRU_SMEM_BYTES  = GRU_SMEM_FLOATS * 4;   // 152,336 B
constexpr int SAB = 304;   // row stride bytes (152 bf16)

__global__ void __launch_bounds__(512, 1)
gru_mma_kernel(const float* __restrict__ xdyn, const float* __restrict__ h1b,
               const float* __restrict__ h2w, const float* __restrict__ h2b,
               float* __restrict__ yout) {
    extern __shared__ float sm[];
    float2* s_girz = (float2*)(sm + OF_GIRZ);
    float*  s_gin  = sm + OF_GIN;
    float*  s_xf   = sm + OF_XF;
    float*  s_wn   = sm + OF_WN;
    float*  s_red  = sm + OF_RED;
    float*  s_bhn  = sm + OF_BHN;
    float*  s_h1b  = sm + OF_H1B;
    float*  s_h2w  = sm + OF_H2W;
    __nv_bfloat16* abf = (__nv_bfloat16*)(sm + OF_A);

    int tid = threadIdx.x;
    int n0  = blockIdx.x * 64;
    int L = tid & 31, wid = tid >> 5;
    int mg = wid >> 2, nh = wid & 3;
    int q = L & 3, rgrp = L >> 2;
    int m0 = mg * 16 + rgrp;

    // ---- prologue: zero A, copy B/gi/wn/biases ----
    for (int i = tid; i < 4864; i += 512) sm[OF_A + i] = 0.0f;
    {
        float4* d4 = (float4*)(sm + OF_B);
        const float4* s4 = (const float4*)g_B;
        for (int i = tid; i < 4864; i += 512) d4[i] = s4[i];
    }
    for (int idx = tid; idx < 4096; idx += 512) {
        int m = idx >> 6, j = idx & 63;
        int gm = min(n0 + m, NN - 1);
        const float* gp = g_gi + (size_t)gm * 192;
        s_girz[idx] = make_float2(gp[j], gp[64 + j]);
        s_gin[idx]  = gp[128 + j];
    }
    if (tid < 512) s_wn[tid] = g_Wn[tid];
    if (tid < 64) { s_bhn[tid] = g_bhn[tid]; s_h1b[tid] = h1b[tid]; s_h2w[tid] = h2w[tid]; }
    if (tid == 0) sm[OF_H2B] = h2b[0];
    __syncthreads();
    // ---- x_0 ----
    if (tid < 64) {
        int gn = min(n0 + tid, NN - 1);
        const float4* x4 = (const float4*)(xdyn + (size_t)gn * 8);
        float4 a = x4[0], b = x4[1];
        float xv[8] = {a.x, a.y, a.z, a.w, b.x, b.y, b.z, b.w};
        __nv_bfloat16* ax = abf + tid * 152 + 128;
#pragma unroll
        for (int kk = 0; kk < 8; ++kk) { ax[kk] = __float2bfloat16(xv[kk]); s_xf[tid * 8 + kk] = xv[kk]; }
    }
    __syncthreads();

    unsigned smA = s2u(sm);
    unsigned smB = smA + OF_B * 4;
    unsigned aLane  = smA + (unsigned)((mg * 16 + (L & 15)) * SAB) + ((L & 16) ? 16u : 0u);
    unsigned bLane1 = smB + (unsigned)((nh * 32 + (L & 7) + ((L & 16) ? 8 : 0)) * SAB) + ((L & 8) ? 16u : 0u);
    unsigned bLane2 = bLane1 + (unsigned)(128 * SAB);

    float h2b0 = sm[OF_H2B];

#pragma unroll 1
    for (int t = 0; t <= TT; ++t) {
        // prefetch x_{t+1}
        float4 xpa, xpb;
        if (t < TT - 1 && tid < 64) {
            int gn = min(n0 + tid, NN - 1);
            const float4* x4 = (const float4*)(xdyn + ((size_t)(t + 1) * NN + gn) * 8);
            xpa = x4[0]; xpb = x4[1];
        }

        // ---- GEMM ----
        float acc1[4][4], acc2[4][4];
#pragma unroll
        for (int i = 0; i < 4; ++i) {
            acc1[i][0]=acc1[i][1]=acc1[i][2]=acc1[i][3]=0.0f;
            acc2[i][0]=acc2[i][1]=acc2[i][2]=acc2[i][3]=0.0f;
        }
#pragma unroll
        for (int c = 0; c < 4; ++c) {
            unsigned a0, a1, a2, a3;      // h_hi chunk c
            unsigned e0, e1, e2, e3;      // h_lo chunk c
            LDSM4(a0, a1, a2, a3, aLane + c * 32);
            LDSM4(e0, e1, e2, e3, aLane + (4 + c) * 32);
#pragma unroll
            for (int tb = 0; tb < 2; ++tb) {
                unsigned b0, b1, b2, b3;
                LDSM4(b0, b1, b2, b3, bLane1 + c * 32 + tb * (16 * SAB));
                MMA16816(acc1[tb * 2],     a0, a1, a2, a3, b0, b1);
                MMA16816(acc1[tb * 2 + 1], a0, a1, a2, a3, b2, b3);
                MMA16816(acc1[tb * 2],     e0, e1, e2, e3, b0, b1);
                MMA16816(acc1[tb * 2 + 1], e0, e1, e2, e3, b2, b3);
                LDSM4(b0, b1, b2, b3, bLane2 + c * 32 + tb * (16 * SAB));
                MMA16816(acc2[tb * 2],     a0, a1, a2, a3, b0, b1);
                MMA16816(acc2[tb * 2 + 1], a0, a1, a2, a3, b2, b3);
                MMA16816(acc2[tb * 2],     e0, e1, e2, e3, b0, b1);
                MMA16816(acc2[tb * 2 + 1], e0, e1, e2, e3, b2, b3);
            }
        }
        {   // x chunk: group1 (r,z) only — group2 x-weights are zero
            unsigned a0, a1, a2, a3;
            LDSM4(a0, a1, a2, a3, aLane + 8 * 32);
#pragma unroll
            for (int tb = 0; tb < 2; ++tb) {
                unsigned b0, b1, b2, b3;
                LDSM4(b0, b1, b2, b3, bLane1 + 8 * 32 + tb * (16 * SAB));
                MMA16816(acc1[tb * 2],     a0, a1, a2, a3, b0, b1);
                MMA16816(acc1[tb * 2 + 1], a0, a1, a2, a3, b2, b3);
            }
        }

        // ---- epilogue: all four gate values resident in this thread ----
        float xf0[8], xf1[8];
#pragma unroll
        for (int k4 = 0; k4 < 2; ++k4) {
            float4 v0 = *(const float4*)(s_xf + m0 * 8 + k4 * 4);
            float4 v1 = *(const float4*)(s_xf + (m0 + 8) * 8 + k4 * 4);
            xf0[k4*4+0]=v0.x; xf0[k4*4+1]=v0.y; xf0[k4*4+2]=v0.z; xf0[k4*4+3]=v0.w;
            xf1[k4*4+0]=v1.x; xf1[k4*4+1]=v1.y; xf1[k4*4+2]=v1.z; xf1[k4*4+3]=v1.w;
        }
        float hp0 = 0.0f, hp1 = 0.0f;
#pragma unroll
        for (int tp = 0; tp < 4; ++tp) {
            int j = nh * 16 + tp * 4 + q;
            float w2j = s_h2w[j], b1j = s_h1b[j];
            hp0 = fmaf(w2j, fmaxf(acc2[tp][1] + b1j, 0.0f), hp0);
            hp1 = fmaf(w2j, fmaxf(acc2[tp][3] + b1j, 0.0f), hp1);
            if (t < TT) {
                float2 g0 = s_girz[m0 * 64 + j];
                float2 g1 = s_girz[(m0 + 8) * 64 + j];
                float ain0 = s_gin[m0 * 64 + j];
                float ain1 = s_gin[(m0 + 8) * 64 + j];
                float4 wa = *(const float4*)(s_wn + j * 8);
                float4 wb = *(const float4*)(s_wn + j * 8 + 4);
                ain0 += xf0[0]*wa.x + xf0[1]*wa.y + xf0[2]*wa.z + xf0[3]*wa.w
                      + xf0[4]*wb.x + xf0[5]*wb.y + xf0[6]*wb.z + xf0[7]*wb.w;
                ain1 += xf1[0]*wa.x + xf1[1]*wa.y + xf1[2]*wa.z + xf1[3]*wa.w
                      + xf1[4]*wb.x + xf1[5]*wb.y + xf1[6]*wb.z + xf1[7]*wb.w;
                float bh = s_bhn[j];
                float r0 = sigf_fast(acc1[tp][0] + g0.x);
                float z0 = sigf_fast(acc1[tp][1] + g0.y);
                float nn0 = tanh_mufu(ain0 + r0 * (acc2[tp][0] + bh));
                float r1 = sigf_fast(acc1[tp][2] + g1.x);
                float z1 = sigf_fast(acc1[tp][3] + g1.y);
                float nn1 = tanh_mufu(ain1 + r1 * (acc2[tp][2] + bh));
                float ho0 = __bfloat162float(abf[m0 * 152 + j]) + __bfloat162float(abf[m0 * 152 + 64 + j]);
                float ho1 = __bfloat162float(abf[(m0 + 8) * 152 + j]) + __bfloat162float(abf[(m0 + 8) * 152 + 64 + j]);
                acc1[tp][0] = nn0 + z0 * (ho0 - nn0);   // stash h_new rows
                acc1[tp][2] = nn1 + z1 * (ho1 - nn1);
            }
        }
        hp0 += __shfl_xor_sync(0xffffffffu, hp0, 1);
        hp0 += __shfl_xor_sync(0xffffffffu, hp0, 2);
        hp1 += __shfl_xor_sync(0xffffffffu, hp1, 1);
        hp1 += __shfl_xor_sync(0xffffffffu, hp1, 2);
        if (q == 0) { s_red[nh * 64 + m0] = hp0; s_red[nh * 64 + m0 + 8] = hp1; }
        __syncthreads();   // bar1: MMA reads of A done, s_red ready

        if (t >= 1 && tid < 64) {
            int gn = n0 + tid;
            if (gn < NN)
                yout[(size_t)(t - 1) * NN + gn] =
                    sigf(s_red[tid] + s_red[64 + tid] + s_red[128 + tid] + s_red[192 + tid] + h2b0);
        }
        if (t < TT) {
#pragma unroll
            for (int tp = 0; tp < 4; ++tp) {
                int j = nh * 16 + tp * 4 + q;
                float h0v = acc1[tp][0], h1v = acc1[tp][2];
                __nv_bfloat16 hi0 = __float2bfloat16(h0v);
                abf[m0 * 152 + j] = hi0;
                abf[m0 * 152 + 64 + j] = __float2bfloat16(h0v - __bfloat162float(hi0));
                __nv_bfloat16 hi1 = __float2bfloat16(h1v);
                abf[(m0 + 8) * 152 + j] = hi1;
                abf[(m0 + 8) * 152 + 64 + j] = __float2bfloat16(h1v - __bfloat162float(hi1));
            }
            if (t < TT - 1 && tid < 64) {
                float xv[8] = {xpa.x, xpa.y, xpa.z, xpa.w, xpb.x, xpb.y, xpb.z, xpb.w};
                __nv_bfloat16* ax = abf + tid * 152 + 128;
#pragma unroll
                for (int kk = 0; kk < 8; ++kk) { ax[kk] = __float2bfloat16(xv[kk]); s_xf[tid * 8 + kk] = xv[kk]; }
            }
        }
        __syncthreads();   // bar2: A ready for next step
    }
}

// ---------------- launch ----------------
extern "C" void kernel_launch(void* const* d_in, const int* in_sizes, int n_in,
                              void* d_out, int out_size) {
    const float* X_static = (const float*)d_in[0];
    const float* X_dyn    = (const float*)d_in[1];
    const int*   er       = (const int*)d_in[2];
    const int*   ec       = (const int*)d_in[3];
    const float* ev       = (const float*)d_in[4];
    const float* g1W      = (const float*)d_in[5];
    const float* g1b      = (const float*)d_in[6];
    const float* g2W      = (const float*)d_in[7];
    const float* g2b      = (const float*)d_in[8];
    const float* Wih      = (const float*)d_in[9];
    const float* Whh      = (const float*)d_in[10];
    const float* bih      = (const float*)d_in[11];
    const float* bhh      = (const float*)d_in[12];
    const float* h1W      = (const float*)d_in[13];
    const float* h1b      = (const float*)d_in[14];
    const float* h2W      = (const float*)d_in[15];
    const float* h2b      = (const float*)d_in[16];
    float* out = (float*)d_out;

    cudaFuncSetAttribute(gru_mma_kernel,
                         cudaFuncAttributeMaxDynamicSharedMemorySize, GRU_SMEM_BYTES);

    lin32_kernel<<<3125, 256>>>(X_static, g1W, g1b, 0);
    spmm_kernel<<<100000, 256>>>(er, ec, ev);
    lin32_kernel<<<3125, 256>>>(X_static, g2W, g2b, 1);
    spmm_kernel<<<100000, 256>>>(er, ec, ev);

    prep_kernel<<<155, 256>>>(Whh, Wih, h1W, bhh);
    gi_prep_kernel<<<3125, 256>>>(Wih, bih, bhh);

    gru_mma_kernel<<<1563, 512, GRU_SMEM_BYTES>>>(X_dyn, h1b, h2W, h2b, out);
}

// round 14
// speedup vs baseline: 2.1925x; 1.1374x over previous
#include <cuda_runtime.h>
#include <cuda_bf16.h>
#include <math.h>

#define DINLINE __device__ __forceinline__

constexpr int NN = 100000;
constexpr int TT = 24;

// ---------------- scratch globals ----------------
__device__ __align__(16) float g_xw[NN * 32];
__device__ __align__(16) float g_acc[NN * 32];
__device__ __align__(16) float g_gi[NN * 192];          // [n][r(64)|z(64)|in(64)] (+biases)
__device__ __align__(16) __nv_bfloat16 g_B[256 * 152];  // MMA B: n<128: (r,z) pairs; n>=128: (hn,head) pairs
__device__ __align__(16) float g_Wn[64 * 8];            // W_ih n-rows, x cols (fp32, SIMT i_n)
__device__ __align__(16) float g_bhn[64];

DINLINE float sigf(float x)  { return __fdividef(1.0f, 1.0f + __expf(-x)); }
DINLINE float tanh_mufu(float x) { float y; asm("tanh.approx.f32 %0, %1;" : "=f"(y) : "f"(x)); return y; }
DINLINE float sigf_fast(float x) { return fmaf(0.5f, tanh_mufu(0.5f * x), 0.5f); }
DINLINE unsigned s2u(const void* p) {
    unsigned a; asm("{ .reg .u64 t; cvta.to.shared.u64 t, %1; cvt.u32.u64 %0, t; }" : "=r"(a) : "l"(p)); return a;
}
#define LDSM4(r0,r1,r2,r3,addr) \
    asm volatile("ldmatrix.sync.aligned.m8n8.x4.shared.b16 {%0,%1,%2,%3}, [%4];" \
        : "=r"(r0),"=r"(r1),"=r"(r2),"=r"(r3) : "r"(addr))
#define MMA16816(d,a0,a1,a2,a3,b0,b1) \
    asm volatile("mma.sync.aligned.m16n8k16.row.col.f32.bf16.bf16.f32 " \
        "{%0,%1,%2,%3},{%4,%5,%6,%7},{%8,%9},{%0,%1,%2,%3};" \
        : "+f"(d[0]),"+f"(d[1]),"+f"(d[2]),"+f"(d[3]) \
        : "r"(a0),"r"(a1),"r"(a2),"r"(a3),"r"(b0),"r"(b1))

// ---------------- graph conv (unchanged pipeline) ----------------
__global__ void lin32_kernel(const float* __restrict__ Xext, const float* __restrict__ W,
                             const float* __restrict__ bias, int relu_acc_src) {
    __shared__ float Wt[1024];
    __shared__ float Xs[32 * 33];
    int tid = threadIdx.x, n0 = blockIdx.x * 32;
    for (int e = tid; e < 1024; e += 256) { int j = e >> 5, k = e & 31; Wt[k * 32 + j] = W[j * 32 + k]; }
    for (int e = tid; e < 1024; e += 256) {
        int n = e >> 5, k = e & 31;
        float v = relu_acc_src ? fmaxf(g_acc[(n0 + n) * 32 + k], 0.0f) : Xext[(n0 + n) * 32 + k];
        Xs[n * 33 + k] = v;
    }
    __syncthreads();
    for (int e = tid; e < 1024; e += 256) g_acc[n0 * 32 + e] = 0.0f;
    int j = tid & 31; float b = bias[j];
#pragma unroll
    for (int g = 0; g < 4; ++g) {
        int n = (tid >> 5) + g * 8; float acc = b;
#pragma unroll
        for (int k = 0; k < 32; ++k) acc = fmaf(Xs[n * 33 + k], Wt[k * 32 + j], acc);
        g_xw[(n0 + n) * 32 + j] = acc;
    }
}

__global__ void spmm_kernel(const int* __restrict__ er, const int* __restrict__ ec,
                            const float* __restrict__ ev) {
    int idx = blockIdx.x * 256 + threadIdx.x;
    int e = idx >> 3, q = idx & 7;
    int r = __ldg(er + e), c = __ldg(ec + e);
    float v = __ldg(ev + e);
    float4 x = *(const float4*)(g_xw + c * 32 + q * 4);
    float* dst = g_acc + r * 32 + q * 4;
    asm volatile("red.global.add.v4.f32 [%0], {%1, %2, %3, %4};"
                 :: "l"(dst), "f"(v * x.x), "f"(v * x.y), "f"(v * x.z), "f"(v * x.w) : "memory");
}

__global__ void gi_prep_kernel(const float* __restrict__ Wih, const float* __restrict__ bih,
                               const float* __restrict__ bhh) {
    __shared__ float Ws[32 * 192];
    __shared__ float Hs[32 * 33];
    int tid = threadIdx.x, n0 = blockIdx.x * 32;
    for (int e = tid; e < 6144; e += 256) { int k = e / 192, j = e - k * 192; Ws[e] = Wih[j * 40 + k]; }
    for (int e = tid; e < 1024; e += 256) {
        int n = e >> 5, k = e & 31;
        Hs[n * 33 + k] = fmaxf(g_acc[(n0 + n) * 32 + k], 0.0f);
    }
    __syncthreads();
#pragma unroll 1
    for (int it = 0; it < 24; ++it) {
        int p = it * 256 + tid;
        int n = p / 192, j = p - n * 192;
        float acc = bih[j] + (j < 128 ? bhh[j] : 0.0f);
#pragma unroll
        for (int k = 0; k < 32; ++k) acc = fmaf(Hs[n * 33 + k], Ws[k * 192 + j], acc);
        g_gi[(n0 + n) * 192 + j] = acc;
    }
}

// Pack MMA B matrix (bf16) + Wn + bhn. grid 155 x 256.
// n<128:  n = 2j + c (c: 0=r, 1=z);     k: W(64)|unused(64)|x(8)|pad
// n>=128: n-128 = 2j + c (c: 0=hn, 1=head); x cols zero
__global__ void prep_kernel(const float* __restrict__ Whh, const float* __restrict__ Wih,
                            const float* __restrict__ h1W, const float* __restrict__ bhh) {
    int id = blockIdx.x * 256 + threadIdx.x;
    if (id < 256 * 152) {
        int n = id / 152, k = id - n * 152;
        float w = 0.0f;
        if (n < 128) {
            int j = n >> 1, c = n & 1;            // 0=r, 1=z
            if (k < 64) {
                w = Whh[(c ? 64 + j : j) * 64 + k];
            } else if (k >= 128 && k < 136) {
                w = Wih[(c ? 64 + j : j) * 40 + 32 + (k - 128)];
            }
        } else {
            int n2 = n - 128, j = n2 >> 1, c = n2 & 1;   // 0=hn, 1=head
            if (k < 64) {
                w = c ? h1W[j * 64 + k] : Whh[(128 + j) * 64 + k];
            }
        }
        g_B[id] = __float2bfloat16(w);
    } else if (id < 256 * 152 + 512) {
        int q = id - 256 * 152;
        g_Wn[q] = Wih[(128 + (q >> 3)) * 40 + 32 + (q & 7)];
    } else if (id < 256 * 152 + 512 + 64) {
        g_bhn[id - (256 * 152 + 512)] = bhh[128 + id - (256 * 152 + 512)];
    }
}

// ---------------- persistent tensor-core GRU: 64-node tiles, 1-term bf16, fp32 h in regs ----------------
constexpr int OF_A    = 0;        // 64 x 152 bf16 = 4864 floats (h cols 0-63, x cols 128-135)
constexpr int OF_B    = 4864;     // 256 x 152 bf16 = 19456 floats
constexpr int OF_GIRZ = 24320;    // [m][j] float2 = 8192 floats
constexpr int OF_GIN  = 32512;    // [m][j] = 4096
constexpr int OF_XF   = 36608;    // [m][8] fp32 = 512
constexpr int OF_WN   = 37120;    // [j][8] fp32 = 512
constexpr int OF_RED  = 37632;    // [4][64] = 256
constexpr int OF_BHN  = 37888;
constexpr int OF_H1B  = 37952;
constexpr int OF_H2W  = 38016;
constexpr int OF_H2B  = 38080;
constexpr int GRU_SMEM_FLOATS = 38084;
constexpr int GRU_SMEM_BYTES  = GRU_SMEM_FLOATS * 4;   // 152,336 B
constexpr int SAB = 304;   // row stride bytes (152 bf16)

__global__ void __launch_bounds__(512, 1)
gru_mma_kernel(const float* __restrict__ xdyn, const float* __restrict__ h1b,
               const float* __restrict__ h2w, const float* __restrict__ h2b,
               float* __restrict__ yout) {
    extern __shared__ float sm[];
    float2* s_girz = (float2*)(sm + OF_GIRZ);
    float*  s_gin  = sm + OF_GIN;
    float*  s_xf   = sm + OF_XF;
    float*  s_wn   = sm + OF_WN;
    float*  s_red  = sm + OF_RED;
    float*  s_bhn  = sm + OF_BHN;
    float*  s_h1b  = sm + OF_H1B;
    float*  s_h2w  = sm + OF_H2W;
    __nv_bfloat16* abf = (__nv_bfloat16*)(sm + OF_A);

    int tid = threadIdx.x;
    int n0  = blockIdx.x * 64;
    int L = tid & 31, wid = tid >> 5;
    int mg = wid >> 2, nh = wid & 3;
    int q = L & 3, rgrp = L >> 2;
    int m0 = mg * 16 + rgrp;

    // ---- prologue: zero A, copy B/gi/wn/biases ----
    for (int i = tid; i < 4864; i += 512) sm[OF_A + i] = 0.0f;
    {
        float4* d4 = (float4*)(sm + OF_B);
        const float4* s4 = (const float4*)g_B;
        for (int i = tid; i < 4864; i += 512) d4[i] = s4[i];
    }
    for (int idx = tid; idx < 4096; idx += 512) {
        int m = idx >> 6, j = idx & 63;
        int gm = min(n0 + m, NN - 1);
        const float* gp = g_gi + (size_t)gm * 192;
        s_girz[idx] = make_float2(gp[j], gp[64 + j]);
        s_gin[idx]  = gp[128 + j];
    }
    if (tid < 512) s_wn[tid] = g_Wn[tid];
    if (tid < 64) { s_bhn[tid] = g_bhn[tid]; s_h1b[tid] = h1b[tid]; s_h2w[tid] = h2w[tid]; }
    if (tid == 0) sm[OF_H2B] = h2b[0];
    __syncthreads();
    // ---- x_0 ----
    if (tid < 64) {
        int gn = min(n0 + tid, NN - 1);
        const float4* x4 = (const float4*)(xdyn + (size_t)gn * 8);
        float4 a = x4[0], b = x4[1];
        float xv[8] = {a.x, a.y, a.z, a.w, b.x, b.y, b.z, b.w};
        __nv_bfloat16* ax = abf + tid * 152 + 128;
#pragma unroll
        for (int kk = 0; kk < 8; ++kk) { ax[kk] = __float2bfloat16(xv[kk]); s_xf[tid * 8 + kk] = xv[kk]; }
    }
    __syncthreads();

    unsigned smA = s2u(sm);
    unsigned smB = smA + OF_B * 4;
    unsigned aLane  = smA + (unsigned)((mg * 16 + (L & 15)) * SAB) + ((L & 16) ? 16u : 0u);
    unsigned bLane1 = smB + (unsigned)((nh * 32 + (L & 7) + ((L & 16) ? 8 : 0)) * SAB) + ((L & 8) ? 16u : 0u);
    unsigned bLane2 = bLane1 + (unsigned)(128 * SAB);

    float h2b0 = sm[OF_H2B];

    // fp32 recurrent state for this thread's fixed 8 (m, j) slots
    float hreg0[4] = {0.f, 0.f, 0.f, 0.f};   // row m0
    float hreg1[4] = {0.f, 0.f, 0.f, 0.f};   // row m0+8

#pragma unroll 1
    for (int t = 0; t <= TT; ++t) {
        // prefetch x_{t+1}
        float4 xpa, xpb;
        if (t < TT - 1 && tid < 64) {
            int gn = min(n0 + tid, NN - 1);
            const float4* x4 = (const float4*)(xdyn + ((size_t)(t + 1) * NN + gn) * 8);
            xpa = x4[0]; xpb = x4[1];
        }

        // ---- GEMM: 4 h-chunks + 1 x-chunk (no lo pass) ----
        float acc1[4][4], acc2[4][4];
#pragma unroll
        for (int i = 0; i < 4; ++i) {
            acc1[i][0]=acc1[i][1]=acc1[i][2]=acc1[i][3]=0.0f;
            acc2[i][0]=acc2[i][1]=acc2[i][2]=acc2[i][3]=0.0f;
        }
#pragma unroll
        for (int c = 0; c < 4; ++c) {
            unsigned a0, a1, a2, a3;
            LDSM4(a0, a1, a2, a3, aLane + c * 32);
#pragma unroll
            for (int tb = 0; tb < 2; ++tb) {
                unsigned b0, b1, b2, b3;
                LDSM4(b0, b1, b2, b3, bLane1 + c * 32 + tb * (16 * SAB));
                MMA16816(acc1[tb * 2],     a0, a1, a2, a3, b0, b1);
                MMA16816(acc1[tb * 2 + 1], a0, a1, a2, a3, b2, b3);
                LDSM4(b0, b1, b2, b3, bLane2 + c * 32 + tb * (16 * SAB));
                MMA16816(acc2[tb * 2],     a0, a1, a2, a3, b0, b1);
                MMA16816(acc2[tb * 2 + 1], a0, a1, a2, a3, b2, b3);
            }
        }
        {   // x chunk: group1 (r,z) only — group2 x-weights are zero
            unsigned a0, a1, a2, a3;
            LDSM4(a0, a1, a2, a3, aLane + 8 * 32);
#pragma unroll
            for (int tb = 0; tb < 2; ++tb) {
                unsigned b0, b1, b2, b3;
                LDSM4(b0, b1, b2, b3, bLane1 + 8 * 32 + tb * (16 * SAB));
                MMA16816(acc1[tb * 2],     a0, a1, a2, a3, b0, b1);
                MMA16816(acc1[tb * 2 + 1], a0, a1, a2, a3, b2, b3);
            }
        }

        // ---- epilogue: all four gate values resident in this thread ----
        float xf0[8], xf1[8];
#pragma unroll
        for (int k4 = 0; k4 < 2; ++k4) {
            float4 v0 = *(const float4*)(s_xf + m0 * 8 + k4 * 4);
            float4 v1 = *(const float4*)(s_xf + (m0 + 8) * 8 + k4 * 4);
            xf0[k4*4+0]=v0.x; xf0[k4*4+1]=v0.y; xf0[k4*4+2]=v0.z; xf0[k4*4+3]=v0.w;
            xf1[k4*4+0]=v1.x; xf1[k4*4+1]=v1.y; xf1[k4*4+2]=v1.z; xf1[k4*4+3]=v1.w;
        }
        float hp0 = 0.0f, hp1 = 0.0f;
#pragma unroll
        for (int tp = 0; tp < 4; ++tp) {
            int j = nh * 16 + tp * 4 + q;
            float w2j = s_h2w[j], b1j = s_h1b[j];
            hp0 = fmaf(w2j, fmaxf(acc2[tp][1] + b1j, 0.0f), hp0);
            hp1 = fmaf(w2j, fmaxf(acc2[tp][3] + b1j, 0.0f), hp1);
            if (t < TT) {
                float2 g0 = s_girz[m0 * 64 + j];
                float2 g1 = s_girz[(m0 + 8) * 64 + j];
                float ain0 = s_gin[m0 * 64 + j];
                float ain1 = s_gin[(m0 + 8) * 64 + j];
                float4 wa = *(const float4*)(s_wn + j * 8);
                float4 wb = *(const float4*)(s_wn + j * 8 + 4);
                ain0 += xf0[0]*wa.x + xf0[1]*wa.y + xf0[2]*wa.z + xf0[3]*wa.w
                      + xf0[4]*wb.x + xf0[5]*wb.y + xf0[6]*wb.z + xf0[7]*wb.w;
                ain1 += xf1[0]*wa.x + xf1[1]*wa.y + xf1[2]*wa.z + xf1[3]*wa.w
                      + xf1[4]*wb.x + xf1[5]*wb.y + xf1[6]*wb.z + xf1[7]*wb.w;
                float bh = s_bhn[j];
                float r0 = sigf_fast(acc1[tp][0] + g0.x);
                float z0 = sigf_fast(acc1[tp][1] + g0.y);
                float nn0 = tanh_mufu(ain0 + r0 * (acc2[tp][0] + bh));
                float r1 = sigf_fast(acc1[tp][2] + g1.x);
                float z1 = sigf_fast(acc1[tp][3] + g1.y);
                float nn1 = tanh_mufu(ain1 + r1 * (acc2[tp][2] + bh));
                hreg0[tp] = nn0 + z0 * (hreg0[tp] - nn0);   // fp32 recurrence
                hreg1[tp] = nn1 + z1 * (hreg1[tp] - nn1);
            }
        }
        hp0 += __shfl_xor_sync(0xffffffffu, hp0, 1);
        hp0 += __shfl_xor_sync(0xffffffffu, hp0, 2);
        hp1 += __shfl_xor_sync(0xffffffffu, hp1, 1);
        hp1 += __shfl_xor_sync(0xffffffffu, hp1, 2);
        if (q == 0) { s_red[nh * 64 + m0] = hp0; s_red[nh * 64 + m0 + 8] = hp1; }
        __syncthreads();   // bar1: MMA reads of A done, s_red ready

        if (t >= 1 && tid < 64) {
            int gn = n0 + tid;
            if (gn < NN)
                yout[(size_t)(t - 1) * NN + gn] =
                    sigf(s_red[tid] + s_red[64 + tid] + s_red[128 + tid] + s_red[192 + tid] + h2b0);
        }
        if (t < TT) {
#pragma unroll
            for (int tp = 0; tp < 4; ++tp) {
                int j = nh * 16 + tp * 4 + q;
                abf[m0 * 152 + j]       = __float2bfloat16(hreg0[tp]);
                abf[(m0 + 8) * 152 + j] = __float2bfloat16(hreg1[tp]);
            }
            if (t < TT - 1 && tid < 64) {
                float xv[8] = {xpa.x, xpa.y, xpa.z, xpa.w, xpb.x, xpb.y, xpb.z, xpb.w};
                __nv_bfloat16* ax = abf + tid * 152 + 128;
#pragma unroll
                for (int kk = 0; kk < 8; ++kk) { ax[kk] = __float2bfloat16(xv[kk]); s_xf[tid * 8 + kk] = xv[kk]; }
            }
        }
        __syncthreads();   // bar2: A ready for next step
    }
}

// ---------------- launch ----------------
extern "C" void kernel_launch(void* const* d_in, const int* in_sizes, int n_in,
                              void* d_out, int out_size) {
    const float* X_static = (const float*)d_in[0];
    const float* X_dyn    = (const float*)d_in[1];
    const int*   er       = (const int*)d_in[2];
    const int*   ec       = (const int*)d_in[3];
    const float* ev       = (const float*)d_in[4];
    const float* g1W      = (const float*)d_in[5];
    const float* g1b      = (const float*)d_in[6];
    const float* g2W      = (const float*)d_in[7];
    const float* g2b      = (const float*)d_in[8];
    const float* Wih      = (const float*)d_in[9];
    const float* Whh      = (const float*)d_in[10];
    const float* bih      = (const float*)d_in[11];
    const float* bhh      = (const float*)d_in[12];
    const float* h1W      = (const float*)d_in[13];
    const float* h1b      = (const float*)d_in[14];
    const float* h2W      = (const float*)d_in[15];
    const float* h2b      = (const float*)d_in[16];
    float* out = (float*)d_out;

    cudaFuncSetAttribute(gru_mma_kernel,
                         cudaFuncAttributeMaxDynamicSharedMemorySize, GRU_SMEM_BYTES);

    lin32_kernel<<<3125, 256>>>(X_static, g1W, g1b, 0);
    spmm_kernel<<<100000, 256>>>(er, ec, ev);
    lin32_kernel<<<3125, 256>>>(X_static, g2W, g2b, 1);
    spmm_kernel<<<100000, 256>>>(er, ec, ev);

    prep_kernel<<<155, 256>>>(Whh, Wih, h1W, bhh);
    gi_prep_kernel<<<3125, 256>>>(Wih, bih, bhh);

    gru_mma_kernel<<<1563, 512, GRU_SMEM_BYTES>>>(X_dyn, h1b, h2W, h2b, out);
}

// round 16
// speedup vs baseline: 2.7905x; 1.2727x over previous
#include <cuda_runtime.h>
#include <cuda_bf16.h>
#include <math.h>

#define DINLINE __device__ __forceinline__

constexpr int NN = 100000;
constexpr int TT = 24;

// ---------------- scratch globals ----------------
__device__ __align__(16) float g_xw[NN * 32];
__device__ __align__(16) float g_acc[NN * 32];
__device__ __align__(16) float g_gi[NN * 192];          // [n][r(64)|z(64)|in(64)] (+biases)
__device__ __align__(16) __nv_bfloat16 g_B[256 * 152];  // MMA B: n<128: (r,z) pairs; n>=128: (hn,head) pairs
__device__ __align__(16) float g_Wn[64 * 8];            // W_ih n-rows, x cols (fp32, SIMT i_n)
__device__ __align__(16) float g_bhn[64];

DINLINE float sigf(float x)  { return __fdividef(1.0f, 1.0f + __expf(-x)); }
DINLINE float tanh_mufu(float x) { float y; asm("tanh.approx.f32 %0, %1;" : "=f"(y) : "f"(x)); return y; }
DINLINE float sigf_fast(float x) { return fmaf(0.5f, tanh_mufu(0.5f * x), 0.5f); }
DINLINE unsigned s2u(const void* p) {
    unsigned a; asm("{ .reg .u64 t; cvta.to.shared.u64 t, %1; cvt.u32.u64 %0, t; }" : "=r"(a) : "l"(p)); return a;
}
#define LDSM4(r0,r1,r2,r3,addr) \
    asm volatile("ldmatrix.sync.aligned.m8n8.x4.shared.b16 {%0,%1,%2,%3}, [%4];" \
        : "=r"(r0),"=r"(r1),"=r"(r2),"=r"(r3) : "r"(addr))
#define MMA16816(d,a0,a1,a2,a3,b0,b1) \
    asm volatile("mma.sync.aligned.m16n8k16.row.col.f32.bf16.bf16.f32 " \
        "{%0,%1,%2,%3},{%4,%5,%6,%7},{%8,%9},{%0,%1,%2,%3};" \
        : "+f"(d[0]),"+f"(d[1]),"+f"(d[2]),"+f"(d[3]) \
        : "r"(a0),"r"(a1),"r"(a2),"r"(a3),"r"(b0),"r"(b1))

// ---------------- graph conv (unchanged pipeline) ----------------
__global__ void lin32_kernel(const float* __restrict__ Xext, const float* __restrict__ W,
                             const float* __restrict__ bias, int relu_acc_src) {
    __shared__ float Wt[1024];
    __shared__ float Xs[32 * 33];
    int tid = threadIdx.x, n0 = blockIdx.x * 32;
    for (int e = tid; e < 1024; e += 256) { int j = e >> 5, k = e & 31; Wt[k * 32 + j] = W[j * 32 + k]; }
    for (int e = tid; e < 1024; e += 256) {
        int n = e >> 5, k = e & 31;
        float v = relu_acc_src ? fmaxf(g_acc[(n0 + n) * 32 + k], 0.0f) : Xext[(n0 + n) * 32 + k];
        Xs[n * 33 + k] = v;
    }
    __syncthreads();
    for (int e = tid; e < 1024; e += 256) g_acc[n0 * 32 + e] = 0.0f;
    int j = tid & 31; float b = bias[j];
#pragma unroll
    for (int g = 0; g < 4; ++g) {
        int n = (tid >> 5) + g * 8; float acc = b;
#pragma unroll
        for (int k = 0; k < 32; ++k) acc = fmaf(Xs[n * 33 + k], Wt[k * 32 + j], acc);
        g_xw[(n0 + n) * 32 + j] = acc;
    }
}

__global__ void spmm_kernel(const int* __restrict__ er, const int* __restrict__ ec,
                            const float* __restrict__ ev) {
    int idx = blockIdx.x * 256 + threadIdx.x;
    int e = idx >> 3, q = idx & 7;
    int r = __ldg(er + e), c = __ldg(ec + e);
    float v = __ldg(ev + e);
    float4 x = *(const float4*)(g_xw + c * 32 + q * 4);
    float* dst = g_acc + r * 32 + q * 4;
    asm volatile("red.global.add.v4.f32 [%0], {%1, %2, %3, %4};"
                 :: "l"(dst), "f"(v * x.x), "f"(v * x.y), "f"(v * x.z), "f"(v * x.w) : "memory");
}

__global__ void gi_prep_kernel(const float* __restrict__ Wih, const float* __restrict__ bih,
                               const float* __restrict__ bhh) {
    __shared__ float Ws[32 * 192];
    __shared__ float Hs[32 * 33];
    int tid = threadIdx.x, n0 = blockIdx.x * 32;
    for (int e = tid; e < 6144; e += 256) { int k = e / 192, j = e - k * 192; Ws[e] = Wih[j * 40 + k]; }
    for (int e = tid; e < 1024; e += 256) {
        int n = e >> 5, k = e & 31;
        Hs[n * 33 + k] = fmaxf(g_acc[(n0 + n) * 32 + k], 0.0f);
    }
    __syncthreads();
#pragma unroll 1
    for (int it = 0; it < 24; ++it) {
        int p = it * 256 + tid;
        int n = p / 192, j = p - n * 192;
        float acc = bih[j] + (j < 128 ? bhh[j] : 0.0f);
#pragma unroll
        for (int k = 0; k < 32; ++k) acc = fmaf(Hs[n * 33 + k], Ws[k * 192 + j], acc);
        g_gi[(n0 + n) * 192 + j] = acc;
    }
}

// Pack MMA B matrix (bf16) + Wn + bhn. grid 155 x 256.
// n<128:  n = 2j + c (c: 0=r, 1=z);     k: W(64)|unused(64)|x(8)|pad
// n>=128: n-128 = 2j + c (c: 0=hn, 1=head); x cols zero
__global__ void prep_kernel(const float* __restrict__ Whh, const float* __restrict__ Wih,
                            const float* __restrict__ h1W, const float* __restrict__ bhh) {
    int id = blockIdx.x * 256 + threadIdx.x;
    if (id < 256 * 152) {
        int n = id / 152, k = id - n * 152;
        float w = 0.0f;
        if (n < 128) {
            int j = n >> 1, c = n & 1;            // 0=r, 1=z
            if (k < 64) {
                w = Whh[(c ? 64 + j : j) * 64 + k];
            } else if (k >= 128 && k < 136) {
                w = Wih[(c ? 64 + j : j) * 40 + 32 + (k - 128)];
            }
        } else {
            int n2 = n - 128, j = n2 >> 1, c = n2 & 1;   // 0=hn, 1=head
            if (k < 64) {
                w = c ? h1W[j * 64 + k] : Whh[(128 + j) * 64 + k];
            }
        }
        g_B[id] = __float2bfloat16(w);
    } else if (id < 256 * 152 + 512) {
        int q = id - 256 * 152;
        g_Wn[q] = Wih[(128 + (q >> 3)) * 40 + 32 + (q & 7)];
    } else if (id < 256 * 152 + 512 + 64) {
        g_bhn[id - (256 * 152 + 512)] = bhh[128 + id - (256 * 152 + 512)];
    }
}

// ---------------- persistent tensor-core GRU: single barrier/step ----------------
// A tile: 64 rows x 168 bf16 (SAB_A 336): h buf0 k0-63, h buf1 k64-127,
// x buf0 k128-135, x buf1 k144-151, zeros elsewhere. B tile 256 x 152 bf16.
constexpr int OF_A    = 0;        // 64*168 bf16 = 21504 B = 5376 floats
constexpr int OF_B    = 5376;     // 256*152 bf16 = 77824 B = 19456 floats
constexpr int OF_XF   = 24832;    // [2][64*8] fp32 = 1024
constexpr int OF_WN   = 25856;    // [j][8] fp32 = 512
constexpr int OF_RED  = 26368;    // [2][4][64] = 512
constexpr int OF_BHN  = 26880;
constexpr int OF_H1B  = 26944;
constexpr int OF_H2W  = 27008;
constexpr int OF_H2B  = 27072;
constexpr int GRU_SMEM_FLOATS = 27076;
constexpr int GRU_SMEM_BYTES  = GRU_SMEM_FLOATS * 4;   // 108,304 B
constexpr int SAB_A = 336;   // A row stride bytes (168 bf16)
constexpr int SAB_B = 304;   // B row stride bytes (152 bf16)

__global__ void __launch_bounds__(512, 1)
gru_mma_kernel(const float* __restrict__ xdyn, const float* __restrict__ h1b,
               const float* __restrict__ h2w, const float* __restrict__ h2b,
               float* __restrict__ yout) {
    extern __shared__ float sm[];
    float*  s_xf   = sm + OF_XF;
    float*  s_wn   = sm + OF_WN;
    float*  s_red  = sm + OF_RED;
    float*  s_bhn  = sm + OF_BHN;
    float*  s_h1b  = sm + OF_H1B;
    float*  s_h2w  = sm + OF_H2W;
    __nv_bfloat16* abf = (__nv_bfloat16*)(sm + OF_A);

    int tid = threadIdx.x;
    int n0  = blockIdx.x * 64;
    int L = tid & 31, wid = tid >> 5;
    int mg = wid >> 2, nh = wid & 3;
    int q = L & 3, rgrp = L >> 2;
    int m0 = mg * 16 + rgrp;

    // ---- prologue: zero A, copy B/wn/biases ----
    for (int i = tid; i < 5376; i += 512) sm[OF_A + i] = 0.0f;
    {
        float4* d4 = (float4*)(sm + OF_B);
        const float4* s4 = (const float4*)g_B;
        for (int i = tid; i < 4864; i += 512) d4[i] = s4[i];
    }
    if (tid < 512) s_wn[tid] = g_Wn[tid];
    if (tid < 64) { s_bhn[tid] = g_bhn[tid]; s_h1b[tid] = h1b[tid]; s_h2w[tid] = h2w[tid]; }
    if (tid == 0) sm[OF_H2B] = h2b[0];

    // ---- register-resident gi statics for this thread's fixed 8 (m,j) slots ----
    int gm0 = min(n0 + m0, NN - 1);
    int gm1 = min(n0 + m0 + 8, NN - 1);
    float2 grz0[4], grz1[4];
    float  gin0[4], gin1[4];
#pragma unroll
    for (int tp = 0; tp < 4; ++tp) {
        int j = nh * 16 + tp * 4 + q;
        const float* p0 = g_gi + (size_t)gm0 * 192;
        const float* p1 = g_gi + (size_t)gm1 * 192;
        grz0[tp] = make_float2(__ldg(p0 + j), __ldg(p0 + 64 + j));
        grz1[tp] = make_float2(__ldg(p1 + j), __ldg(p1 + 64 + j));
        gin0[tp] = __ldg(p0 + 128 + j);
        gin1[tp] = __ldg(p1 + 128 + j);
    }
    __syncthreads();
    // ---- x_0 into buf0 ----
    if (tid < 64) {
        int gn = min(n0 + tid, NN - 1);
        const float4* x4 = (const float4*)(xdyn + (size_t)gn * 8);
        float4 a = x4[0], b = x4[1];
        float xv[8] = {a.x, a.y, a.z, a.w, b.x, b.y, b.z, b.w};
        __nv_bfloat16* ax = abf + tid * 168 + 128;
#pragma unroll
        for (int kk = 0; kk < 8; ++kk) { ax[kk] = __float2bfloat16(xv[kk]); s_xf[tid * 8 + kk] = xv[kk]; }
    }
    __syncthreads();

    unsigned smA = s2u(sm);
    unsigned smB = smA + OF_B * 4;
    unsigned aLane  = smA + (unsigned)((mg * 16 + (L & 15)) * SAB_A) + ((L & 16) ? 16u : 0u);
    unsigned bLane1 = smB + (unsigned)((nh * 32 + (L & 7) + ((L & 16) ? 8 : 0)) * SAB_B) + ((L & 8) ? 16u : 0u);
    unsigned bLane2 = bLane1 + (unsigned)(128 * SAB_B);

    float h2b0 = sm[OF_H2B];

    // fp32 recurrent state
    float hreg0[4] = {0.f, 0.f, 0.f, 0.f};
    float hreg1[4] = {0.f, 0.f, 0.f, 0.f};

#pragma unroll 1
    for (int t = 0; t <= TT; ++t) {
        int pw = t & 1;

        // ---- write y_{t-2} from the red buffer filled two parities ago ----
        if (t >= 2 && tid < 64) {
            const float* rb = s_red + (1 - pw) * 256;
            int gn = n0 + tid;
            if (gn < NN)
                yout[(size_t)(t - 2) * NN + gn] =
                    sigf(rb[tid] + rb[64 + tid] + rb[128 + tid] + rb[192 + tid] + h2b0);
        }
        // ---- prefetch x_{t+1} ----
        float4 xpa, xpb;
        if (t < TT - 1 && tid < 64) {
            int gn = min(n0 + tid, NN - 1);
            const float4* x4 = (const float4*)(xdyn + ((size_t)(t + 1) * NN + gn) * 8);
            xpa = x4[0]; xpb = x4[1];
        }

        // ---- GEMM: h chunks pw*4..pw*4+3 (vs B chunks 0-3), x chunk 8+pw (vs B chunk 8) ----
        float acc1[4][4], acc2[4][4];
#pragma unroll
        for (int i = 0; i < 4; ++i) {
            acc1[i][0]=acc1[i][1]=acc1[i][2]=acc1[i][3]=0.0f;
            acc2[i][0]=acc2[i][1]=acc2[i][2]=acc2[i][3]=0.0f;
        }
#pragma unroll
        for (int c = 0; c < 4; ++c) {
            unsigned a0, a1, a2, a3;
            LDSM4(a0, a1, a2, a3, aLane + (pw * 4 + c) * 32);
#pragma unroll
            for (int tb = 0; tb < 2; ++tb) {
                unsigned b0, b1, b2, b3;
                LDSM4(b0, b1, b2, b3, bLane1 + c * 32 + tb * (16 * SAB_B));
                MMA16816(acc1[tb * 2],     a0, a1, a2, a3, b0, b1);
                MMA16816(acc1[tb * 2 + 1], a0, a1, a2, a3, b2, b3);
                LDSM4(b0, b1, b2, b3, bLane2 + c * 32 + tb * (16 * SAB_B));
                MMA16816(acc2[tb * 2],     a0, a1, a2, a3, b0, b1);
                MMA16816(acc2[tb * 2 + 1], a0, a1, a2, a3, b2, b3);
            }
        }
        {   // x chunk (group1 only)
            unsigned a0, a1, a2, a3;
            LDSM4(a0, a1, a2, a3, aLane + (8 + pw) * 32);
#pragma unroll
            for (int tb = 0; tb < 2; ++tb) {
                unsigned b0, b1, b2, b3;
                LDSM4(b0, b1, b2, b3, bLane1 + 8 * 32 + tb * (16 * SAB_B));
                MMA16816(acc1[tb * 2],     a0, a1, a2, a3, b0, b1);
                MMA16816(acc1[tb * 2 + 1], a0, a1, a2, a3, b2, b3);
            }
        }

        // ---- epilogue ----
        float xf0[8], xf1[8];
        {
            const float* xb = s_xf + pw * 512;
#pragma unroll
            for (int k4 = 0; k4 < 2; ++k4) {
                float4 v0 = *(const float4*)(xb + m0 * 8 + k4 * 4);
                float4 v1 = *(const float4*)(xb + (m0 + 8) * 8 + k4 * 4);
                xf0[k4*4+0]=v0.x; xf0[k4*4+1]=v0.y; xf0[k4*4+2]=v0.z; xf0[k4*4+3]=v0.w;
                xf1[k4*4+0]=v1.x; xf1[k4*4+1]=v1.y; xf1[k4*4+2]=v1.z; xf1[k4*4+3]=v1.w;
            }
        }
        int hb = (1 - pw) * 64;   // h_new column base (next step's read buffer)
        float hp0 = 0.0f, hp1 = 0.0f;
#pragma unroll
        for (int tp = 0; tp < 4; ++tp) {
            int j = nh * 16 + tp * 4 + q;
            float w2j = s_h2w[j], b1j = s_h1b[j];
            hp0 = fmaf(w2j, fmaxf(acc2[tp][1] + b1j, 0.0f), hp0);
            hp1 = fmaf(w2j, fmaxf(acc2[tp][3] + b1j, 0.0f), hp1);
            if (t < TT) {
                float ain0 = gin0[tp], ain1 = gin1[tp];
                float4 wa = *(const float4*)(s_wn + j * 8);
                float4 wb = *(const float4*)(s_wn + j * 8 + 4);
                ain0 += xf0[0]*wa.x + xf0[1]*wa.y + xf0[2]*wa.z + xf0[3]*wa.w
                      + xf0[4]*wb.x + xf0[5]*wb.y + xf0[6]*wb.z + xf0[7]*wb.w;
                ain1 += xf1[0]*wa.x + xf1[1]*wa.y + xf1[2]*wa.z + xf1[3]*wa.w
                      + xf1[4]*wb.x + xf1[5]*wb.y + xf1[6]*wb.z + xf1[7]*wb.w;
                float bh = s_bhn[j];
                float r0 = sigf_fast(acc1[tp][0] + grz0[tp].x);
                float z0 = sigf_fast(acc1[tp][1] + grz0[tp].y);
                float nn0 = tanh_mufu(ain0 + r0 * (acc2[tp][0] + bh));
                float r1 = sigf_fast(acc1[tp][2] + grz1[tp].x);
                float z1 = sigf_fast(acc1[tp][3] + grz1[tp].y);
                float nn1 = tanh_mufu(ain1 + r1 * (acc2[tp][2] + bh));
                hreg0[tp] = nn0 + z0 * (hreg0[tp] - nn0);
                hreg1[tp] = nn1 + z1 * (hreg1[tp] - nn1);
                abf[m0 * 168 + hb + j]       = __float2bfloat16(hreg0[tp]);
                abf[(m0 + 8) * 168 + hb + j] = __float2bfloat16(hreg1[tp]);
            }
        }
        hp0 += __shfl_xor_sync(0xffffffffu, hp0, 1);
        hp0 += __shfl_xor_sync(0xffffffffu, hp0, 2);
        hp1 += __shfl_xor_sync(0xffffffffu, hp1, 1);
        hp1 += __shfl_xor_sync(0xffffffffu, hp1, 2);
        if (q == 0) { s_red[pw * 256 + nh * 64 + m0] = hp0; s_red[pw * 256 + nh * 64 + m0 + 8] = hp1; }

        // ---- store prefetched x_{t+1} into the other x buffer ----
        if (t < TT - 1 && tid < 64) {
            float xv[8] = {xpa.x, xpa.y, xpa.z, xpa.w, xpb.x, xpb.y, xpb.z, xpb.w};
            __nv_bfloat16* ax = abf + tid * 168 + 128 + (1 - pw) * 16;
            float* xn = s_xf + (1 - pw) * 512 + tid * 8;
#pragma unroll
            for (int kk = 0; kk < 8; ++kk) { ax[kk] = __float2bfloat16(xv[kk]); xn[kk] = xv[kk]; }
        }
        __syncthreads();   // single barrier: publishes hNew, x, red
    }

    // ---- tail: y_{TT-1} from red[TT&1] ----
    if (tid < 64) {
        const float* rb = s_red + (TT & 1) * 256;
        int gn = n0 + tid;
        if (gn < NN)
            yout[(size_t)(TT - 1) * NN + gn] =
                sigf(rb[tid] + rb[64 + tid] + rb[128 + tid] + rb[192 + tid] + h2b0);
    }
}

// ---------------- launch ----------------
extern "C" void kernel_launch(void* const* d_in, const int* in_sizes, int n_in,
                              void* d_out, int out_size) {
    const float* X_static = (const float*)d_in[0];
    const float* X_dyn    = (const float*)d_in[1];
    const int*   er       = (const int*)d_in[2];
    const int*   ec       = (const int*)d_in[3];
    const float* ev       = (const float*)d_in[4];
    const float* g1W      = (const float*)d_in[5];
    const float* g1b      = (const float*)d_in[6];
    const float* g2W      = (const float*)d_in[7];
    const float* g2b      = (const float*)d_in[8];
    const float* Wih      = (const float*)d_in[9];
    const float* Whh      = (const float*)d_in[10];
    const float* bih      = (const float*)d_in[11];
    const float* bhh      = (const float*)d_in[12];
    const float* h1W      = (const float*)d_in[13];
    const float* h1b      = (const float*)d_in[14];
    const float* h2W      = (const float*)d_in[15];
    const float* h2b      = (const float*)d_in[16];
    float* out = (float*)d_out;

    cudaFuncSetAttribute(gru_mma_kernel,
                         cudaFuncAttributeMaxDynamicSharedMemorySize, GRU_SMEM_BYTES);

    lin32_kernel<<<3125, 256>>>(X_static, g1W, g1b, 0);
    spmm_kernel<<<100000, 256>>>(er, ec, ev);
    lin32_kernel<<<3125, 256>>>(X_static, g2W, g2b, 1);
    spmm_kernel<<<100000, 256>>>(er, ec, ev);

    prep_kernel<<<155, 256>>>(Whh, Wih, h1W, bhh);
    gi_prep_kernel<<<3125, 256>>>(Wih, bih, bhh);

    gru_mma_kernel<<<1563, 512, GRU_SMEM_BYTES>>>(X_dyn, h1b, h2W, h2b, out);
}